// round 2
// baseline (speedup 1.0000x reference)
#include <cuda_runtime.h>
#include <math.h>

#define Bb 2
#define Nn 1024
#define Dd 256
#define Hh 4
#define Oo 8
#define HO 32
#define DKK 64
#define NSTEPS 5
#define DT_F 0.1f
#define PI_F 3.14159265358979323846f
#define TWO_PI_F 6.28318530717958647692f

// Scratch (no cudaMalloc allowed)
__device__ float g_q[Bb * Nn * Dd];
__device__ float g_k[Bb * Nn * Dd];
__device__ float g_ph[Bb * Nn * HO];
__device__ float g_s0[Bb * Nn * HO];
__device__ float g_s1[Bb * Nn * HO];
__device__ float g_c0[Bb * Nn * HO];
__device__ float g_c1[Bb * Nn * HO];
__device__ float g_J[(size_t)Bb * Hh * Nn * Nn];   // 32 MB, L2-resident

// ---------------------------------------------------------------------------
// Generic C = X @ W^T (+bias). X:(M,K) row-major, W:(Nout,K) row-major.
// BM=BN=64, BK=32, 256 threads, 4x4 micro-tile per thread.
// ---------------------------------------------------------------------------
__global__ void gemm_xwt(const float* __restrict__ X, const float* __restrict__ W,
                         const float* __restrict__ bias, float* __restrict__ out,
                         int M, int K, int Nout) {
    __shared__ float As[64][33];
    __shared__ float Ws[64][33];
    int m0 = blockIdx.x * 64, n0 = blockIdx.y * 64;
    int tid = threadIdx.x;
    int tx = tid & 15, ty = tid >> 4;
    float acc[4][4] = {};
    for (int kt = 0; kt < K; kt += 32) {
        for (int li = tid; li < 64 * 32; li += 256) {
            int r = li >> 5, c = li & 31;
            As[r][c] = X[(size_t)(m0 + r) * K + kt + c];
            Ws[r][c] = (n0 + r < Nout) ? W[(size_t)(n0 + r) * K + kt + c] : 0.f;
        }
        __syncthreads();
#pragma unroll
        for (int kk = 0; kk < 32; kk++) {
            float a[4], bb[4];
#pragma unroll
            for (int i = 0; i < 4; i++) a[i] = As[ty * 4 + i][kk];
#pragma unroll
            for (int j = 0; j < 4; j++) bb[j] = Ws[tx * 4 + j][kk];
#pragma unroll
            for (int i = 0; i < 4; i++)
#pragma unroll
                for (int j = 0; j < 4; j++)
                    acc[i][j] = fmaf(a[i], bb[j], acc[i][j]);
        }
        __syncthreads();
    }
#pragma unroll
    for (int i = 0; i < 4; i++) {
        int m = m0 + ty * 4 + i;
#pragma unroll
        for (int j = 0; j < 4; j++) {
            int n = n0 + tx * 4 + j;
            if (n < Nout)
                out[(size_t)m * Nout + n] = acc[i][j] + (bias ? bias[n] : 0.f);
        }
    }
}

// ---------------------------------------------------------------------------
// Raw attention scores: S[bh,i,j] = 0.125 * dot(q_i, k_j) over dk=64.
// One CTA per 64x64 tile of one (b,h).
// ---------------------------------------------------------------------------
__global__ void scores_kernel(const float* __restrict__ q, const float* __restrict__ k,
                              float* __restrict__ J) {
    __shared__ float Qs[64][65];
    __shared__ float Ks[64][65];
    int bh = blockIdx.z;
    int b = bh >> 2, h = bh & 3;
    int i0 = blockIdx.x * 64, j0 = blockIdx.y * 64;
    int tid = threadIdx.x;
    for (int li = tid; li < 64 * 64; li += 256) {
        int r = li >> 6, c = li & 63;
        Qs[r][c] = q[(size_t)(b * Nn + i0 + r) * Dd + h * DKK + c];
        Ks[r][c] = k[(size_t)(b * Nn + j0 + r) * Dd + h * DKK + c];
    }
    __syncthreads();
    int tx = tid & 15, ty = tid >> 4;
    float acc[4][4] = {};
#pragma unroll
    for (int kk = 0; kk < 64; kk++) {
        float a[4], bb[4];
#pragma unroll
        for (int i = 0; i < 4; i++) a[i] = Qs[ty * 4 + i][kk];
#pragma unroll
        for (int j = 0; j < 4; j++) bb[j] = Ks[tx * 4 + j][kk];
#pragma unroll
        for (int i = 0; i < 4; i++)
#pragma unroll
            for (int j = 0; j < 4; j++)
                acc[i][j] = fmaf(a[i], bb[j], acc[i][j]);
    }
    size_t rowbase = ((size_t)bh * Nn + i0) * Nn + j0;
#pragma unroll
    for (int i = 0; i < 4; i++)
#pragma unroll
        for (int j = 0; j < 4; j++)
            J[rowbase + (size_t)(ty * 4 + i) * Nn + tx * 4 + j] = 0.125f * acc[i][j];
}

// ---------------------------------------------------------------------------
// In-place row softmax over J rows of length 1024. One 256-thread CTA per row.
// ---------------------------------------------------------------------------
__global__ void softmax_kernel(float* __restrict__ J) {
    __shared__ float red[8];
    size_t base = (size_t)blockIdx.x * Nn;
    int tid = threadIdx.x, lane = tid & 31, warp = tid >> 5;
    float4 v = reinterpret_cast<float4*>(J + base)[tid];
    float m = fmaxf(fmaxf(v.x, v.y), fmaxf(v.z, v.w));
#pragma unroll
    for (int off = 16; off; off >>= 1)
        m = fmaxf(m, __shfl_xor_sync(0xffffffffu, m, off));
    if (lane == 0) red[warp] = m;
    __syncthreads();
    if (warp == 0) {
        float x = (lane < 8) ? red[lane] : -1e30f;
#pragma unroll
        for (int off = 16; off; off >>= 1)
            x = fmaxf(x, __shfl_xor_sync(0xffffffffu, x, off));
        if (lane == 0) red[0] = x;
    }
    __syncthreads();
    m = red[0];
    v.x = expf(v.x - m); v.y = expf(v.y - m);
    v.z = expf(v.z - m); v.w = expf(v.w - m);
    float s = v.x + v.y + v.z + v.w;
#pragma unroll
    for (int off = 16; off; off >>= 1)
        s += __shfl_xor_sync(0xffffffffu, s, off);
    __syncthreads();   // red[0] read above must complete before reuse
    if (lane == 0) red[warp] = s;
    __syncthreads();
    if (warp == 0) {
        float x = (lane < 8) ? red[lane] : 0.f;
#pragma unroll
        for (int off = 16; off; off >>= 1)
            x += __shfl_xor_sync(0xffffffffu, x, off);
        if (lane == 0) red[0] = x;
    }
    __syncthreads();
    float inv = 1.f / red[0];
    v.x *= inv; v.y *= inv; v.z *= inv; v.w *= inv;
    reinterpret_cast<float4*>(J + base)[tid] = v;
}

// ---------------------------------------------------------------------------
// Initial sin/cos of phases.
// ---------------------------------------------------------------------------
__global__ void sincos_kernel(const float* __restrict__ ph, float* __restrict__ s,
                              float* __restrict__ c) {
    int i = blockIdx.x * blockDim.x + threadIdx.x;
    float sn, cn;
    sincosf(ph[i], &sn, &cn);
    s[i] = sn;
    c[i] = cn;
}

// ---------------------------------------------------------------------------
// One Kuramoto step. Grid (Nn/32, B*H), 256 threads = 8 warps, 4 rows/warp.
// smem caches sin/cos for the whole (b,h) with stride-9 padding (conflict-free).
// Fuses the phase update + wrap + sincos of the NEW phase (ping-pong s/c).
// ---------------------------------------------------------------------------
__global__ void step_kernel(const float* __restrict__ J, float* __restrict__ ph,
                            const float* __restrict__ s_in, const float* __restrict__ c_in,
                            float* __restrict__ s_out, float* __restrict__ c_out,
                            const float* __restrict__ omega,
                            const float* __restrict__ cs_ptr) {
    extern __shared__ float sm[];
    float* s_sm = sm;             // [Nn*9]
    float* c_sm = sm + Nn * 9;    // [Nn*9]
    int bh = blockIdx.y;
    int b = bh >> 2, h = bh & 3;
    int tid = threadIdx.x;
    for (int idx = tid; idx < Nn * Oo; idx += 256) {
        int j = idx >> 3, o = idx & 7;
        int g = (b * Nn + j) * HO + h * Oo + o;
        s_sm[j * 9 + o] = s_in[g];
        c_sm[j * 9 + o] = c_in[g];
    }
    __syncthreads();
    int warp = tid >> 5, lane = tid & 31;
    int ibase = blockIdx.x * 32 + warp * 4;
    const float* Jrow = J + ((size_t)bh * Nn + ibase) * Nn;
    float accS[4][8] = {}, accC[4][8] = {};
    for (int j = lane; j < Nn; j += 32) {
        float Jv[4];
#pragma unroll
        for (int r = 0; r < 4; r++) Jv[r] = Jrow[(size_t)r * Nn + j];
        float sv[8], cv[8];
#pragma unroll
        for (int o = 0; o < 8; o++) { sv[o] = s_sm[j * 9 + o]; cv[o] = c_sm[j * 9 + o]; }
#pragma unroll
        for (int r = 0; r < 4; r++)
#pragma unroll
            for (int o = 0; o < 8; o++) {
                accS[r][o] = fmaf(Jv[r], sv[o], accS[r][o]);
                accC[r][o] = fmaf(Jv[r], cv[o], accC[r][o]);
            }
    }
#pragma unroll
    for (int r = 0; r < 4; r++)
#pragma unroll
        for (int o = 0; o < 8; o++)
#pragma unroll
            for (int off = 16; off; off >>= 1) {
                accS[r][o] += __shfl_xor_sync(0xffffffffu, accS[r][o], off);
                accC[r][o] += __shfl_xor_sync(0xffffffffu, accC[r][o], off);
            }
    float csv = *cs_ptr;
#pragma unroll
    for (int r = 0; r < 4; r++) {
        float Js = 0.f, Jc = 0.f;
#pragma unroll
        for (int o = 0; o < 8; o++)
            if (lane == o) { Js = accS[r][o]; Jc = accC[r][o]; }
        if (lane < 8) {
            int i = ibase + r;
            int o = lane;
            float si = s_sm[i * 9 + o], ci = c_sm[i * 9 + o];
            float coup = ci * Js - si * Jc;
            int g = (b * Nn + i) * HO + h * Oo + o;
            float np = ph[g] + DT_F * (omega[h * Oo + o] + csv * coup);
            float t = fmodf(np + PI_F, TWO_PI_F);
            if (t < 0.f) t += TWO_PI_F;
            np = t - PI_F;
            ph[g] = np;
            float sn, cn;
            sincosf(np, &sn, &cn);
            s_out[g] = sn;
            c_out[g] = cn;
        }
    }
}

// ---------------------------------------------------------------------------
extern "C" void kernel_launch(void* const* d_in, const int* in_sizes, int n_in,
                              void* d_out, int out_size) {
    const float* x     = (const float*)d_in[0];
    const float* Wq    = (const float*)d_in[1];
    const float* Wk    = (const float*)d_in[2];
    const float* Wp    = (const float*)d_in[3];
    const float* bp    = (const float*)d_in[4];
    const float* Wo    = (const float*)d_in[5];
    const float* bo    = (const float*)d_in[6];
    const float* omega = (const float*)d_in[7];
    const float* cs    = (const float*)d_in[8];
    float* out = (float*)d_out;

    float *q, *k, *ph, *s0, *s1, *c0, *c1, *J;
    cudaGetSymbolAddress((void**)&q,  g_q);
    cudaGetSymbolAddress((void**)&k,  g_k);
    cudaGetSymbolAddress((void**)&ph, g_ph);
    cudaGetSymbolAddress((void**)&s0, g_s0);
    cudaGetSymbolAddress((void**)&s1, g_s1);
    cudaGetSymbolAddress((void**)&c0, g_c0);
    cudaGetSymbolAddress((void**)&c1, g_c1);
    cudaGetSymbolAddress((void**)&J,  g_J);

    dim3 blk(256);
    // projections
    gemm_xwt<<<dim3(Bb * Nn / 64, Dd / 64), blk>>>(x, Wq, nullptr, q, Bb * Nn, Dd, Dd);
    gemm_xwt<<<dim3(Bb * Nn / 64, Dd / 64), blk>>>(x, Wk, nullptr, k, Bb * Nn, Dd, Dd);
    gemm_xwt<<<dim3(Bb * Nn / 64, 1),       blk>>>(x, Wp, bp,      ph, Bb * Nn, Dd, HO);
    // attention J
    scores_kernel<<<dim3(Nn / 64, Nn / 64, Bb * Hh), blk>>>(q, k, J);
    softmax_kernel<<<Bb * Hh * Nn, blk>>>(J);
    // initial sin/cos
    sincos_kernel<<<(Bb * Nn * HO) / 256, blk>>>(ph, s0, c0);
    // 5 oscillator steps (ping-pong s/c)
    size_t smem = (size_t)Nn * 9 * sizeof(float) * 2;   // 73728 B
    cudaFuncSetAttribute(step_kernel, cudaFuncAttributeMaxDynamicSharedMemorySize, (int)smem);
    float* sbuf[2] = {s0, s1};
    float* cbuf[2] = {c0, c1};
    for (int t = 0; t < NSTEPS; t++) {
        step_kernel<<<dim3(Nn / 32, Bb * Hh), blk, smem>>>(
            J, ph, sbuf[t & 1], cbuf[t & 1], sbuf[(t + 1) & 1], cbuf[(t + 1) & 1],
            omega, cs);
    }
    // output: out = cos(final phases) @ Wo^T + bo  (c buffer already in (B,N,H*O))
    const float* cfin = cbuf[NSTEPS & 1];
    gemm_xwt<<<dim3(Bb * Nn / 64, Dd / 64), blk>>>(cfin, Wo, bo, out, Bb * Nn, HO, Dd);
}

// round 3
// speedup vs baseline: 1.5337x; 1.5337x over previous
#include <cuda_runtime.h>
#include <math.h>

#define Bb 2
#define Nn 1024
#define Dd 256
#define Hh 4
#define Oo 8
#define HO 32
#define DKK 64
#define NSTEPS 5
#define DT_F 0.1f
#define PI_F 3.14159265358979323846f
#define TWO_PI_F 6.28318530717958647692f
#define INV_2PI_F 0.15915494309189533577f

// Scratch (no cudaMalloc allowed)
__device__ float g_q[Bb * Nn * Dd];
__device__ float g_k[Bb * Nn * Dd];
__device__ float g_ph[Bb * Nn * HO];
__device__ float g_s0[Bb * Nn * HO];
__device__ float g_s1[Bb * Nn * HO];
__device__ float g_c0[Bb * Nn * HO];
__device__ float g_c1[Bb * Nn * HO];
__device__ float g_J[(size_t)Bb * Hh * Nn * Nn];   // 32 MB, L2-resident

// ---------------------------------------------------------------------------
// Fused projection kernel: one launch computes q = x@Wq^T, k = x@Wk^T,
// ph = x@Wp^T + bp (and sin/cos of ph). grid = (M/64, 9).
// 64(M)x64(N) tile, K-chunks of 64 held transposed in smem -> float4 LDS.
// ---------------------------------------------------------------------------
__global__ __launch_bounds__(256, 2) void proj_kernel(
    const float* __restrict__ x,
    const float* __restrict__ Wq, const float* __restrict__ Wk,
    const float* __restrict__ Wp, const float* __restrict__ bp,
    float* __restrict__ q, float* __restrict__ k,
    float* __restrict__ ph, float* __restrict__ s0, float* __restrict__ c0) {
    __shared__ float As[64][68];   // [kk][m]
    __shared__ float Bs[64][68];   // [kk][n]
    int m0 = blockIdx.x * 64;
    int y = blockIdx.y;
    const float* W;
    int n0, Nout;
    if (y < 4)      { W = Wq; n0 = y * 64;       Nout = Dd; }
    else if (y < 8) { W = Wk; n0 = (y - 4) * 64; Nout = Dd; }
    else            { W = Wp; n0 = 0;            Nout = HO; }
    int tid = threadIdx.x;
    int tx = tid & 15, ty = tid >> 4;
    float acc[4][4] = {};
    for (int kt = 0; kt < Dd; kt += 64) {
        for (int t = tid; t < 64 * 16; t += 256) {
            int r = t >> 4, c4 = (t & 15) * 4;
            float4 va = *(const float4*)&x[(size_t)(m0 + r) * Dd + kt + c4];
            As[c4 + 0][r] = va.x; As[c4 + 1][r] = va.y;
            As[c4 + 2][r] = va.z; As[c4 + 3][r] = va.w;
            float4 vb = make_float4(0.f, 0.f, 0.f, 0.f);
            if (n0 + r < Nout)
                vb = *(const float4*)&W[(size_t)(n0 + r) * Dd + kt + c4];
            Bs[c4 + 0][r] = vb.x; Bs[c4 + 1][r] = vb.y;
            Bs[c4 + 2][r] = vb.z; Bs[c4 + 3][r] = vb.w;
        }
        __syncthreads();
#pragma unroll
        for (int kk = 0; kk < 64; kk++) {
            float4 a = *(const float4*)&As[kk][ty * 4];
            float4 bv = *(const float4*)&Bs[kk][tx * 4];
            float av[4] = {a.x, a.y, a.z, a.w};
            float bw[4] = {bv.x, bv.y, bv.z, bv.w};
#pragma unroll
            for (int i = 0; i < 4; i++)
#pragma unroll
                for (int j = 0; j < 4; j++)
                    acc[i][j] = fmaf(av[i], bw[j], acc[i][j]);
        }
        __syncthreads();
    }
    if (y < 8) {
        float* out = (y < 4) ? q : k;
#pragma unroll
        for (int i = 0; i < 4; i++) {
            int m = m0 + ty * 4 + i;
            float4 v = make_float4(acc[i][0], acc[i][1], acc[i][2], acc[i][3]);
            *(float4*)&out[(size_t)m * Dd + n0 + tx * 4] = v;
        }
    } else if (tx * 4 < HO) {
#pragma unroll
        for (int i = 0; i < 4; i++) {
            int m = m0 + ty * 4 + i;
#pragma unroll
            for (int j = 0; j < 4; j++) {
                int n = tx * 4 + j;
                float p = acc[i][j] + bp[n];
                int g = m * HO + n;
                ph[g] = p;
                float sn, cn;
                sincosf(p, &sn, &cn);
                s0[g] = sn;
                c0[g] = cn;
            }
        }
    }
}

// ---------------------------------------------------------------------------
// Scores: S[bh,i,j] = 0.125 * dot(q_i,k_j), dk=64 fully in smem (transposed).
// 128x128 tile per CTA, 8x8 micro-tile, 4x LDS.128 + 64 FFMA per kk.
// ---------------------------------------------------------------------------
#define SP 132   // smem pitch (floats): 132*4 bytes = multiple of 16
__global__ __launch_bounds__(256, 2) void scores_kernel(
    const float* __restrict__ q, const float* __restrict__ k,
    float* __restrict__ J) {
    extern __shared__ float sm[];
    float* Qs = sm;            // [64][SP]  [kk][i]
    float* Ks = sm + 64 * SP;  // [64][SP]  [kk][j]
    int bh = blockIdx.z;
    int b = bh >> 2, h = bh & 3;
    int i0 = blockIdx.x * 128, j0 = blockIdx.y * 128;
    int tid = threadIdx.x;
    for (int t = tid; t < 128 * 16; t += 256) {
        int r = t >> 4, c4 = (t & 15) * 4;
        float4 vq = *(const float4*)&q[(size_t)(b * Nn + i0 + r) * Dd + h * DKK + c4];
        Qs[(c4 + 0) * SP + r] = vq.x; Qs[(c4 + 1) * SP + r] = vq.y;
        Qs[(c4 + 2) * SP + r] = vq.z; Qs[(c4 + 3) * SP + r] = vq.w;
        float4 vk = *(const float4*)&k[(size_t)(b * Nn + j0 + r) * Dd + h * DKK + c4];
        Ks[(c4 + 0) * SP + r] = vk.x; Ks[(c4 + 1) * SP + r] = vk.y;
        Ks[(c4 + 2) * SP + r] = vk.z; Ks[(c4 + 3) * SP + r] = vk.w;
    }
    __syncthreads();
    int tx = tid & 15, ty = tid >> 4;
    float acc[8][8] = {};
#pragma unroll
    for (int kk = 0; kk < 64; kk++) {
        float4 a0 = *(const float4*)&Qs[kk * SP + ty * 8];
        float4 a1 = *(const float4*)&Qs[kk * SP + ty * 8 + 4];
        float4 b0 = *(const float4*)&Ks[kk * SP + tx * 8];
        float4 b1 = *(const float4*)&Ks[kk * SP + tx * 8 + 4];
        float av[8] = {a0.x, a0.y, a0.z, a0.w, a1.x, a1.y, a1.z, a1.w};
        float bw[8] = {b0.x, b0.y, b0.z, b0.w, b1.x, b1.y, b1.z, b1.w};
#pragma unroll
        for (int i = 0; i < 8; i++)
#pragma unroll
            for (int j = 0; j < 8; j++)
                acc[i][j] = fmaf(av[i], bw[j], acc[i][j]);
    }
    size_t rowbase = ((size_t)bh * Nn + i0 + ty * 8) * Nn + j0 + tx * 8;
#pragma unroll
    for (int i = 0; i < 8; i++) {
        float4 v0 = make_float4(0.125f * acc[i][0], 0.125f * acc[i][1],
                                0.125f * acc[i][2], 0.125f * acc[i][3]);
        float4 v1 = make_float4(0.125f * acc[i][4], 0.125f * acc[i][5],
                                0.125f * acc[i][6], 0.125f * acc[i][7]);
        *(float4*)&J[rowbase + (size_t)i * Nn] = v0;
        *(float4*)&J[rowbase + (size_t)i * Nn + 4] = v1;
    }
}

// ---------------------------------------------------------------------------
// In-place row softmax over J rows of length 1024. One 256-thread CTA per row.
// ---------------------------------------------------------------------------
__global__ void softmax_kernel(float* __restrict__ J) {
    __shared__ float red[8];
    size_t base = (size_t)blockIdx.x * Nn;
    int tid = threadIdx.x, lane = tid & 31, warp = tid >> 5;
    float4 v = reinterpret_cast<float4*>(J + base)[tid];
    float m = fmaxf(fmaxf(v.x, v.y), fmaxf(v.z, v.w));
#pragma unroll
    for (int off = 16; off; off >>= 1)
        m = fmaxf(m, __shfl_xor_sync(0xffffffffu, m, off));
    if (lane == 0) red[warp] = m;
    __syncthreads();
    if (warp == 0) {
        float x = (lane < 8) ? red[lane] : -1e30f;
#pragma unroll
        for (int off = 16; off; off >>= 1)
            x = fmaxf(x, __shfl_xor_sync(0xffffffffu, x, off));
        if (lane == 0) red[0] = x;
    }
    __syncthreads();
    m = red[0];
    v.x = __expf(v.x - m); v.y = __expf(v.y - m);
    v.z = __expf(v.z - m); v.w = __expf(v.w - m);
    float s = v.x + v.y + v.z + v.w;
#pragma unroll
    for (int off = 16; off; off >>= 1)
        s += __shfl_xor_sync(0xffffffffu, s, off);
    __syncthreads();
    if (lane == 0) red[warp] = s;
    __syncthreads();
    if (warp == 0) {
        float x = (lane < 8) ? red[lane] : 0.f;
#pragma unroll
        for (int off = 16; off; off >>= 1)
            x += __shfl_xor_sync(0xffffffffu, x, off);
        if (lane == 0) red[0] = x;
    }
    __syncthreads();
    float inv = 1.f / red[0];
    v.x *= inv; v.y *= inv; v.z *= inv; v.w *= inv;
    reinterpret_cast<float4*>(J + base)[tid] = v;
}

// ---------------------------------------------------------------------------
// One Kuramoto step. Grid (Nn/32, B*H), 256 threads = 8 warps, 4 rows/warp.
// smem caches sin/cos for the whole (b,h) with stride-9 padding.
// ---------------------------------------------------------------------------
__global__ void step_kernel(const float* __restrict__ J, float* __restrict__ ph,
                            const float* __restrict__ s_in, const float* __restrict__ c_in,
                            float* __restrict__ s_out, float* __restrict__ c_out,
                            const float* __restrict__ omega,
                            const float* __restrict__ cs_ptr) {
    extern __shared__ float sm[];
    float* s_sm = sm;             // [Nn*9]
    float* c_sm = sm + Nn * 9;    // [Nn*9]
    int bh = blockIdx.y;
    int b = bh >> 2, h = bh & 3;
    int tid = threadIdx.x;
    // vectorized preamble: 2048 float4 per buffer
    for (int idx = tid; idx < Nn * 2; idx += 256) {
        int j = idx >> 1, q4 = (idx & 1) * 4;
        int g4 = ((b * Nn + j) * HO + h * Oo + q4) >> 2;
        float4 vs = reinterpret_cast<const float4*>(s_in)[g4];
        float4 vc = reinterpret_cast<const float4*>(c_in)[g4];
        int o = j * 9 + q4;
        s_sm[o + 0] = vs.x; s_sm[o + 1] = vs.y; s_sm[o + 2] = vs.z; s_sm[o + 3] = vs.w;
        c_sm[o + 0] = vc.x; c_sm[o + 1] = vc.y; c_sm[o + 2] = vc.z; c_sm[o + 3] = vc.w;
    }
    __syncthreads();
    int warp = tid >> 5, lane = tid & 31;
    int ibase = blockIdx.x * 32 + warp * 4;
    const float* Jrow = J + ((size_t)bh * Nn + ibase) * Nn;
    float accS[4][8] = {}, accC[4][8] = {};
    for (int j = lane; j < Nn; j += 32) {
        float Jv[4];
#pragma unroll
        for (int r = 0; r < 4; r++) Jv[r] = Jrow[(size_t)r * Nn + j];
        float sv[8], cv[8];
#pragma unroll
        for (int o = 0; o < 8; o++) { sv[o] = s_sm[j * 9 + o]; cv[o] = c_sm[j * 9 + o]; }
#pragma unroll
        for (int r = 0; r < 4; r++)
#pragma unroll
            for (int o = 0; o < 8; o++) {
                accS[r][o] = fmaf(Jv[r], sv[o], accS[r][o]);
                accC[r][o] = fmaf(Jv[r], cv[o], accC[r][o]);
            }
    }
#pragma unroll
    for (int r = 0; r < 4; r++)
#pragma unroll
        for (int o = 0; o < 8; o++)
#pragma unroll
            for (int off = 16; off; off >>= 1) {
                accS[r][o] += __shfl_xor_sync(0xffffffffu, accS[r][o], off);
                accC[r][o] += __shfl_xor_sync(0xffffffffu, accC[r][o], off);
            }
    float csv = *cs_ptr;
#pragma unroll
    for (int r = 0; r < 4; r++) {
        float Js = 0.f, Jc = 0.f;
#pragma unroll
        for (int o = 0; o < 8; o++)
            if (lane == o) { Js = accS[r][o]; Jc = accC[r][o]; }
        if (lane < 8) {
            int i = ibase + r;
            int o = lane;
            float si = s_sm[i * 9 + o], ci = c_sm[i * 9 + o];
            float coup = ci * Js - si * Jc;
            int g = (b * Nn + i) * HO + h * Oo + o;
            float np = ph[g] + DT_F * (omega[h * Oo + o] + csv * coup);
            // remainder(np + pi, 2pi) - pi   (matches jnp.remainder semantics)
            float v = np + PI_F;
            np = v - floorf(v * INV_2PI_F) * TWO_PI_F - PI_F;
            ph[g] = np;
            float sn, cn;
            sincosf(np, &sn, &cn);
            s_out[g] = sn;
            c_out[g] = cn;
        }
    }
}

// ---------------------------------------------------------------------------
// Final small GEMM: out = C @ Wo^T + bo, K=32.
// ---------------------------------------------------------------------------
__global__ void gemm_out(const float* __restrict__ X, const float* __restrict__ W,
                         const float* __restrict__ bias, float* __restrict__ out) {
    __shared__ float As[64][33];
    __shared__ float Ws[64][33];
    int m0 = blockIdx.x * 64, n0 = blockIdx.y * 64;
    int tid = threadIdx.x;
    int tx = tid & 15, ty = tid >> 4;
    float acc[4][4] = {};
    for (int li = tid; li < 64 * 32; li += 256) {
        int r = li >> 5, c = li & 31;
        As[r][c] = X[(size_t)(m0 + r) * HO + c];
        Ws[r][c] = W[(size_t)(n0 + r) * HO + c];
    }
    __syncthreads();
#pragma unroll
    for (int kk = 0; kk < 32; kk++) {
        float a[4], bb[4];
#pragma unroll
        for (int i = 0; i < 4; i++) a[i] = As[ty * 4 + i][kk];
#pragma unroll
        for (int j = 0; j < 4; j++) bb[j] = Ws[tx * 4 + j][kk];
#pragma unroll
        for (int i = 0; i < 4; i++)
#pragma unroll
            for (int j = 0; j < 4; j++)
                acc[i][j] = fmaf(a[i], bb[j], acc[i][j]);
    }
#pragma unroll
    for (int i = 0; i < 4; i++) {
        int m = m0 + ty * 4 + i;
#pragma unroll
        for (int j = 0; j < 4; j++) {
            int n = n0 + tx * 4 + j;
            out[(size_t)m * Dd + n] = acc[i][j] + bias[n];
        }
    }
}

// ---------------------------------------------------------------------------
extern "C" void kernel_launch(void* const* d_in, const int* in_sizes, int n_in,
                              void* d_out, int out_size) {
    const float* x     = (const float*)d_in[0];
    const float* Wq    = (const float*)d_in[1];
    const float* Wk    = (const float*)d_in[2];
    const float* Wp    = (const float*)d_in[3];
    const float* bp    = (const float*)d_in[4];
    const float* Wo    = (const float*)d_in[5];
    const float* bo    = (const float*)d_in[6];
    const float* omega = (const float*)d_in[7];
    const float* cs    = (const float*)d_in[8];
    float* out = (float*)d_out;

    float *q, *k, *ph, *s0, *s1, *c0, *c1, *J;
    cudaGetSymbolAddress((void**)&q,  g_q);
    cudaGetSymbolAddress((void**)&k,  g_k);
    cudaGetSymbolAddress((void**)&ph, g_ph);
    cudaGetSymbolAddress((void**)&s0, g_s0);
    cudaGetSymbolAddress((void**)&s1, g_s1);
    cudaGetSymbolAddress((void**)&c0, g_c0);
    cudaGetSymbolAddress((void**)&c1, g_c1);
    cudaGetSymbolAddress((void**)&J,  g_J);

    dim3 blk(256);
    // fused projections (q, k, ph + sincos)
    proj_kernel<<<dim3(Bb * Nn / 64, 9), blk>>>(x, Wq, Wk, Wp, bp, q, k, ph, s0, c0);
    // attention J
    size_t smem_sc = (size_t)2 * 64 * SP * sizeof(float);   // 67584 B
    cudaFuncSetAttribute(scores_kernel, cudaFuncAttributeMaxDynamicSharedMemorySize, (int)smem_sc);
    scores_kernel<<<dim3(Nn / 128, Nn / 128, Bb * Hh), blk, smem_sc>>>(q, k, J);
    softmax_kernel<<<Bb * Hh * Nn, blk>>>(J);
    // 5 oscillator steps (ping-pong s/c)
    size_t smem = (size_t)Nn * 9 * sizeof(float) * 2;   // 73728 B
    cudaFuncSetAttribute(step_kernel, cudaFuncAttributeMaxDynamicSharedMemorySize, (int)smem);
    float* sbuf[2] = {s0, s1};
    float* cbuf[2] = {c0, c1};
    for (int t = 0; t < NSTEPS; t++) {
        step_kernel<<<dim3(Nn / 32, Bb * Hh), blk, smem>>>(
            J, ph, sbuf[t & 1], cbuf[t & 1], sbuf[(t + 1) & 1], cbuf[(t + 1) & 1],
            omega, cs);
    }
    // output: out = cos(final phases) @ Wo^T + bo
    const float* cfin = cbuf[NSTEPS & 1];
    gemm_out<<<dim3(Bb * Nn / 64, Dd / 64), blk>>>(cfin, Wo, bo, out);
}

// round 5
// speedup vs baseline: 1.5995x; 1.0429x over previous
#include <cuda_runtime.h>
#include <math.h>

#define Bb 2
#define Nn 1024
#define Dd 256
#define Hh 4
#define Oo 8
#define HO 32
#define DKK 64
#define NSTEPS 5
#define DT_F 0.1f
#define PI_F 3.14159265358979323846f
#define TWO_PI_F 6.28318530717958647692f
#define INV_2PI_F 0.15915494309189533577f

#define GTOT (Bb * Nn * HO)   // 65536
#define ITILE 128
#define JCH 64
#define NC (Nn / JCH)         // 16
#define JSTR 65               // smem stride for J tile (conflict-free)

// Scratch (no cudaMalloc allowed)
__device__ float g_q[Bb * Nn * Dd];
__device__ float g_k[Bb * Nn * Dd];
__device__ float g_ph[GTOT];
__device__ float g_s0[GTOT];
__device__ float g_s1[GTOT];
__device__ float g_c0[GTOT];
__device__ float g_c1[GTOT];
__device__ float g_pS[NC * GTOT];   // 4 MB partial J@sin
__device__ float g_pC[NC * GTOT];   // 4 MB partial J@cos
__device__ float g_J[(size_t)Bb * Hh * Nn * Nn];   // 32 MB, L2-resident

// ---------------------------------------------------------------------------
// Fused projection kernel: q = x@Wq^T, k = x@Wk^T, ph = x@Wp^T + bp (+sincos).
// ---------------------------------------------------------------------------
__global__ __launch_bounds__(256, 2) void proj_kernel(
    const float* __restrict__ x,
    const float* __restrict__ Wq, const float* __restrict__ Wk,
    const float* __restrict__ Wp, const float* __restrict__ bp,
    float* __restrict__ q, float* __restrict__ k,
    float* __restrict__ ph, float* __restrict__ s0, float* __restrict__ c0) {
    __shared__ float As[64][68];   // [kk][m]
    __shared__ float Bs[64][68];   // [kk][n]
    int m0 = blockIdx.x * 64;
    int y = blockIdx.y;
    const float* W;
    int n0, Nout;
    if (y < 4)      { W = Wq; n0 = y * 64;       Nout = Dd; }
    else if (y < 8) { W = Wk; n0 = (y - 4) * 64; Nout = Dd; }
    else            { W = Wp; n0 = 0;            Nout = HO; }
    int tid = threadIdx.x;
    int tx = tid & 15, ty = tid >> 4;
    float acc[4][4] = {};
    for (int kt = 0; kt < Dd; kt += 64) {
        for (int t = tid; t < 64 * 16; t += 256) {
            int r = t >> 4, c4 = (t & 15) * 4;
            float4 va = *(const float4*)&x[(size_t)(m0 + r) * Dd + kt + c4];
            As[c4 + 0][r] = va.x; As[c4 + 1][r] = va.y;
            As[c4 + 2][r] = va.z; As[c4 + 3][r] = va.w;
            float4 vb = make_float4(0.f, 0.f, 0.f, 0.f);
            if (n0 + r < Nout)
                vb = *(const float4*)&W[(size_t)(n0 + r) * Dd + kt + c4];
            Bs[c4 + 0][r] = vb.x; Bs[c4 + 1][r] = vb.y;
            Bs[c4 + 2][r] = vb.z; Bs[c4 + 3][r] = vb.w;
        }
        __syncthreads();
#pragma unroll
        for (int kk = 0; kk < 64; kk++) {
            float4 a = *(const float4*)&As[kk][ty * 4];
            float4 bv = *(const float4*)&Bs[kk][tx * 4];
            float av[4] = {a.x, a.y, a.z, a.w};
            float bw[4] = {bv.x, bv.y, bv.z, bv.w};
#pragma unroll
            for (int i = 0; i < 4; i++)
#pragma unroll
                for (int j = 0; j < 4; j++)
                    acc[i][j] = fmaf(av[i], bw[j], acc[i][j]);
        }
        __syncthreads();
    }
    if (y < 8) {
        float* out = (y < 4) ? q : k;
#pragma unroll
        for (int i = 0; i < 4; i++) {
            int m = m0 + ty * 4 + i;
            float4 v = make_float4(acc[i][0], acc[i][1], acc[i][2], acc[i][3]);
            *(float4*)&out[(size_t)m * Dd + n0 + tx * 4] = v;
        }
    } else if (tx * 4 < HO) {
#pragma unroll
        for (int i = 0; i < 4; i++) {
            int m = m0 + ty * 4 + i;
#pragma unroll
            for (int j = 0; j < 4; j++) {
                int n = tx * 4 + j;
                float p = acc[i][j] + bp[n];
                int g = m * HO + n;
                ph[g] = p;
                float sn, cn;
                sincosf(p, &sn, &cn);
                s0[g] = sn;
                c0[g] = cn;
            }
        }
    }
}

// ---------------------------------------------------------------------------
// Scores: S[bh,i,j] = 0.125 * dot(q_i,k_j). 128x128 tile, 8x8 micro-tile.
// ---------------------------------------------------------------------------
#define SP 132
__global__ __launch_bounds__(256, 2) void scores_kernel(
    const float* __restrict__ q, const float* __restrict__ k,
    float* __restrict__ J) {
    extern __shared__ float sm[];
    float* Qs = sm;            // [64][SP]
    float* Ks = sm + 64 * SP;  // [64][SP]
    int bh = blockIdx.z;
    int b = bh >> 2, h = bh & 3;
    int i0 = blockIdx.x * 128, j0 = blockIdx.y * 128;
    int tid = threadIdx.x;
    for (int t = tid; t < 128 * 16; t += 256) {
        int r = t >> 4, c4 = (t & 15) * 4;
        float4 vq = *(const float4*)&q[(size_t)(b * Nn + i0 + r) * Dd + h * DKK + c4];
        Qs[(c4 + 0) * SP + r] = vq.x; Qs[(c4 + 1) * SP + r] = vq.y;
        Qs[(c4 + 2) * SP + r] = vq.z; Qs[(c4 + 3) * SP + r] = vq.w;
        float4 vk = *(const float4*)&k[(size_t)(b * Nn + j0 + r) * Dd + h * DKK + c4];
        Ks[(c4 + 0) * SP + r] = vk.x; Ks[(c4 + 1) * SP + r] = vk.y;
        Ks[(c4 + 2) * SP + r] = vk.z; Ks[(c4 + 3) * SP + r] = vk.w;
    }
    __syncthreads();
    int tx = tid & 15, ty = tid >> 4;
    float acc[8][8] = {};
#pragma unroll
    for (int kk = 0; kk < 64; kk++) {
        float4 a0 = *(const float4*)&Qs[kk * SP + ty * 8];
        float4 a1 = *(const float4*)&Qs[kk * SP + ty * 8 + 4];
        float4 b0 = *(const float4*)&Ks[kk * SP + tx * 8];
        float4 b1 = *(const float4*)&Ks[kk * SP + tx * 8 + 4];
        float av[8] = {a0.x, a0.y, a0.z, a0.w, a1.x, a1.y, a1.z, a1.w};
        float bw[8] = {b0.x, b0.y, b0.z, b0.w, b1.x, b1.y, b1.z, b1.w};
#pragma unroll
        for (int i = 0; i < 8; i++)
#pragma unroll
            for (int j = 0; j < 8; j++)
                acc[i][j] = fmaf(av[i], bw[j], acc[i][j]);
    }
    size_t rowbase = ((size_t)bh * Nn + i0 + ty * 8) * Nn + j0 + tx * 8;
#pragma unroll
    for (int i = 0; i < 8; i++) {
        float4 v0 = make_float4(0.125f * acc[i][0], 0.125f * acc[i][1],
                                0.125f * acc[i][2], 0.125f * acc[i][3]);
        float4 v1 = make_float4(0.125f * acc[i][4], 0.125f * acc[i][5],
                                0.125f * acc[i][6], 0.125f * acc[i][7]);
        *(float4*)&J[rowbase + (size_t)i * Nn] = v0;
        *(float4*)&J[rowbase + (size_t)i * Nn + 4] = v1;
    }
}

// ---------------------------------------------------------------------------
// In-place row softmax over J rows of length 1024.
// ---------------------------------------------------------------------------
__global__ void softmax_kernel(float* __restrict__ J) {
    __shared__ float red[8];
    size_t base = (size_t)blockIdx.x * Nn;
    int tid = threadIdx.x, lane = tid & 31, warp = tid >> 5;
    float4 v = reinterpret_cast<float4*>(J + base)[tid];
    float m = fmaxf(fmaxf(v.x, v.y), fmaxf(v.z, v.w));
#pragma unroll
    for (int off = 16; off; off >>= 1)
        m = fmaxf(m, __shfl_xor_sync(0xffffffffu, m, off));
    if (lane == 0) red[warp] = m;
    __syncthreads();
    if (warp == 0) {
        float x = (lane < 8) ? red[lane] : -1e30f;
#pragma unroll
        for (int off = 16; off; off >>= 1)
            x = fmaxf(x, __shfl_xor_sync(0xffffffffu, x, off));
        if (lane == 0) red[0] = x;
    }
    __syncthreads();
    m = red[0];
    v.x = __expf(v.x - m); v.y = __expf(v.y - m);
    v.z = __expf(v.z - m); v.w = __expf(v.w - m);
    float s = v.x + v.y + v.z + v.w;
#pragma unroll
    for (int off = 16; off; off >>= 1)
        s += __shfl_xor_sync(0xffffffffu, s, off);
    __syncthreads();
    if (lane == 0) red[warp] = s;
    __syncthreads();
    if (warp == 0) {
        float x = (lane < 8) ? red[lane] : 0.f;
#pragma unroll
        for (int off = 16; off; off >>= 1)
            x += __shfl_xor_sync(0xffffffffu, x, off);
        if (lane == 0) red[0] = x;
    }
    __syncthreads();
    float inv = 1.f / red[0];
    v.x *= inv; v.y *= inv; v.z *= inv; v.w *= inv;
    reinterpret_cast<float4*>(J + base)[tid] = v;
}

// ---------------------------------------------------------------------------
// Step part 1: partial sums pS/pC[jc][g] = sum_{j in chunk} J[bh,i,j]*{s,c}[j].
// Grid (Nn/ITILE=8, NC=16, 8 bh), 256 threads. Thread = (row, o-quad).
// Per j: 1 LDS.32 (J, broadcast x2) + 2 LDS.128 (s,c) + 8 FFMA. No shuffles.
// ---------------------------------------------------------------------------
__global__ __launch_bounds__(256, 5) void step_part(
    const float* __restrict__ J,
    const float* __restrict__ s_in, const float* __restrict__ c_in,
    float* __restrict__ pS, float* __restrict__ pC) {
    __shared__ float Jt[ITILE * JSTR];   // 33280 B
    __shared__ float ss[JCH * 8];        // 2 KB
    __shared__ float cs[JCH * 8];        // 2 KB
    int i0 = blockIdx.x * ITILE;
    int j0 = blockIdx.y * JCH;
    int bh = blockIdx.z;
    int b = bh >> 2, h = bh & 3;
    int tid = threadIdx.x;
    // Load J tile: 128 rows x 64 cols (2048 float4, coalesced 256B per row)
    const float* Jb = J + ((size_t)bh * Nn + i0) * Nn + j0;
#pragma unroll
    for (int it = 0; it < 8; it++) {
        int idx = tid + it * 256;
        int r = idx >> 4, c4 = (idx & 15) * 4;
        float4 v = *(const float4*)&Jb[(size_t)r * Nn + c4];
        float* d = &Jt[r * JSTR + c4];
        d[0] = v.x; d[1] = v.y; d[2] = v.z; d[3] = v.w;
    }
    // Load s/c chunk (64 j x 8 o each)
    {
        int t = tid & 127;
        int j = t >> 1, qo = (t & 1) * 4;
        int g4 = ((b * Nn + j0 + j) * HO + h * Oo + qo) >> 2;
        if (tid < 128) {
            float4 v = reinterpret_cast<const float4*>(s_in)[g4];
            *(float4*)&ss[j * 8 + qo] = v;
        } else {
            float4 v = reinterpret_cast<const float4*>(c_in)[g4];
            *(float4*)&cs[j * 8 + qo] = v;
        }
    }
    __syncthreads();
    int row = tid >> 1, qo = (tid & 1) * 4;
    const float* Jr = &Jt[row * JSTR];
    float aS0 = 0.f, aS1 = 0.f, aS2 = 0.f, aS3 = 0.f;
    float aC0 = 0.f, aC1 = 0.f, aC2 = 0.f, aC3 = 0.f;
#pragma unroll 16
    for (int j = 0; j < JCH; j++) {
        float jv = Jr[j];
        float4 sv = *(const float4*)&ss[j * 8 + qo];
        float4 cv = *(const float4*)&cs[j * 8 + qo];
        aS0 = fmaf(jv, sv.x, aS0); aS1 = fmaf(jv, sv.y, aS1);
        aS2 = fmaf(jv, sv.z, aS2); aS3 = fmaf(jv, sv.w, aS3);
        aC0 = fmaf(jv, cv.x, aC0); aC1 = fmaf(jv, cv.y, aC1);
        aC2 = fmaf(jv, cv.z, aC2); aC3 = fmaf(jv, cv.w, aC3);
    }
    size_t pbase = (size_t)blockIdx.y * GTOT +
                   ((size_t)(b * Nn + i0 + row) * HO + h * Oo + qo);
    *(float4*)&pS[pbase] = make_float4(aS0, aS1, aS2, aS3);
    *(float4*)&pC[pbase] = make_float4(aC0, aC1, aC2, aC3);
}

// ---------------------------------------------------------------------------
// Step part 2: reduce NC partials, phase update + wrap + sincos.
// ---------------------------------------------------------------------------
__global__ void step_update(const float* __restrict__ pS, const float* __restrict__ pC,
                            float* __restrict__ ph,
                            const float* __restrict__ s_in, const float* __restrict__ c_in,
                            float* __restrict__ s_out, float* __restrict__ c_out,
                            const float* __restrict__ omega,
                            const float* __restrict__ cs_ptr) {
    int g = blockIdx.x * 256 + threadIdx.x;
    float js = 0.f, jc = 0.f;
#pragma unroll
    for (int c = 0; c < NC; c++) {
        js += pS[(size_t)c * GTOT + g];
        jc += pC[(size_t)c * GTOT + g];
    }
    float si = s_in[g], ci = c_in[g];
    float coup = ci * js - si * jc;
    float np = ph[g] + DT_F * (omega[g & 31] + (*cs_ptr) * coup);
    float v = np + PI_F;
    np = v - floorf(v * INV_2PI_F) * TWO_PI_F - PI_F;
    ph[g] = np;
    float sn, cn;
    sincosf(np, &sn, &cn);
    s_out[g] = sn;
    c_out[g] = cn;
}

// ---------------------------------------------------------------------------
// Final small GEMM: out = C @ Wo^T + bo, K=32.
// ---------------------------------------------------------------------------
__global__ void gemm_out(const float* __restrict__ X, const float* __restrict__ W,
                         const float* __restrict__ bias, float* __restrict__ out) {
    __shared__ float As[64][33];
    __shared__ float Ws[64][33];
    int m0 = blockIdx.x * 64, n0 = blockIdx.y * 64;
    int tid = threadIdx.x;
    int tx = tid & 15, ty = tid >> 4;
    float acc[4][4] = {};
    for (int li = tid; li < 64 * 32; li += 256) {
        int r = li >> 5, c = li & 31;
        As[r][c] = X[(size_t)(m0 + r) * HO + c];
        Ws[r][c] = W[(size_t)(n0 + r) * HO + c];
    }
    __syncthreads();
#pragma unroll
    for (int kk = 0; kk < 32; kk++) {
        float a[4], bb[4];
#pragma unroll
        for (int i = 0; i < 4; i++) a[i] = As[ty * 4 + i][kk];
#pragma unroll
        for (int j = 0; j < 4; j++) bb[j] = Ws[tx * 4 + j][kk];
#pragma unroll
        for (int i = 0; i < 4; i++)
#pragma unroll
            for (int j = 0; j < 4; j++)
                acc[i][j] = fmaf(a[i], bb[j], acc[i][j]);
    }
#pragma unroll
    for (int i = 0; i < 4; i++) {
        int m = m0 + ty * 4 + i;
#pragma unroll
        for (int j = 0; j < 4; j++) {
            int n = n0 + tx * 4 + j;
            out[(size_t)m * Dd + n] = acc[i][j] + bias[n];
        }
    }
}

// ---------------------------------------------------------------------------
extern "C" void kernel_launch(void* const* d_in, const int* in_sizes, int n_in,
                              void* d_out, int out_size) {
    const float* x     = (const float*)d_in[0];
    const float* Wq    = (const float*)d_in[1];
    const float* Wk    = (const float*)d_in[2];
    const float* Wp    = (const float*)d_in[3];
    const float* bp    = (const float*)d_in[4];
    const float* Wo    = (const float*)d_in[5];
    const float* bo    = (const float*)d_in[6];
    const float* omega = (const float*)d_in[7];
    const float* cs    = (const float*)d_in[8];
    float* out = (float*)d_out;

    float *q, *k, *ph, *s0, *s1, *c0, *c1, *J, *pS, *pC;
    cudaGetSymbolAddress((void**)&q,  g_q);
    cudaGetSymbolAddress((void**)&k,  g_k);
    cudaGetSymbolAddress((void**)&ph, g_ph);
    cudaGetSymbolAddress((void**)&s0, g_s0);
    cudaGetSymbolAddress((void**)&s1, g_s1);
    cudaGetSymbolAddress((void**)&c0, g_c0);
    cudaGetSymbolAddress((void**)&c1, g_c1);
    cudaGetSymbolAddress((void**)&J,  g_J);
    cudaGetSymbolAddress((void**)&pS, g_pS);
    cudaGetSymbolAddress((void**)&pC, g_pC);

    dim3 blk(256);
    // fused projections (q, k, ph + sincos)
    proj_kernel<<<dim3(Bb * Nn / 64, 9), blk>>>(x, Wq, Wk, Wp, bp, q, k, ph, s0, c0);
    // attention J
    size_t smem_sc = (size_t)2 * 64 * SP * sizeof(float);
    cudaFuncSetAttribute(scores_kernel, cudaFuncAttributeMaxDynamicSharedMemorySize, (int)smem_sc);
    scores_kernel<<<dim3(Nn / 128, Nn / 128, Bb * Hh), blk, smem_sc>>>(q, k, J);
    softmax_kernel<<<Bb * Hh * Nn, blk>>>(J);
    // 5 oscillator steps (split-j partials + reduce/update, ping-pong s/c)
    float* sbuf[2] = {s0, s1};
    float* cbuf[2] = {c0, c1};
    for (int t = 0; t < NSTEPS; t++) {
        step_part<<<dim3(Nn / ITILE, NC, Bb * Hh), blk>>>(
            J, sbuf[t & 1], cbuf[t & 1], pS, pC);
        step_update<<<GTOT / 256, blk>>>(
            pS, pC, ph, sbuf[t & 1], cbuf[t & 1],
            sbuf[(t + 1) & 1], cbuf[(t + 1) & 1], omega, cs);
    }
    // output: out = cos(final phases) @ Wo^T + bo
    const float* cfin = cbuf[NSTEPS & 1];
    gemm_out<<<dim3(Bb * Nn / 64, Dd / 64), blk>>>(cfin, Wo, bo, out);
}

// round 7
// speedup vs baseline: 1.6331x; 1.0210x over previous
#include <cuda_runtime.h>
#include <math.h>

#define Bb 2
#define Nn 1024
#define Dd 256
#define Hh 4
#define Oo 8
#define HO 32
#define DKK 64
#define NSTEPS 5
#define DT_F 0.1f
#define PI_F 3.14159265358979323846f
#define TWO_PI_F 6.28318530717958647692f
#define INV_2PI_F 0.15915494309189533577f

#define GTOT (Bb * Nn * HO)   // 65536
#define ITILE 512
#define JCH 32
#define NC (Nn / JCH)         // 32
#define JSTR 33               // J tile smem stride (odd -> conflict-free)

// Scratch (no cudaMalloc allowed)
__device__ float g_q[Bb * Nn * Dd];
__device__ float g_k[Bb * Nn * Dd];
__device__ float g_ph[GTOT];
__device__ float g_s0[GTOT];
__device__ float g_s1[GTOT];
__device__ float g_c0[GTOT];
__device__ float g_c1[GTOT];
__device__ float g_pS[NC * GTOT];   // 8 MB partial J@sin
__device__ float g_pC[NC * GTOT];   // 8 MB partial J@cos
__device__ float g_J[(size_t)Bb * Hh * Nn * Nn];   // 32 MB

// ---------------------------------------------------------------------------
// Fused projection kernel: q = x@Wq^T, k = x@Wk^T, ph = x@Wp^T + bp (+sincos).
// ---------------------------------------------------------------------------
__global__ __launch_bounds__(256, 2) void proj_kernel(
    const float* __restrict__ x,
    const float* __restrict__ Wq, const float* __restrict__ Wk,
    const float* __restrict__ Wp, const float* __restrict__ bp,
    float* __restrict__ q, float* __restrict__ k,
    float* __restrict__ ph, float* __restrict__ s0, float* __restrict__ c0) {
    __shared__ float As[64][68];   // [kk][m]
    __shared__ float Bs[64][68];   // [kk][n]
    int m0 = blockIdx.x * 64;
    int y = blockIdx.y;
    const float* W;
    int n0, Nout;
    if (y < 4)      { W = Wq; n0 = y * 64;       Nout = Dd; }
    else if (y < 8) { W = Wk; n0 = (y - 4) * 64; Nout = Dd; }
    else            { W = Wp; n0 = 0;            Nout = HO; }
    int tid = threadIdx.x;
    int tx = tid & 15, ty = tid >> 4;
    float acc[4][4] = {};
    for (int kt = 0; kt < Dd; kt += 64) {
        for (int t = tid; t < 64 * 16; t += 256) {
            int r = t >> 4, c4 = (t & 15) * 4;
            float4 va = *(const float4*)&x[(size_t)(m0 + r) * Dd + kt + c4];
            As[c4 + 0][r] = va.x; As[c4 + 1][r] = va.y;
            As[c4 + 2][r] = va.z; As[c4 + 3][r] = va.w;
            float4 vb = make_float4(0.f, 0.f, 0.f, 0.f);
            if (n0 + r < Nout)
                vb = *(const float4*)&W[(size_t)(n0 + r) * Dd + kt + c4];
            Bs[c4 + 0][r] = vb.x; Bs[c4 + 1][r] = vb.y;
            Bs[c4 + 2][r] = vb.z; Bs[c4 + 3][r] = vb.w;
        }
        __syncthreads();
#pragma unroll
        for (int kk = 0; kk < 64; kk++) {
            float4 a = *(const float4*)&As[kk][ty * 4];
            float4 bv = *(const float4*)&Bs[kk][tx * 4];
            float av[4] = {a.x, a.y, a.z, a.w};
            float bw[4] = {bv.x, bv.y, bv.z, bv.w};
#pragma unroll
            for (int i = 0; i < 4; i++)
#pragma unroll
                for (int j = 0; j < 4; j++)
                    acc[i][j] = fmaf(av[i], bw[j], acc[i][j]);
        }
        __syncthreads();
    }
    if (y < 8) {
        float* out = (y < 4) ? q : k;
#pragma unroll
        for (int i = 0; i < 4; i++) {
            int m = m0 + ty * 4 + i;
            float4 v = make_float4(acc[i][0], acc[i][1], acc[i][2], acc[i][3]);
            *(float4*)&out[(size_t)m * Dd + n0 + tx * 4] = v;
        }
    } else if (tx * 4 < HO) {
#pragma unroll
        for (int i = 0; i < 4; i++) {
            int m = m0 + ty * 4 + i;
#pragma unroll
            for (int j = 0; j < 4; j++) {
                int n = tx * 4 + j;
                float p = acc[i][j] + bp[n];
                int g = m * HO + n;
                ph[g] = p;
                float sn, cn;
                sincosf(p, &sn, &cn);
                s0[g] = sn;
                c0[g] = cn;
            }
        }
    }
}

// ---------------------------------------------------------------------------
// Scores: S[bh,i,j] = 0.125 * dot(q_i,k_j). 128x128 tile, 8x8 micro-tile.
// ---------------------------------------------------------------------------
#define SP 132
__global__ __launch_bounds__(256, 2) void scores_kernel(
    const float* __restrict__ q, const float* __restrict__ k,
    float* __restrict__ J) {
    extern __shared__ float sm[];
    float* Qs = sm;            // [64][SP]
    float* Ks = sm + 64 * SP;  // [64][SP]
    int bh = blockIdx.z;
    int b = bh >> 2, h = bh & 3;
    int i0 = blockIdx.x * 128, j0 = blockIdx.y * 128;
    int tid = threadIdx.x;
    for (int t = tid; t < 128 * 16; t += 256) {
        int r = t >> 4, c4 = (t & 15) * 4;
        float4 vq = *(const float4*)&q[(size_t)(b * Nn + i0 + r) * Dd + h * DKK + c4];
        Qs[(c4 + 0) * SP + r] = vq.x; Qs[(c4 + 1) * SP + r] = vq.y;
        Qs[(c4 + 2) * SP + r] = vq.z; Qs[(c4 + 3) * SP + r] = vq.w;
        float4 vk = *(const float4*)&k[(size_t)(b * Nn + j0 + r) * Dd + h * DKK + c4];
        Ks[(c4 + 0) * SP + r] = vk.x; Ks[(c4 + 1) * SP + r] = vk.y;
        Ks[(c4 + 2) * SP + r] = vk.z; Ks[(c4 + 3) * SP + r] = vk.w;
    }
    __syncthreads();
    int tx = tid & 15, ty = tid >> 4;
    float acc[8][8] = {};
#pragma unroll
    for (int kk = 0; kk < 64; kk++) {
        float4 a0 = *(const float4*)&Qs[kk * SP + ty * 8];
        float4 a1 = *(const float4*)&Qs[kk * SP + ty * 8 + 4];
        float4 b0 = *(const float4*)&Ks[kk * SP + tx * 8];
        float4 b1 = *(const float4*)&Ks[kk * SP + tx * 8 + 4];
        float av[8] = {a0.x, a0.y, a0.z, a0.w, a1.x, a1.y, a1.z, a1.w};
        float bw[8] = {b0.x, b0.y, b0.z, b0.w, b1.x, b1.y, b1.z, b1.w};
#pragma unroll
        for (int i = 0; i < 8; i++)
#pragma unroll
            for (int j = 0; j < 8; j++)
                acc[i][j] = fmaf(av[i], bw[j], acc[i][j]);
    }
    size_t rowbase = ((size_t)bh * Nn + i0 + ty * 8) * Nn + j0 + tx * 8;
#pragma unroll
    for (int i = 0; i < 8; i++) {
        float4 v0 = make_float4(0.125f * acc[i][0], 0.125f * acc[i][1],
                                0.125f * acc[i][2], 0.125f * acc[i][3]);
        float4 v1 = make_float4(0.125f * acc[i][4], 0.125f * acc[i][5],
                                0.125f * acc[i][6], 0.125f * acc[i][7]);
        *(float4*)&J[rowbase + (size_t)i * Nn] = v0;
        *(float4*)&J[rowbase + (size_t)i * Nn + 4] = v1;
    }
}

// ---------------------------------------------------------------------------
// In-place row softmax over J rows of length 1024.
// ---------------------------------------------------------------------------
__global__ void softmax_kernel(float* __restrict__ J) {
    __shared__ float red[8];
    size_t base = (size_t)blockIdx.x * Nn;
    int tid = threadIdx.x, lane = tid & 31, warp = tid >> 5;
    float4 v = reinterpret_cast<float4*>(J + base)[tid];
    float m = fmaxf(fmaxf(v.x, v.y), fmaxf(v.z, v.w));
#pragma unroll
    for (int off = 16; off; off >>= 1)
        m = fmaxf(m, __shfl_xor_sync(0xffffffffu, m, off));
    if (lane == 0) red[warp] = m;
    __syncthreads();
    if (warp == 0) {
        float x = (lane < 8) ? red[lane] : -1e30f;
#pragma unroll
        for (int off = 16; off; off >>= 1)
            x = fmaxf(x, __shfl_xor_sync(0xffffffffu, x, off));
        if (lane == 0) red[0] = x;
    }
    __syncthreads();
    m = red[0];
    v.x = __expf(v.x - m); v.y = __expf(v.y - m);
    v.z = __expf(v.z - m); v.w = __expf(v.w - m);
    float s = v.x + v.y + v.z + v.w;
#pragma unroll
    for (int off = 16; off; off >>= 1)
        s += __shfl_xor_sync(0xffffffffu, s, off);
    __syncthreads();
    if (lane == 0) red[warp] = s;
    __syncthreads();
    if (warp == 0) {
        float x = (lane < 8) ? red[lane] : 0.f;
#pragma unroll
        for (int off = 16; off; off >>= 1)
            x += __shfl_xor_sync(0xffffffffu, x, off);
        if (lane == 0) red[0] = x;
    }
    __syncthreads();
    float inv = 1.f / red[0];
    v.x *= inv; v.y *= inv; v.z *= inv; v.w *= inv;
    reinterpret_cast<float4*>(J + base)[tid] = v;
}

// ---------------------------------------------------------------------------
// Step part 1: pS/pC[jc][g] = sum_{j in 32-chunk} J[bh,i,j]*{s,c}[j].
// Grid (Nn/ITILE=2, NC=32, 8 bh), 256 threads, 3 CTAs/SM.
// Thread owns 4 rows (stride 128) x 1 o-quad -> 32 accumulators.
// Per j: 4x LDS.32 (J, 16 distinct banks, pair-broadcast) +
//        2x LDS.128 (s/c, broadcast) + 32 FFMA  => 1.5 smem B/FMA.
// ---------------------------------------------------------------------------
__global__ __launch_bounds__(256, 3) void step_part(
    const float* __restrict__ J,
    const float* __restrict__ s_in, const float* __restrict__ c_in,
    float* __restrict__ pS, float* __restrict__ pC) {
    __shared__ float Jt[ITILE * JSTR];   // 67584 B
    __shared__ float ss[JCH * 8];        // 1 KB
    __shared__ float cs[JCH * 8];        // 1 KB
    int i0 = blockIdx.x * ITILE;
    int j0 = blockIdx.y * JCH;
    int bh = blockIdx.z;
    int b = bh >> 2, h = bh & 3;
    int tid = threadIdx.x;
    // Load J tile: 512 rows x 32 cols (4096 float4; 128B coalesced per row).
    // STS banks: (r*33 + c) % 32 = (r + c) % 32, r in 4-consec x c4 step4
    // across warp -> 32 distinct -> conflict-free.
    const float* Jb = J + ((size_t)bh * Nn + i0) * Nn + j0;
#pragma unroll
    for (int it = 0; it < 16; it++) {
        int idx = tid + it * 256;
        int r = idx >> 3, c4 = (idx & 7) * 4;
        float4 v = *(const float4*)&Jb[(size_t)r * Nn + c4];
        float* d = &Jt[r * JSTR + c4];
        d[0] = v.x; d[1] = v.y; d[2] = v.z; d[3] = v.w;
    }
    // Load s/c chunk (32 j x 8 o each = 64 float4 each)
    if (tid < 64) {
        int j = tid >> 1, qo = (tid & 1) * 4;
        *(float4*)&ss[j * 8 + qo] =
            *(const float4*)&s_in[(b * Nn + j0 + j) * HO + h * Oo + qo];
    } else if (tid < 128) {
        int t = tid - 64;
        int j = t >> 1, qo = (t & 1) * 4;
        *(float4*)&cs[j * 8 + qo] =
            *(const float4*)&c_in[(b * Nn + j0 + j) * HO + h * Oo + qo];
    }
    __syncthreads();
    int rg = tid >> 1, qo = (tid & 1) * 4;   // row-group 0..127, quad 0/4
    float aS[4][4] = {}, aC[4][4] = {};
#pragma unroll 8
    for (int j = 0; j < JCH; j++) {
        float4 sv = *(const float4*)&ss[j * 8 + qo];
        float4 cv = *(const float4*)&cs[j * 8 + qo];
        float jv[4];
#pragma unroll
        for (int i = 0; i < 4; i++) jv[i] = Jt[(rg + i * 128) * JSTR + j];
#pragma unroll
        for (int i = 0; i < 4; i++) {
            aS[i][0] = fmaf(jv[i], sv.x, aS[i][0]);
            aS[i][1] = fmaf(jv[i], sv.y, aS[i][1]);
            aS[i][2] = fmaf(jv[i], sv.z, aS[i][2]);
            aS[i][3] = fmaf(jv[i], sv.w, aS[i][3]);
            aC[i][0] = fmaf(jv[i], cv.x, aC[i][0]);
            aC[i][1] = fmaf(jv[i], cv.y, aC[i][1]);
            aC[i][2] = fmaf(jv[i], cv.z, aC[i][2]);
            aC[i][3] = fmaf(jv[i], cv.w, aC[i][3]);
        }
    }
#pragma unroll
    for (int i = 0; i < 4; i++) {
        int row = i0 + rg + i * 128;
        size_t pbase = (size_t)blockIdx.y * GTOT +
                       ((size_t)(b * Nn + row) * HO + h * Oo + qo);
        *(float4*)&pS[pbase] = make_float4(aS[i][0], aS[i][1], aS[i][2], aS[i][3]);
        *(float4*)&pC[pbase] = make_float4(aC[i][0], aC[i][1], aC[i][2], aC[i][3]);
    }
}

// ---------------------------------------------------------------------------
// Step part 2: reduce NC partials, phase update + wrap + sincos.
// ---------------------------------------------------------------------------
__global__ void step_update(const float* __restrict__ pS, const float* __restrict__ pC,
                            float* __restrict__ ph,
                            const float* __restrict__ s_in, const float* __restrict__ c_in,
                            float* __restrict__ s_out, float* __restrict__ c_out,
                            const float* __restrict__ omega,
                            const float* __restrict__ cs_ptr) {
    int g = blockIdx.x * 256 + threadIdx.x;
    float js = 0.f, jc = 0.f;
#pragma unroll
    for (int c = 0; c < NC; c++) {
        js += pS[(size_t)c * GTOT + g];
        jc += pC[(size_t)c * GTOT + g];
    }
    float si = s_in[g], ci = c_in[g];
    float coup = ci * js - si * jc;
    float np = ph[g] + DT_F * (omega[g & 31] + (*cs_ptr) * coup);
    float v = np + PI_F;
    np = v - floorf(v * INV_2PI_F) * TWO_PI_F - PI_F;
    ph[g] = np;
    float sn, cn;
    sincosf(np, &sn, &cn);
    s_out[g] = sn;
    c_out[g] = cn;
}

// ---------------------------------------------------------------------------
// Final small GEMM: out = C @ Wo^T + bo, K=32.
// ---------------------------------------------------------------------------
__global__ void gemm_out(const float* __restrict__ X, const float* __restrict__ W,
                         const float* __restrict__ bias, float* __restrict__ out) {
    __shared__ float As[64][33];
    __shared__ float Ws[64][33];
    int m0 = blockIdx.x * 64, n0 = blockIdx.y * 64;
    int tid = threadIdx.x;
    int tx = tid & 15, ty = tid >> 4;
    float acc[4][4] = {};
    for (int li = tid; li < 64 * 32; li += 256) {
        int r = li >> 5, c = li & 31;
        As[r][c] = X[(size_t)(m0 + r) * HO + c];
        Ws[r][c] = W[(size_t)(n0 + r) * HO + c];
    }
    __syncthreads();
#pragma unroll
    for (int kk = 0; kk < 32; kk++) {
        float a[4], bb[4];
#pragma unroll
        for (int i = 0; i < 4; i++) a[i] = As[ty * 4 + i][kk];
#pragma unroll
        for (int j = 0; j < 4; j++) bb[j] = Ws[tx * 4 + j][kk];
#pragma unroll
        for (int i = 0; i < 4; i++)
#pragma unroll
            for (int j = 0; j < 4; j++)
                acc[i][j] = fmaf(a[i], bb[j], acc[i][j]);
    }
#pragma unroll
    for (int i = 0; i < 4; i++) {
        int m = m0 + ty * 4 + i;
#pragma unroll
        for (int j = 0; j < 4; j++) {
            int n = n0 + tx * 4 + j;
            out[(size_t)m * Dd + n] = acc[i][j] + bias[n];
        }
    }
}

// ---------------------------------------------------------------------------
extern "C" void kernel_launch(void* const* d_in, const int* in_sizes, int n_in,
                              void* d_out, int out_size) {
    const float* x     = (const float*)d_in[0];
    const float* Wq    = (const float*)d_in[1];
    const float* Wk    = (const float*)d_in[2];
    const float* Wp    = (const float*)d_in[3];
    const float* bp    = (const float*)d_in[4];
    const float* Wo    = (const float*)d_in[5];
    const float* bo    = (const float*)d_in[6];
    const float* omega = (const float*)d_in[7];
    const float* cs    = (const float*)d_in[8];
    float* out = (float*)d_out;

    float *q, *k, *ph, *s0, *s1, *c0, *c1, *J, *pS, *pC;
    cudaGetSymbolAddress((void**)&q,  g_q);
    cudaGetSymbolAddress((void**)&k,  g_k);
    cudaGetSymbolAddress((void**)&ph, g_ph);
    cudaGetSymbolAddress((void**)&s0, g_s0);
    cudaGetSymbolAddress((void**)&s1, g_s1);
    cudaGetSymbolAddress((void**)&c0, g_c0);
    cudaGetSymbolAddress((void**)&c1, g_c1);
    cudaGetSymbolAddress((void**)&J,  g_J);
    cudaGetSymbolAddress((void**)&pS, g_pS);
    cudaGetSymbolAddress((void**)&pC, g_pC);

    dim3 blk(256);
    // fused projections (q, k, ph + sincos)
    proj_kernel<<<dim3(Bb * Nn / 64, 9), blk>>>(x, Wq, Wk, Wp, bp, q, k, ph, s0, c0);
    // attention J
    size_t smem_sc = (size_t)2 * 64 * SP * sizeof(float);
    cudaFuncSetAttribute(scores_kernel, cudaFuncAttributeMaxDynamicSharedMemorySize, (int)smem_sc);
    scores_kernel<<<dim3(Nn / 128, Nn / 128, Bb * Hh), blk, smem_sc>>>(q, k, J);
    softmax_kernel<<<Bb * Hh * Nn, blk>>>(J);
    // 5 oscillator steps (split-j partials + reduce/update, ping-pong s/c)
    float* sbuf[2] = {s0, s1};
    float* cbuf[2] = {c0, c1};
    for (int t = 0; t < NSTEPS; t++) {
        step_part<<<dim3(Nn / ITILE, NC, Bb * Hh), blk>>>(
            J, sbuf[t & 1], cbuf[t & 1], pS, pC);
        step_update<<<GTOT / 256, blk>>>(
            pS, pC, ph, sbuf[t & 1], cbuf[t & 1],
            sbuf[(t + 1) & 1], cbuf[(t + 1) & 1], omega, cs);
    }
    // output: out = cos(final phases) @ Wo^T + bo
    const float* cfin = cbuf[NSTEPS & 1];
    gemm_out<<<dim3(Bb * Nn / 64, Dd / 64), blk>>>(cfin, Wo, bo, out);
}

// round 8
// speedup vs baseline: 1.6962x; 1.0386x over previous
#include <cuda_runtime.h>
#include <math.h>

#define Bb 2
#define Nn 1024
#define Dd 256
#define Hh 4
#define Oo 8
#define HO 32
#define DKK 64
#define NSTEPS 5
#define DT_F 0.1f
#define PI_F 3.14159265358979323846f
#define TWO_PI_F 6.28318530717958647692f
#define INV_2PI_F 0.15915494309189533577f

#define GTOT (Bb * Nn * HO)   // 65536
#define ITILE 256
#define JCH 64
#define NC (Nn / JCH)         // 16
#define JSTR 65               // J tile smem stride (odd -> conflict-free)

typedef unsigned long long ull;

// Packed fp32x2 FMA: d = a*b + d (bit-identical to two scalar FFMAs).
#define FMA2(d, a, b) \
    asm("fma.rn.f32x2 %0, %1, %2, %0;" : "+l"(d) : "l"(a), "l"(b))
// Broadcast-pack a scalar float into both lanes of an f32x2.
#define PACK2(d, x) \
    asm("mov.b64 %0, {%1, %1};" : "=l"(d) : "r"(__float_as_uint(x)))
// Unpack f32x2 -> two floats.
#define UNPK2(lo, hi, v) \
    asm("mov.b64 {%0, %1}, %2;" : "=f"(lo), "=f"(hi) : "l"(v))

// Scratch (no cudaMalloc allowed)
__device__ float g_q[Bb * Nn * Dd];
__device__ float g_k[Bb * Nn * Dd];
__device__ float g_ph[GTOT];
__device__ float g_s0[GTOT];
__device__ float g_s1[GTOT];
__device__ float g_c0[GTOT];
__device__ float g_c1[GTOT];
__device__ float g_pS[NC * GTOT];   // 4 MB partial J@sin
__device__ float g_pC[NC * GTOT];   // 4 MB partial J@cos
__device__ float g_J[(size_t)Bb * Hh * Nn * Nn];   // 32 MB

// ---------------------------------------------------------------------------
// Fused projection kernel: q = x@Wq^T, k = x@Wk^T, ph = x@Wp^T + bp (+sincos).
// FFMA2 micro-kernel: per kk, 1 LDS.128 + 1 LDS.128(ull2) + 4 pack + 8 FMA2.
// ---------------------------------------------------------------------------
__global__ __launch_bounds__(256, 2) void proj_kernel(
    const float* __restrict__ x,
    const float* __restrict__ Wq, const float* __restrict__ Wk,
    const float* __restrict__ Wp, const float* __restrict__ bp,
    float* __restrict__ q, float* __restrict__ k,
    float* __restrict__ ph, float* __restrict__ s0, float* __restrict__ c0) {
    __shared__ __align__(16) float As[64][68];   // [kk][m]
    __shared__ __align__(16) float Bs[64][68];   // [kk][n]
    int m0 = blockIdx.x * 64;
    int y = blockIdx.y;
    const float* W;
    int n0, Nout;
    if (y < 4)      { W = Wq; n0 = y * 64;       Nout = Dd; }
    else if (y < 8) { W = Wk; n0 = (y - 4) * 64; Nout = Dd; }
    else            { W = Wp; n0 = 0;            Nout = HO; }
    int tid = threadIdx.x;
    int tx = tid & 15, ty = tid >> 4;
    ull acc2[4][2] = {};
    for (int kt = 0; kt < Dd; kt += 64) {
        for (int t = tid; t < 64 * 16; t += 256) {
            int r = t >> 4, c4 = (t & 15) * 4;
            float4 va = *(const float4*)&x[(size_t)(m0 + r) * Dd + kt + c4];
            As[c4 + 0][r] = va.x; As[c4 + 1][r] = va.y;
            As[c4 + 2][r] = va.z; As[c4 + 3][r] = va.w;
            float4 vb = make_float4(0.f, 0.f, 0.f, 0.f);
            if (n0 + r < Nout)
                vb = *(const float4*)&W[(size_t)(n0 + r) * Dd + kt + c4];
            Bs[c4 + 0][r] = vb.x; Bs[c4 + 1][r] = vb.y;
            Bs[c4 + 2][r] = vb.z; Bs[c4 + 3][r] = vb.w;
        }
        __syncthreads();
#pragma unroll
        for (int kk = 0; kk < 64; kk++) {
            float4 a = *(const float4*)&As[kk][ty * 4];
            ulonglong2 bv = *(const ulonglong2*)&Bs[kk][tx * 4];
            ull aa0, aa1, aa2, aa3;
            PACK2(aa0, a.x); PACK2(aa1, a.y); PACK2(aa2, a.z); PACK2(aa3, a.w);
            FMA2(acc2[0][0], aa0, bv.x); FMA2(acc2[0][1], aa0, bv.y);
            FMA2(acc2[1][0], aa1, bv.x); FMA2(acc2[1][1], aa1, bv.y);
            FMA2(acc2[2][0], aa2, bv.x); FMA2(acc2[2][1], aa2, bv.y);
            FMA2(acc2[3][0], aa3, bv.x); FMA2(acc2[3][1], aa3, bv.y);
        }
        __syncthreads();
    }
    float acc[4][4];
#pragma unroll
    for (int i = 0; i < 4; i++) {
        UNPK2(acc[i][0], acc[i][1], acc2[i][0]);
        UNPK2(acc[i][2], acc[i][3], acc2[i][1]);
    }
    if (y < 8) {
        float* out = (y < 4) ? q : k;
#pragma unroll
        for (int i = 0; i < 4; i++) {
            int m = m0 + ty * 4 + i;
            float4 v = make_float4(acc[i][0], acc[i][1], acc[i][2], acc[i][3]);
            *(float4*)&out[(size_t)m * Dd + n0 + tx * 4] = v;
        }
    } else if (tx * 4 < HO) {
#pragma unroll
        for (int i = 0; i < 4; i++) {
            int m = m0 + ty * 4 + i;
#pragma unroll
            for (int j = 0; j < 4; j++) {
                int n = tx * 4 + j;
                float p = acc[i][j] + bp[n];
                int g = m * HO + n;
                ph[g] = p;
                float sn, cn;
                sincosf(p, &sn, &cn);
                s0[g] = sn;
                c0[g] = cn;
            }
        }
    }
}

// ---------------------------------------------------------------------------
// Scores: S[bh,i,j] = 0.125 * dot(q_i,k_j). 128x128 tile, 8x8 micro-tile.
// FFMA2: per kk, 2x LDS.128 (a) + 2x LDS.128 (b as ull2) + 8 pack + 32 FMA2.
// ---------------------------------------------------------------------------
#define SP 132
__global__ __launch_bounds__(256, 2) void scores_kernel(
    const float* __restrict__ q, const float* __restrict__ k,
    float* __restrict__ J) {
    extern __shared__ __align__(16) float sm[];
    float* Qs = sm;            // [64][SP]
    float* Ks = sm + 64 * SP;  // [64][SP]
    int bh = blockIdx.z;
    int b = bh >> 2, h = bh & 3;
    int i0 = blockIdx.x * 128, j0 = blockIdx.y * 128;
    int tid = threadIdx.x;
    for (int t = tid; t < 128 * 16; t += 256) {
        int r = t >> 4, c4 = (t & 15) * 4;
        float4 vq = *(const float4*)&q[(size_t)(b * Nn + i0 + r) * Dd + h * DKK + c4];
        Qs[(c4 + 0) * SP + r] = vq.x; Qs[(c4 + 1) * SP + r] = vq.y;
        Qs[(c4 + 2) * SP + r] = vq.z; Qs[(c4 + 3) * SP + r] = vq.w;
        float4 vk = *(const float4*)&k[(size_t)(b * Nn + j0 + r) * Dd + h * DKK + c4];
        Ks[(c4 + 0) * SP + r] = vk.x; Ks[(c4 + 1) * SP + r] = vk.y;
        Ks[(c4 + 2) * SP + r] = vk.z; Ks[(c4 + 3) * SP + r] = vk.w;
    }
    __syncthreads();
    int tx = tid & 15, ty = tid >> 4;
    ull acc2[8][4] = {};
#pragma unroll
    for (int kk = 0; kk < 64; kk++) {
        float4 a0 = *(const float4*)&Qs[kk * SP + ty * 8];
        float4 a1 = *(const float4*)&Qs[kk * SP + ty * 8 + 4];
        ulonglong2 b0 = *(const ulonglong2*)&Ks[kk * SP + tx * 8];
        ulonglong2 b1 = *(const ulonglong2*)&Ks[kk * SP + tx * 8 + 4];
        float av[8] = {a0.x, a0.y, a0.z, a0.w, a1.x, a1.y, a1.z, a1.w};
#pragma unroll
        for (int i = 0; i < 8; i++) {
            ull aa;
            PACK2(aa, av[i]);
            FMA2(acc2[i][0], aa, b0.x);
            FMA2(acc2[i][1], aa, b0.y);
            FMA2(acc2[i][2], aa, b1.x);
            FMA2(acc2[i][3], aa, b1.y);
        }
    }
    size_t rowbase = ((size_t)bh * Nn + i0 + ty * 8) * Nn + j0 + tx * 8;
#pragma unroll
    for (int i = 0; i < 8; i++) {
        float o0, o1, o2, o3, o4, o5, o6, o7;
        UNPK2(o0, o1, acc2[i][0]); UNPK2(o2, o3, acc2[i][1]);
        UNPK2(o4, o5, acc2[i][2]); UNPK2(o6, o7, acc2[i][3]);
        float4 v0 = make_float4(0.125f * o0, 0.125f * o1, 0.125f * o2, 0.125f * o3);
        float4 v1 = make_float4(0.125f * o4, 0.125f * o5, 0.125f * o6, 0.125f * o7);
        *(float4*)&J[rowbase + (size_t)i * Nn] = v0;
        *(float4*)&J[rowbase + (size_t)i * Nn + 4] = v1;
    }
}

// ---------------------------------------------------------------------------
// In-place row softmax over J rows of length 1024.
// ---------------------------------------------------------------------------
__global__ void softmax_kernel(float* __restrict__ J) {
    __shared__ float red[8];
    size_t base = (size_t)blockIdx.x * Nn;
    int tid = threadIdx.x, lane = tid & 31, warp = tid >> 5;
    float4 v = reinterpret_cast<float4*>(J + base)[tid];
    float m = fmaxf(fmaxf(v.x, v.y), fmaxf(v.z, v.w));
#pragma unroll
    for (int off = 16; off; off >>= 1)
        m = fmaxf(m, __shfl_xor_sync(0xffffffffu, m, off));
    if (lane == 0) red[warp] = m;
    __syncthreads();
    if (warp == 0) {
        float x = (lane < 8) ? red[lane] : -1e30f;
#pragma unroll
        for (int off = 16; off; off >>= 1)
            x = fmaxf(x, __shfl_xor_sync(0xffffffffu, x, off));
        if (lane == 0) red[0] = x;
    }
    __syncthreads();
    m = red[0];
    v.x = __expf(v.x - m); v.y = __expf(v.y - m);
    v.z = __expf(v.z - m); v.w = __expf(v.w - m);
    float s = v.x + v.y + v.z + v.w;
#pragma unroll
    for (int off = 16; off; off >>= 1)
        s += __shfl_xor_sync(0xffffffffu, s, off);
    __syncthreads();
    if (lane == 0) red[warp] = s;
    __syncthreads();
    if (warp == 0) {
        float x = (lane < 8) ? red[lane] : 0.f;
#pragma unroll
        for (int off = 16; off; off >>= 1)
            x += __shfl_xor_sync(0xffffffffu, x, off);
        if (lane == 0) red[0] = x;
    }
    __syncthreads();
    float inv = 1.f / red[0];
    v.x *= inv; v.y *= inv; v.z *= inv; v.w *= inv;
    reinterpret_cast<float4*>(J + base)[tid] = v;
}

// ---------------------------------------------------------------------------
// Step part 1: pS/pC[jc][g] = sum_{j in 64-chunk} J[bh,i,j]*{s,c}[j].
// Grid (Nn/ITILE=4, NC=16, 8 bh), 256 threads, 3 CTAs/SM.
// Thread owns 2 rows (rg, rg+128) x 1 o-quad. Per j:
//   2x LDS.32 (J, pair-broadcast, 1 wf each) + 2x LDS.128 (s/c, broadcast)
//   + 2 pack + 8 FMA2 (= 16 FMA).
// ---------------------------------------------------------------------------
__global__ __launch_bounds__(256, 3) void step_part(
    const float* __restrict__ J,
    const float* __restrict__ s_in, const float* __restrict__ c_in,
    float* __restrict__ pS, float* __restrict__ pC) {
    __shared__ __align__(16) float Jt[ITILE * JSTR];   // 66560 B
    __shared__ __align__(16) float ss[JCH * 8];        // 2 KB
    __shared__ __align__(16) float cs[JCH * 8];        // 2 KB
    int i0 = blockIdx.x * ITILE;
    int j0 = blockIdx.y * JCH;
    int bh = blockIdx.z;
    int b = bh >> 2, h = bh & 3;
    int tid = threadIdx.x;
    // Load J tile: 256 rows x 64 cols (4096 float4, 256B coalesced per row)
    const float* Jb = J + ((size_t)bh * Nn + i0) * Nn + j0;
#pragma unroll
    for (int it = 0; it < 16; it++) {
        int idx = tid + it * 256;
        int r = idx >> 4, c4 = (idx & 15) * 4;
        float4 v = *(const float4*)&Jb[(size_t)r * Nn + c4];
        float* d = &Jt[r * JSTR + c4];
        d[0] = v.x; d[1] = v.y; d[2] = v.z; d[3] = v.w;
    }
    // Load s/c chunk (64 j x 8 o each = 128 float4 each)
    if (tid < 128) {
        int j = tid >> 1, qo = (tid & 1) * 4;
        *(float4*)&ss[j * 8 + qo] =
            *(const float4*)&s_in[(b * Nn + j0 + j) * HO + h * Oo + qo];
    } else {
        int t = tid - 128;
        int j = t >> 1, qo = (t & 1) * 4;
        *(float4*)&cs[j * 8 + qo] =
            *(const float4*)&c_in[(b * Nn + j0 + j) * HO + h * Oo + qo];
    }
    __syncthreads();
    int rg = tid >> 1, qo = (tid & 1) * 4;   // row-group 0..127, quad 0/4
    ull aS[2][2] = {}, aC[2][2] = {};
    const float* Jr0 = &Jt[rg * JSTR];
    const float* Jr1 = &Jt[(rg + 128) * JSTR];
#pragma unroll 8
    for (int j = 0; j < JCH; j++) {
        ulonglong2 sv = *(const ulonglong2*)&ss[j * 8 + qo];
        ulonglong2 cv = *(const ulonglong2*)&cs[j * 8 + qo];
        ull jj0, jj1;
        PACK2(jj0, Jr0[j]);
        PACK2(jj1, Jr1[j]);
        FMA2(aS[0][0], jj0, sv.x); FMA2(aS[0][1], jj0, sv.y);
        FMA2(aC[0][0], jj0, cv.x); FMA2(aC[0][1], jj0, cv.y);
        FMA2(aS[1][0], jj1, sv.x); FMA2(aS[1][1], jj1, sv.y);
        FMA2(aC[1][0], jj1, cv.x); FMA2(aC[1][1], jj1, cv.y);
    }
#pragma unroll
    for (int i = 0; i < 2; i++) {
        int row = i0 + rg + i * 128;
        size_t pbase = (size_t)blockIdx.y * GTOT +
                       ((size_t)(b * Nn + row) * HO + h * Oo + qo);
        float s0f, s1f, s2f, s3f, c0f, c1f, c2f, c3f;
        UNPK2(s0f, s1f, aS[i][0]); UNPK2(s2f, s3f, aS[i][1]);
        UNPK2(c0f, c1f, aC[i][0]); UNPK2(c2f, c3f, aC[i][1]);
        *(float4*)&pS[pbase] = make_float4(s0f, s1f, s2f, s3f);
        *(float4*)&pC[pbase] = make_float4(c0f, c1f, c2f, c3f);
    }
}

// ---------------------------------------------------------------------------
// Step part 2: reduce NC partials, phase update + wrap + sincos.
// ---------------------------------------------------------------------------
__global__ void step_update(const float* __restrict__ pS, const float* __restrict__ pC,
                            float* __restrict__ ph,
                            const float* __restrict__ s_in, const float* __restrict__ c_in,
                            float* __restrict__ s_out, float* __restrict__ c_out,
                            const float* __restrict__ omega,
                            const float* __restrict__ cs_ptr) {
    int g = blockIdx.x * 256 + threadIdx.x;
    float js = 0.f, jc = 0.f;
#pragma unroll
    for (int c = 0; c < NC; c++) {
        js += pS[(size_t)c * GTOT + g];
        jc += pC[(size_t)c * GTOT + g];
    }
    float si = s_in[g], ci = c_in[g];
    float coup = ci * js - si * jc;
    float np = ph[g] + DT_F * (omega[g & 31] + (*cs_ptr) * coup);
    float v = np + PI_F;
    np = v - floorf(v * INV_2PI_F) * TWO_PI_F - PI_F;
    ph[g] = np;
    float sn, cn;
    sincosf(np, &sn, &cn);
    s_out[g] = sn;
    c_out[g] = cn;
}

// ---------------------------------------------------------------------------
// Final small GEMM: out = C @ Wo^T + bo, K=32.
// ---------------------------------------------------------------------------
__global__ void gemm_out(const float* __restrict__ X, const float* __restrict__ W,
                         const float* __restrict__ bias, float* __restrict__ out) {
    __shared__ float As[64][33];
    __shared__ float Ws[64][33];
    int m0 = blockIdx.x * 64, n0 = blockIdx.y * 64;
    int tid = threadIdx.x;
    int tx = tid & 15, ty = tid >> 4;
    float acc[4][4] = {};
    for (int li = tid; li < 64 * 32; li += 256) {
        int r = li >> 5, c = li & 31;
        As[r][c] = X[(size_t)(m0 + r) * HO + c];
        Ws[r][c] = W[(size_t)(n0 + r) * HO + c];
    }
    __syncthreads();
#pragma unroll
    for (int kk = 0; kk < 32; kk++) {
        float a[4], bb[4];
#pragma unroll
        for (int i = 0; i < 4; i++) a[i] = As[ty * 4 + i][kk];
#pragma unroll
        for (int j = 0; j < 4; j++) bb[j] = Ws[tx * 4 + j][kk];
#pragma unroll
        for (int i = 0; i < 4; i++)
#pragma unroll
            for (int j = 0; j < 4; j++)
                acc[i][j] = fmaf(a[i], bb[j], acc[i][j]);
    }
#pragma unroll
    for (int i = 0; i < 4; i++) {
        int m = m0 + ty * 4 + i;
#pragma unroll
        for (int j = 0; j < 4; j++) {
            int n = n0 + tx * 4 + j;
            out[(size_t)m * Dd + n] = acc[i][j] + bias[n];
        }
    }
}

// ---------------------------------------------------------------------------
extern "C" void kernel_launch(void* const* d_in, const int* in_sizes, int n_in,
                              void* d_out, int out_size) {
    const float* x     = (const float*)d_in[0];
    const float* Wq    = (const float*)d_in[1];
    const float* Wk    = (const float*)d_in[2];
    const float* Wp    = (const float*)d_in[3];
    const float* bp    = (const float*)d_in[4];
    const float* Wo    = (const float*)d_in[5];
    const float* bo    = (const float*)d_in[6];
    const float* omega = (const float*)d_in[7];
    const float* cs    = (const float*)d_in[8];
    float* out = (float*)d_out;

    float *q, *k, *ph, *s0, *s1, *c0, *c1, *J, *pS, *pC;
    cudaGetSymbolAddress((void**)&q,  g_q);
    cudaGetSymbolAddress((void**)&k,  g_k);
    cudaGetSymbolAddress((void**)&ph, g_ph);
    cudaGetSymbolAddress((void**)&s0, g_s0);
    cudaGetSymbolAddress((void**)&s1, g_s1);
    cudaGetSymbolAddress((void**)&c0, g_c0);
    cudaGetSymbolAddress((void**)&c1, g_c1);
    cudaGetSymbolAddress((void**)&J,  g_J);
    cudaGetSymbolAddress((void**)&pS, g_pS);
    cudaGetSymbolAddress((void**)&pC, g_pC);

    dim3 blk(256);
    // fused projections (q, k, ph + sincos)
    proj_kernel<<<dim3(Bb * Nn / 64, 9), blk>>>(x, Wq, Wk, Wp, bp, q, k, ph, s0, c0);
    // attention J
    size_t smem_sc = (size_t)2 * 64 * SP * sizeof(float);
    cudaFuncSetAttribute(scores_kernel, cudaFuncAttributeMaxDynamicSharedMemorySize, (int)smem_sc);
    scores_kernel<<<dim3(Nn / 128, Nn / 128, Bb * Hh), blk, smem_sc>>>(q, k, J);
    softmax_kernel<<<Bb * Hh * Nn, blk>>>(J);
    // 5 oscillator steps (split-j partials + reduce/update, ping-pong s/c)
    float* sbuf[2] = {s0, s1};
    float* cbuf[2] = {c0, c1};
    for (int t = 0; t < NSTEPS; t++) {
        step_part<<<dim3(Nn / ITILE, NC, Bb * Hh), blk>>>(
            J, sbuf[t & 1], cbuf[t & 1], pS, pC);
        step_update<<<GTOT / 256, blk>>>(
            pS, pC, ph, sbuf[t & 1], cbuf[t & 1],
            sbuf[(t + 1) & 1], cbuf[(t + 1) & 1], omega, cs);
    }
    // output: out = cos(final phases) @ Wo^T + bo
    const float* cfin = cbuf[NSTEPS & 1];
    gemm_out<<<dim3(Bb * Nn / 64, Dd / 64), blk>>>(cfin, Wo, bo, out);
}

// round 9
// speedup vs baseline: 1.7160x; 1.0117x over previous
#include <cuda_runtime.h>
#include <math.h>

#define Bb 2
#define Nn 1024
#define Dd 256
#define Hh 4
#define Oo 8
#define HO 32
#define DKK 64
#define NSTEPS 5
#define DT_F 0.1f
#define PI_F 3.14159265358979323846f
#define TWO_PI_F 6.28318530717958647692f
#define INV_2PI_F 0.15915494309189533577f

#define GTOT (Bb * Nn * HO)   // 65536
#define NKC 8                 // k-chunks for step mma (K=1024 -> 128 each)

typedef unsigned long long ull;
typedef unsigned int uint;

// Packed fp32x2 FMA (bit-identical to two scalar FFMAs).
#define FMA2(d, a, b) \
    asm("fma.rn.f32x2 %0, %1, %2, %0;" : "+l"(d) : "l"(a), "l"(b))
#define PACK2(d, x) \
    asm("mov.b64 %0, {%1, %1};" : "=l"(d) : "r"(__float_as_uint(x)))
#define UNPK2(lo, hi, v) \
    asm("mov.b64 {%0, %1}, %2;" : "=f"(lo), "=f"(hi) : "l"(v))

// tf32 round-to-nearest (so mma's truncation of these bits is exact)
__device__ __forceinline__ float tf32r(float x) {
    uint u;
    asm("cvt.rna.tf32.f32 %0, %1;" : "=r"(u) : "f"(x));
    return __uint_as_float(u);
}

// m16n8k8 tf32 mma, fp32 accumulate
#define MMA_TF32(d, a0, a1, a2, a3, b0, b1) \
    asm("mma.sync.aligned.m16n8k8.row.col.f32.tf32.tf32.f32 " \
        "{%0,%1,%2,%3}, {%4,%5,%6,%7}, {%8,%9}, {%0,%1,%2,%3};" \
        : "+f"(d[0]), "+f"(d[1]), "+f"(d[2]), "+f"(d[3]) \
        : "r"(a0), "r"(a1), "r"(a2), "r"(a3), "r"(b0), "r"(b1))

// Scratch (no cudaMalloc allowed)
__device__ float g_q[Bb * Nn * Dd];
__device__ float g_k[Bb * Nn * Dd];
__device__ float g_ph[GTOT];
__device__ float g_s0[GTOT];
__device__ float g_s1[GTOT];
__device__ float g_c0[GTOT];
__device__ float g_c1[GTOT];
__device__ float g_sc0[Bb * Hh * Nn * 16];   // [bh][j][s0..7|c0..7] tf32
__device__ float g_sc1[Bb * Hh * Nn * 16];
__device__ float g_pD[NKC * Bb * Hh * Nn * 16];    // 4 MB partials
__device__ float g_J[(size_t)Bb * Hh * Nn * Nn];   // 32 MB (tf32-rounded)

// ---------------------------------------------------------------------------
// Fused projection kernel: q = x@Wq^T, k = x@Wk^T, ph = x@Wp^T + bp (+sincos).
// ---------------------------------------------------------------------------
__global__ __launch_bounds__(256, 2) void proj_kernel(
    const float* __restrict__ x,
    const float* __restrict__ Wq, const float* __restrict__ Wk,
    const float* __restrict__ Wp, const float* __restrict__ bp,
    float* __restrict__ q, float* __restrict__ k,
    float* __restrict__ ph, float* __restrict__ s0, float* __restrict__ c0,
    float* __restrict__ sc0) {
    __shared__ __align__(16) float As[64][68];   // [kk][m]
    __shared__ __align__(16) float Bs[64][68];   // [kk][n]
    int m0 = blockIdx.x * 64;
    int y = blockIdx.y;
    const float* W;
    int n0, Nout;
    if (y < 4)      { W = Wq; n0 = y * 64;       Nout = Dd; }
    else if (y < 8) { W = Wk; n0 = (y - 4) * 64; Nout = Dd; }
    else            { W = Wp; n0 = 0;            Nout = HO; }
    int tid = threadIdx.x;
    int tx = tid & 15, ty = tid >> 4;
    ull acc2[4][2] = {};
    for (int kt = 0; kt < Dd; kt += 64) {
        for (int t = tid; t < 64 * 16; t += 256) {
            int r = t >> 4, c4 = (t & 15) * 4;
            float4 va = *(const float4*)&x[(size_t)(m0 + r) * Dd + kt + c4];
            As[c4 + 0][r] = va.x; As[c4 + 1][r] = va.y;
            As[c4 + 2][r] = va.z; As[c4 + 3][r] = va.w;
            float4 vb = make_float4(0.f, 0.f, 0.f, 0.f);
            if (n0 + r < Nout)
                vb = *(const float4*)&W[(size_t)(n0 + r) * Dd + kt + c4];
            Bs[c4 + 0][r] = vb.x; Bs[c4 + 1][r] = vb.y;
            Bs[c4 + 2][r] = vb.z; Bs[c4 + 3][r] = vb.w;
        }
        __syncthreads();
#pragma unroll
        for (int kk = 0; kk < 64; kk++) {
            float4 a = *(const float4*)&As[kk][ty * 4];
            ulonglong2 bv = *(const ulonglong2*)&Bs[kk][tx * 4];
            ull aa0, aa1, aa2, aa3;
            PACK2(aa0, a.x); PACK2(aa1, a.y); PACK2(aa2, a.z); PACK2(aa3, a.w);
            FMA2(acc2[0][0], aa0, bv.x); FMA2(acc2[0][1], aa0, bv.y);
            FMA2(acc2[1][0], aa1, bv.x); FMA2(acc2[1][1], aa1, bv.y);
            FMA2(acc2[2][0], aa2, bv.x); FMA2(acc2[2][1], aa2, bv.y);
            FMA2(acc2[3][0], aa3, bv.x); FMA2(acc2[3][1], aa3, bv.y);
        }
        __syncthreads();
    }
    float acc[4][4];
#pragma unroll
    for (int i = 0; i < 4; i++) {
        UNPK2(acc[i][0], acc[i][1], acc2[i][0]);
        UNPK2(acc[i][2], acc[i][3], acc2[i][1]);
    }
    if (y < 8) {
        float* out = (y < 4) ? q : k;
#pragma unroll
        for (int i = 0; i < 4; i++) {
            int m = m0 + ty * 4 + i;
            float4 v = make_float4(acc[i][0], acc[i][1], acc[i][2], acc[i][3]);
            *(float4*)&out[(size_t)m * Dd + n0 + tx * 4] = v;
        }
    } else if (tx * 4 < HO) {
#pragma unroll
        for (int i = 0; i < 4; i++) {
            int m = m0 + ty * 4 + i;
#pragma unroll
            for (int j = 0; j < 4; j++) {
                int n = tx * 4 + j;
                float p = acc[i][j] + bp[n];
                int g = m * HO + n;
                ph[g] = p;
                float sn, cn;
                sincosf(p, &sn, &cn);
                s0[g] = sn;
                c0[g] = cn;
                int bh = (m >> 10) * 4 + (n >> 3);
                int scb = ((bh << 10) + (m & 1023)) * 16 + (n & 7);
                sc0[scb] = tf32r(sn);
                sc0[scb + 8] = tf32r(cn);
            }
        }
    }
}

// ---------------------------------------------------------------------------
// Scores: S[bh,i,j] = 0.125 * dot(q_i,k_j). 128x128 tile, 8x8 micro-tile.
// ---------------------------------------------------------------------------
#define SP 132
__global__ __launch_bounds__(256, 2) void scores_kernel(
    const float* __restrict__ q, const float* __restrict__ k,
    float* __restrict__ J) {
    extern __shared__ __align__(16) float sm[];
    float* Qs = sm;            // [64][SP]
    float* Ks = sm + 64 * SP;  // [64][SP]
    int bh = blockIdx.z;
    int b = bh >> 2, h = bh & 3;
    int i0 = blockIdx.x * 128, j0 = blockIdx.y * 128;
    int tid = threadIdx.x;
    for (int t = tid; t < 128 * 16; t += 256) {
        int r = t >> 4, c4 = (t & 15) * 4;
        float4 vq = *(const float4*)&q[(size_t)(b * Nn + i0 + r) * Dd + h * DKK + c4];
        Qs[(c4 + 0) * SP + r] = vq.x; Qs[(c4 + 1) * SP + r] = vq.y;
        Qs[(c4 + 2) * SP + r] = vq.z; Qs[(c4 + 3) * SP + r] = vq.w;
        float4 vk = *(const float4*)&k[(size_t)(b * Nn + j0 + r) * Dd + h * DKK + c4];
        Ks[(c4 + 0) * SP + r] = vk.x; Ks[(c4 + 1) * SP + r] = vk.y;
        Ks[(c4 + 2) * SP + r] = vk.z; Ks[(c4 + 3) * SP + r] = vk.w;
    }
    __syncthreads();
    int tx = tid & 15, ty = tid >> 4;
    ull acc2[8][4] = {};
#pragma unroll
    for (int kk = 0; kk < 64; kk++) {
        float4 a0 = *(const float4*)&Qs[kk * SP + ty * 8];
        float4 a1 = *(const float4*)&Qs[kk * SP + ty * 8 + 4];
        ulonglong2 b0 = *(const ulonglong2*)&Ks[kk * SP + tx * 8];
        ulonglong2 b1 = *(const ulonglong2*)&Ks[kk * SP + tx * 8 + 4];
        float av[8] = {a0.x, a0.y, a0.z, a0.w, a1.x, a1.y, a1.z, a1.w};
#pragma unroll
        for (int i = 0; i < 8; i++) {
            ull aa;
            PACK2(aa, av[i]);
            FMA2(acc2[i][0], aa, b0.x);
            FMA2(acc2[i][1], aa, b0.y);
            FMA2(acc2[i][2], aa, b1.x);
            FMA2(acc2[i][3], aa, b1.y);
        }
    }
    size_t rowbase = ((size_t)bh * Nn + i0 + ty * 8) * Nn + j0 + tx * 8;
#pragma unroll
    for (int i = 0; i < 8; i++) {
        float o0, o1, o2, o3, o4, o5, o6, o7;
        UNPK2(o0, o1, acc2[i][0]); UNPK2(o2, o3, acc2[i][1]);
        UNPK2(o4, o5, acc2[i][2]); UNPK2(o6, o7, acc2[i][3]);
        float4 v0 = make_float4(0.125f * o0, 0.125f * o1, 0.125f * o2, 0.125f * o3);
        float4 v1 = make_float4(0.125f * o4, 0.125f * o5, 0.125f * o6, 0.125f * o7);
        *(float4*)&J[rowbase + (size_t)i * Nn] = v0;
        *(float4*)&J[rowbase + (size_t)i * Nn + 4] = v1;
    }
}

// ---------------------------------------------------------------------------
// In-place row softmax over J rows of length 1024; output rounded to tf32.
// ---------------------------------------------------------------------------
__global__ void softmax_kernel(float* __restrict__ J) {
    __shared__ float red[8];
    size_t base = (size_t)blockIdx.x * Nn;
    int tid = threadIdx.x, lane = tid & 31, warp = tid >> 5;
    float4 v = reinterpret_cast<float4*>(J + base)[tid];
    float m = fmaxf(fmaxf(v.x, v.y), fmaxf(v.z, v.w));
#pragma unroll
    for (int off = 16; off; off >>= 1)
        m = fmaxf(m, __shfl_xor_sync(0xffffffffu, m, off));
    if (lane == 0) red[warp] = m;
    __syncthreads();
    if (warp == 0) {
        float x = (lane < 8) ? red[lane] : -1e30f;
#pragma unroll
        for (int off = 16; off; off >>= 1)
            x = fmaxf(x, __shfl_xor_sync(0xffffffffu, x, off));
        if (lane == 0) red[0] = x;
    }
    __syncthreads();
    m = red[0];
    v.x = __expf(v.x - m); v.y = __expf(v.y - m);
    v.z = __expf(v.z - m); v.w = __expf(v.w - m);
    float s = v.x + v.y + v.z + v.w;
#pragma unroll
    for (int off = 16; off; off >>= 1)
        s += __shfl_xor_sync(0xffffffffu, s, off);
    __syncthreads();
    if (lane == 0) red[warp] = s;
    __syncthreads();
    if (warp == 0) {
        float x = (lane < 8) ? red[lane] : 0.f;
#pragma unroll
        for (int off = 16; off; off >>= 1)
            x += __shfl_xor_sync(0xffffffffu, x, off);
        if (lane == 0) red[0] = x;
    }
    __syncthreads();
    float inv = 1.f / red[0];
    v.x = tf32r(v.x * inv); v.y = tf32r(v.y * inv);
    v.z = tf32r(v.z * inv); v.w = tf32r(v.w * inv);
    reinterpret_cast<float4*>(J + base)[tid] = v;
}

// ---------------------------------------------------------------------------
// Step matvec on tensor cores: pD[kc][bh][i][0..7]=J@s, [8..15]=J@c partials.
// Grid (8 i-strips, NKC k-chunks, 8 bh), 256 thr = 8 warps x 16 rows.
// A fragments LDG'd straight from L2 (sector-coalesced); B (sc) from smem.
// ---------------------------------------------------------------------------
__global__ __launch_bounds__(256, 4) void step_mma(
    const float* __restrict__ J, const float* __restrict__ sc,
    float* __restrict__ pD) {
    __shared__ __align__(16) float scs[128 * 16];   // 8 KB
    int i0 = blockIdx.x * 128;
    int k0 = blockIdx.y * 128;
    int bh = blockIdx.z;
    int tid = threadIdx.x;
    {
        const float4* src = (const float4*)&sc[((bh << 10) + k0) * 16];
        float4* dst = (float4*)scs;
        dst[tid] = src[tid];
        dst[tid + 256] = src[tid + 256];
    }
    __syncthreads();
    int w = tid >> 5, lane = tid & 31;
    int gid = lane >> 2, tig = lane & 3;
    const float* A0 = &J[((size_t)(bh << 10) + i0 + w * 16 + gid) * Nn + k0];
    const float* A8 = A0 + (size_t)8 * Nn;
    float ds[4] = {}, dc[4] = {};
#pragma unroll 4
    for (int ks = 0; ks < 16; ks++) {
        int kb = ks * 8;
        uint a0 = __float_as_uint(A0[kb + tig]);
        uint a1 = __float_as_uint(A8[kb + tig]);
        uint a2 = __float_as_uint(A0[kb + tig + 4]);
        uint a3 = __float_as_uint(A8[kb + tig + 4]);
        uint b0s = __float_as_uint(scs[(kb + tig) * 16 + gid]);
        uint b1s = __float_as_uint(scs[(kb + tig + 4) * 16 + gid]);
        uint b0c = __float_as_uint(scs[(kb + tig) * 16 + 8 + gid]);
        uint b1c = __float_as_uint(scs[(kb + tig + 4) * 16 + 8 + gid]);
        MMA_TF32(ds, a0, a1, a2, a3, b0s, b1s);
        MMA_TF32(dc, a0, a1, a2, a3, b0c, b1c);
    }
    size_t base = ((size_t)blockIdx.y * (Bb * Hh * Nn) + (bh << 10) + i0 + w * 16) * 16;
    int o2 = tig * 2;
    *(float2*)&pD[base + (size_t)gid * 16 + o2]           = make_float2(ds[0], ds[1]);
    *(float2*)&pD[base + (size_t)gid * 16 + 8 + o2]       = make_float2(dc[0], dc[1]);
    *(float2*)&pD[base + (size_t)(gid + 8) * 16 + o2]     = make_float2(ds[2], ds[3]);
    *(float2*)&pD[base + (size_t)(gid + 8) * 16 + 8 + o2] = make_float2(dc[2], dc[3]);
}

// ---------------------------------------------------------------------------
// Step update: reduce NKC partials, phase update + wrap + sincos.
// Writes std-layout s/c (full precision) and bh-layout sc (tf32) for next mma.
// ---------------------------------------------------------------------------
__global__ void step_update(const float* __restrict__ pD, float* __restrict__ ph,
                            const float* __restrict__ s_in, const float* __restrict__ c_in,
                            float* __restrict__ s_out, float* __restrict__ c_out,
                            float* __restrict__ sc_out,
                            const float* __restrict__ omega,
                            const float* __restrict__ cs_ptr) {
    int g = blockIdx.x * 256 + threadIdx.x;   // (bh, n, o)
    int bh = g >> 13, rem = g & 8191, n = rem >> 3, o = rem & 7;
    float js = 0.f, jc = 0.f;
#pragma unroll
    for (int kc = 0; kc < NKC; kc++) {
        size_t base = ((size_t)kc * (Bb * Hh * Nn) + (bh << 10) + n) * 16;
        js += pD[base + o];
        jc += pD[base + 8 + o];
    }
    int b = bh >> 2, h = bh & 3;
    int gs = ((b << 10) + n) * HO + h * Oo + o;
    float si = s_in[gs], ci = c_in[gs];
    float coup = ci * js - si * jc;
    float np = ph[gs] + DT_F * (omega[h * Oo + o] + (*cs_ptr) * coup);
    float v = np + PI_F;
    np = v - floorf(v * INV_2PI_F) * TWO_PI_F - PI_F;
    ph[gs] = np;
    float sn, cn;
    sincosf(np, &sn, &cn);
    s_out[gs] = sn;
    c_out[gs] = cn;
    int scb = ((bh << 10) + n) * 16 + o;
    sc_out[scb] = tf32r(sn);
    sc_out[scb + 8] = tf32r(cn);
}

// ---------------------------------------------------------------------------
// Final small GEMM: out = C @ Wo^T + bo, K=32.
// ---------------------------------------------------------------------------
__global__ void gemm_out(const float* __restrict__ X, const float* __restrict__ W,
                         const float* __restrict__ bias, float* __restrict__ out) {
    __shared__ float As[64][33];
    __shared__ float Ws[64][33];
    int m0 = blockIdx.x * 64, n0 = blockIdx.y * 64;
    int tid = threadIdx.x;
    int tx = tid & 15, ty = tid >> 4;
    float acc[4][4] = {};
    for (int li = tid; li < 64 * 32; li += 256) {
        int r = li >> 5, c = li & 31;
        As[r][c] = X[(size_t)(m0 + r) * HO + c];
        Ws[r][c] = W[(size_t)(n0 + r) * HO + c];
    }
    __syncthreads();
#pragma unroll
    for (int kk = 0; kk < 32; kk++) {
        float a[4], bb[4];
#pragma unroll
        for (int i = 0; i < 4; i++) a[i] = As[ty * 4 + i][kk];
#pragma unroll
        for (int j = 0; j < 4; j++) bb[j] = Ws[tx * 4 + j][kk];
#pragma unroll
        for (int i = 0; i < 4; i++)
#pragma unroll
            for (int j = 0; j < 4; j++)
                acc[i][j] = fmaf(a[i], bb[j], acc[i][j]);
    }
#pragma unroll
    for (int i = 0; i < 4; i++) {
        int m = m0 + ty * 4 + i;
#pragma unroll
        for (int j = 0; j < 4; j++) {
            int n = n0 + tx * 4 + j;
            out[(size_t)m * Dd + n] = acc[i][j] + bias[n];
        }
    }
}

// ---------------------------------------------------------------------------
extern "C" void kernel_launch(void* const* d_in, const int* in_sizes, int n_in,
                              void* d_out, int out_size) {
    const float* x     = (const float*)d_in[0];
    const float* Wq    = (const float*)d_in[1];
    const float* Wk    = (const float*)d_in[2];
    const float* Wp    = (const float*)d_in[3];
    const float* bp    = (const float*)d_in[4];
    const float* Wo    = (const float*)d_in[5];
    const float* bo    = (const float*)d_in[6];
    const float* omega = (const float*)d_in[7];
    const float* cs    = (const float*)d_in[8];
    float* out = (float*)d_out;

    float *q, *k, *ph, *s0, *s1, *c0, *c1, *sc0, *sc1, *J, *pD;
    cudaGetSymbolAddress((void**)&q,   g_q);
    cudaGetSymbolAddress((void**)&k,   g_k);
    cudaGetSymbolAddress((void**)&ph,  g_ph);
    cudaGetSymbolAddress((void**)&s0,  g_s0);
    cudaGetSymbolAddress((void**)&s1,  g_s1);
    cudaGetSymbolAddress((void**)&c0,  g_c0);
    cudaGetSymbolAddress((void**)&c1,  g_c1);
    cudaGetSymbolAddress((void**)&sc0, g_sc0);
    cudaGetSymbolAddress((void**)&sc1, g_sc1);
    cudaGetSymbolAddress((void**)&J,   g_J);
    cudaGetSymbolAddress((void**)&pD,  g_pD);

    dim3 blk(256);
    // fused projections (q, k, ph + sincos, both layouts)
    proj_kernel<<<dim3(Bb * Nn / 64, 9), blk>>>(x, Wq, Wk, Wp, bp, q, k, ph, s0, c0, sc0);
    // attention J (tf32-rounded in softmax)
    size_t smem_sc = (size_t)2 * 64 * SP * sizeof(float);
    cudaFuncSetAttribute(scores_kernel, cudaFuncAttributeMaxDynamicSharedMemorySize, (int)smem_sc);
    scores_kernel<<<dim3(Nn / 128, Nn / 128, Bb * Hh), blk, smem_sc>>>(q, k, J);
    softmax_kernel<<<Bb * Hh * Nn, blk>>>(J);
    // 5 oscillator steps: tensor-core matvec partials + reduce/update
    float* sbuf[2] = {s0, s1};
    float* cbuf[2] = {c0, c1};
    float* scbuf[2] = {sc0, sc1};
    for (int t = 0; t < NSTEPS; t++) {
        step_mma<<<dim3(Nn / 128, NKC, Bb * Hh), blk>>>(J, scbuf[t & 1], pD);
        step_update<<<GTOT / 256, blk>>>(
            pD, ph, sbuf[t & 1], cbuf[t & 1],
            sbuf[(t + 1) & 1], cbuf[(t + 1) & 1], scbuf[(t + 1) & 1],
            omega, cs);
    }
    // output: out = cos(final phases) @ Wo^T + bo
    const float* cfin = cbuf[NSTEPS & 1];
    gemm_out<<<dim3(Bb * Nn / 64, Dd / 64), blk>>>(cfin, Wo, bo, out);
}

// round 10
// speedup vs baseline: 2.0359x; 1.1865x over previous
#include <cuda_runtime.h>
#include <math.h>

#define Bb 2
#define Nn 1024
#define Dd 256
#define Hh 4
#define Oo 8
#define HO 32
#define DKK 64
#define NSTEPS 5
#define DT_F 0.1f
#define PI_F 3.14159265358979323846f
#define TWO_PI_F 6.28318530717958647692f
#define INV_2PI_F 0.15915494309189533577f

#define GTOT (Bb * Nn * HO)   // 65536
#define NKC 8                 // k-chunks for step mma (K=1024 -> 128 each)
#define JST 36                // smem stride (floats) for J sub-tile

typedef unsigned long long ull;
typedef unsigned int uint;

// Packed fp32x2 FMA (bit-identical to two scalar FFMAs).
#define FMA2(d, a, b) \
    asm("fma.rn.f32x2 %0, %1, %2, %0;" : "+l"(d) : "l"(a), "l"(b))
#define PACK2(d, x) \
    asm("mov.b64 %0, {%1, %1};" : "=l"(d) : "r"(__float_as_uint(x)))
#define UNPK2(lo, hi, v) \
    asm("mov.b64 {%0, %1}, %2;" : "=f"(lo), "=f"(hi) : "l"(v))

// tf32 round-to-nearest (so mma's truncation of these bits is exact)
__device__ __forceinline__ float tf32r(float x) {
    uint u;
    asm("cvt.rna.tf32.f32 %0, %1;" : "=r"(u) : "f"(x));
    return __uint_as_float(u);
}

// m16n8k8 tf32 mma, fp32 accumulate
#define MMA_TF32(d, a0, a1, a2, a3, b0, b1) \
    asm("mma.sync.aligned.m16n8k8.row.col.f32.tf32.tf32.f32 " \
        "{%0,%1,%2,%3}, {%4,%5,%6,%7}, {%8,%9}, {%0,%1,%2,%3};" \
        : "+f"(d[0]), "+f"(d[1]), "+f"(d[2]), "+f"(d[3]) \
        : "r"(a0), "r"(a1), "r"(a2), "r"(a3), "r"(b0), "r"(b1))

// cp.async helpers
#define CP16(dst_u32, src_ptr) \
    asm volatile("cp.async.cg.shared.global [%0], [%1], 16;" \
                 :: "r"(dst_u32), "l"(src_ptr))
#define CP_COMMIT() asm volatile("cp.async.commit_group;")
#define CP_WAIT(n)  asm volatile("cp.async.wait_group %0;" :: "n"(n))

// Scratch (no cudaMalloc allowed)
__device__ float g_q[Bb * Nn * Dd];
__device__ float g_k[Bb * Nn * Dd];
__device__ float g_ph[GTOT];
__device__ float g_s0[GTOT];
__device__ float g_s1[GTOT];
__device__ float g_c0[GTOT];
__device__ float g_c1[GTOT];
__device__ float g_sc0[Bb * Hh * Nn * 16];   // [bh][j][s0..7|c0..7] tf32
__device__ float g_sc1[Bb * Hh * Nn * 16];
__device__ float g_pD[NKC * Bb * Hh * Nn * 16];    // 4 MB partials
__device__ float g_J[(size_t)Bb * Hh * Nn * Nn];   // 32 MB (tf32-rounded)

// ---------------------------------------------------------------------------
// Fused projection kernel: q = x@Wq^T, k = x@Wk^T, ph = x@Wp^T + bp (+sincos).
// ---------------------------------------------------------------------------
__global__ __launch_bounds__(256, 2) void proj_kernel(
    const float* __restrict__ x,
    const float* __restrict__ Wq, const float* __restrict__ Wk,
    const float* __restrict__ Wp, const float* __restrict__ bp,
    float* __restrict__ q, float* __restrict__ k,
    float* __restrict__ ph, float* __restrict__ s0, float* __restrict__ c0,
    float* __restrict__ sc0) {
    __shared__ __align__(16) float As[64][68];   // [kk][m]
    __shared__ __align__(16) float Bs[64][68];   // [kk][n]
    int m0 = blockIdx.x * 64;
    int y = blockIdx.y;
    const float* W;
    int n0, Nout;
    if (y < 4)      { W = Wq; n0 = y * 64;       Nout = Dd; }
    else if (y < 8) { W = Wk; n0 = (y - 4) * 64; Nout = Dd; }
    else            { W = Wp; n0 = 0;            Nout = HO; }
    int tid = threadIdx.x;
    int tx = tid & 15, ty = tid >> 4;
    ull acc2[4][2] = {};
    for (int kt = 0; kt < Dd; kt += 64) {
        for (int t = tid; t < 64 * 16; t += 256) {
            int r = t >> 4, c4 = (t & 15) * 4;
            float4 va = *(const float4*)&x[(size_t)(m0 + r) * Dd + kt + c4];
            As[c4 + 0][r] = va.x; As[c4 + 1][r] = va.y;
            As[c4 + 2][r] = va.z; As[c4 + 3][r] = va.w;
            float4 vb = make_float4(0.f, 0.f, 0.f, 0.f);
            if (n0 + r < Nout)
                vb = *(const float4*)&W[(size_t)(n0 + r) * Dd + kt + c4];
            Bs[c4 + 0][r] = vb.x; Bs[c4 + 1][r] = vb.y;
            Bs[c4 + 2][r] = vb.z; Bs[c4 + 3][r] = vb.w;
        }
        __syncthreads();
#pragma unroll
        for (int kk = 0; kk < 64; kk++) {
            float4 a = *(const float4*)&As[kk][ty * 4];
            ulonglong2 bv = *(const ulonglong2*)&Bs[kk][tx * 4];
            ull aa0, aa1, aa2, aa3;
            PACK2(aa0, a.x); PACK2(aa1, a.y); PACK2(aa2, a.z); PACK2(aa3, a.w);
            FMA2(acc2[0][0], aa0, bv.x); FMA2(acc2[0][1], aa0, bv.y);
            FMA2(acc2[1][0], aa1, bv.x); FMA2(acc2[1][1], aa1, bv.y);
            FMA2(acc2[2][0], aa2, bv.x); FMA2(acc2[2][1], aa2, bv.y);
            FMA2(acc2[3][0], aa3, bv.x); FMA2(acc2[3][1], aa3, bv.y);
        }
        __syncthreads();
    }
    float acc[4][4];
#pragma unroll
    for (int i = 0; i < 4; i++) {
        UNPK2(acc[i][0], acc[i][1], acc2[i][0]);
        UNPK2(acc[i][2], acc[i][3], acc2[i][1]);
    }
    if (y < 8) {
        float* out = (y < 4) ? q : k;
#pragma unroll
        for (int i = 0; i < 4; i++) {
            int m = m0 + ty * 4 + i;
            float4 v = make_float4(acc[i][0], acc[i][1], acc[i][2], acc[i][3]);
            *(float4*)&out[(size_t)m * Dd + n0 + tx * 4] = v;
        }
    } else if (tx * 4 < HO) {
#pragma unroll
        for (int i = 0; i < 4; i++) {
            int m = m0 + ty * 4 + i;
#pragma unroll
            for (int j = 0; j < 4; j++) {
                int n = tx * 4 + j;
                float p = acc[i][j] + bp[n];
                int g = m * HO + n;
                ph[g] = p;
                float sn, cn;
                sincosf(p, &sn, &cn);
                s0[g] = sn;
                c0[g] = cn;
                int bh = (m >> 10) * 4 + (n >> 3);
                int scb = ((bh << 10) + (m & 1023)) * 16 + (n & 7);
                sc0[scb] = tf32r(sn);
                sc0[scb + 8] = tf32r(cn);
            }
        }
    }
}

// ---------------------------------------------------------------------------
// Scores: S[bh,i,j] = 0.125 * dot(q_i,k_j). 128x128 tile, 8x8 micro-tile.
// ---------------------------------------------------------------------------
#define SP 132
__global__ __launch_bounds__(256, 2) void scores_kernel(
    const float* __restrict__ q, const float* __restrict__ k,
    float* __restrict__ J) {
    extern __shared__ __align__(16) float sm[];
    float* Qs = sm;            // [64][SP]
    float* Ks = sm + 64 * SP;  // [64][SP]
    int bh = blockIdx.z;
    int b = bh >> 2, h = bh & 3;
    int i0 = blockIdx.x * 128, j0 = blockIdx.y * 128;
    int tid = threadIdx.x;
    for (int t = tid; t < 128 * 16; t += 256) {
        int r = t >> 4, c4 = (t & 15) * 4;
        float4 vq = *(const float4*)&q[(size_t)(b * Nn + i0 + r) * Dd + h * DKK + c4];
        Qs[(c4 + 0) * SP + r] = vq.x; Qs[(c4 + 1) * SP + r] = vq.y;
        Qs[(c4 + 2) * SP + r] = vq.z; Qs[(c4 + 3) * SP + r] = vq.w;
        float4 vk = *(const float4*)&k[(size_t)(b * Nn + j0 + r) * Dd + h * DKK + c4];
        Ks[(c4 + 0) * SP + r] = vk.x; Ks[(c4 + 1) * SP + r] = vk.y;
        Ks[(c4 + 2) * SP + r] = vk.z; Ks[(c4 + 3) * SP + r] = vk.w;
    }
    __syncthreads();
    int tx = tid & 15, ty = tid >> 4;
    ull acc2[8][4] = {};
#pragma unroll
    for (int kk = 0; kk < 64; kk++) {
        float4 a0 = *(const float4*)&Qs[kk * SP + ty * 8];
        float4 a1 = *(const float4*)&Qs[kk * SP + ty * 8 + 4];
        ulonglong2 b0 = *(const ulonglong2*)&Ks[kk * SP + tx * 8];
        ulonglong2 b1 = *(const ulonglong2*)&Ks[kk * SP + tx * 8 + 4];
        float av[8] = {a0.x, a0.y, a0.z, a0.w, a1.x, a1.y, a1.z, a1.w};
#pragma unroll
        for (int i = 0; i < 8; i++) {
            ull aa;
            PACK2(aa, av[i]);
            FMA2(acc2[i][0], aa, b0.x);
            FMA2(acc2[i][1], aa, b0.y);
            FMA2(acc2[i][2], aa, b1.x);
            FMA2(acc2[i][3], aa, b1.y);
        }
    }
    size_t rowbase = ((size_t)bh * Nn + i0 + ty * 8) * Nn + j0 + tx * 8;
#pragma unroll
    for (int i = 0; i < 8; i++) {
        float o0, o1, o2, o3, o4, o5, o6, o7;
        UNPK2(o0, o1, acc2[i][0]); UNPK2(o2, o3, acc2[i][1]);
        UNPK2(o4, o5, acc2[i][2]); UNPK2(o6, o7, acc2[i][3]);
        float4 v0 = make_float4(0.125f * o0, 0.125f * o1, 0.125f * o2, 0.125f * o3);
        float4 v1 = make_float4(0.125f * o4, 0.125f * o5, 0.125f * o6, 0.125f * o7);
        *(float4*)&J[rowbase + (size_t)i * Nn] = v0;
        *(float4*)&J[rowbase + (size_t)i * Nn + 4] = v1;
    }
}

// ---------------------------------------------------------------------------
// In-place row softmax over J rows of length 1024; output rounded to tf32.
// ---------------------------------------------------------------------------
__global__ void softmax_kernel(float* __restrict__ J) {
    __shared__ float red[8];
    size_t base = (size_t)blockIdx.x * Nn;
    int tid = threadIdx.x, lane = tid & 31, warp = tid >> 5;
    float4 v = reinterpret_cast<float4*>(J + base)[tid];
    float m = fmaxf(fmaxf(v.x, v.y), fmaxf(v.z, v.w));
#pragma unroll
    for (int off = 16; off; off >>= 1)
        m = fmaxf(m, __shfl_xor_sync(0xffffffffu, m, off));
    if (lane == 0) red[warp] = m;
    __syncthreads();
    if (warp == 0) {
        float x = (lane < 8) ? red[lane] : -1e30f;
#pragma unroll
        for (int off = 16; off; off >>= 1)
            x = fmaxf(x, __shfl_xor_sync(0xffffffffu, x, off));
        if (lane == 0) red[0] = x;
    }
    __syncthreads();
    m = red[0];
    v.x = __expf(v.x - m); v.y = __expf(v.y - m);
    v.z = __expf(v.z - m); v.w = __expf(v.w - m);
    float s = v.x + v.y + v.z + v.w;
#pragma unroll
    for (int off = 16; off; off >>= 1)
        s += __shfl_xor_sync(0xffffffffu, s, off);
    __syncthreads();
    if (lane == 0) red[warp] = s;
    __syncthreads();
    if (warp == 0) {
        float x = (lane < 8) ? red[lane] : 0.f;
#pragma unroll
        for (int off = 16; off; off >>= 1)
            x += __shfl_xor_sync(0xffffffffu, x, off);
        if (lane == 0) red[0] = x;
    }
    __syncthreads();
    float inv = 1.f / red[0];
    v.x = tf32r(v.x * inv); v.y = tf32r(v.y * inv);
    v.z = tf32r(v.z * inv); v.w = tf32r(v.w * inv);
    reinterpret_cast<float4*>(J + base)[tid] = v;
}

// ---------------------------------------------------------------------------
// Step matvec on tensor cores with cp.async double-buffered J staging.
// pD[kc][bh][i][0..7]=J@s partial, [8..15]=J@c partial.
// Grid (8 i-strips, NKC k-chunks, 8 bh), 256 thr = 8 warps x 16 rows.
// K=128 per CTA processed in 4 sub-chunks of 32 (16 KB tiles, 2 buffers).
// ---------------------------------------------------------------------------
__global__ __launch_bounds__(256, 4) void step_mma(
    const float* __restrict__ J, const float* __restrict__ sc,
    float* __restrict__ pD) {
    __shared__ __align__(16) float scs[128 * 16];        // 8 KB
    __shared__ __align__(16) float Jt[2][128 * JST];     // 2 x 18 KB
    int i0 = blockIdx.x * 128;
    int k0 = blockIdx.y * 128;
    int bh = blockIdx.z;
    int tid = threadIdx.x;
    // B operand (sc) -> smem (plain loads; covered by first __syncthreads)
    {
        const float4* src = (const float4*)&sc[((bh << 10) + k0) * 16];
        float4* dst = (float4*)scs;
        dst[tid] = src[tid];
        dst[tid + 256] = src[tid + 256];
    }
    // cp.async J tile prologue: sub-chunk 0 -> buffer 0
    const float* Jbase = &J[((size_t)(bh << 10) + i0) * Nn + k0];
    int lr = tid >> 3, lc4 = (tid & 7) * 4;   // row 0..31 block, col quad
#pragma unroll
    for (int it = 0; it < 4; it++) {
        int r = lr + it * 32;
        uint dst = (uint)__cvta_generic_to_shared(&Jt[0][r * JST + lc4]);
        CP16(dst, &Jbase[(size_t)r * Nn + lc4]);
    }
    CP_COMMIT();

    int w = tid >> 5, lane = tid & 31;
    int gid = lane >> 2, tig = lane & 3;
    int r0 = w * 16 + gid;
    float ds[4] = {}, dc[4] = {};
#pragma unroll
    for (int sub = 0; sub < 4; sub++) {
        if (sub < 3) {   // prefetch next sub-chunk into other buffer
            int nk = (sub + 1) * 32;
            float* bufn = Jt[(sub + 1) & 1];
#pragma unroll
            for (int it = 0; it < 4; it++) {
                int r = lr + it * 32;
                uint dst = (uint)__cvta_generic_to_shared(&bufn[r * JST + lc4]);
                CP16(dst, &Jbase[(size_t)r * Nn + nk + lc4]);
            }
            CP_COMMIT();
            CP_WAIT(1);
        } else {
            CP_WAIT(0);
        }
        __syncthreads();
        const float* buf = Jt[sub & 1];
#pragma unroll
        for (int ks = 0; ks < 4; ks++) {
            int kb = ks * 8;
            uint a0 = __float_as_uint(buf[r0 * JST + kb + tig]);
            uint a1 = __float_as_uint(buf[(r0 + 8) * JST + kb + tig]);
            uint a2 = __float_as_uint(buf[r0 * JST + kb + tig + 4]);
            uint a3 = __float_as_uint(buf[(r0 + 8) * JST + kb + tig + 4]);
            int kg = sub * 32 + kb;
            uint b0s = __float_as_uint(scs[(kg + tig) * 16 + gid]);
            uint b1s = __float_as_uint(scs[(kg + tig + 4) * 16 + gid]);
            uint b0c = __float_as_uint(scs[(kg + tig) * 16 + 8 + gid]);
            uint b1c = __float_as_uint(scs[(kg + tig + 4) * 16 + 8 + gid]);
            MMA_TF32(ds, a0, a1, a2, a3, b0s, b1s);
            MMA_TF32(dc, a0, a1, a2, a3, b0c, b1c);
        }
        __syncthreads();
    }
    size_t base = ((size_t)blockIdx.y * (Bb * Hh * Nn) + (bh << 10) + i0 + w * 16) * 16;
    int o2 = tig * 2;
    *(float2*)&pD[base + (size_t)gid * 16 + o2]           = make_float2(ds[0], ds[1]);
    *(float2*)&pD[base + (size_t)gid * 16 + 8 + o2]       = make_float2(dc[0], dc[1]);
    *(float2*)&pD[base + (size_t)(gid + 8) * 16 + o2]     = make_float2(ds[2], ds[3]);
    *(float2*)&pD[base + (size_t)(gid + 8) * 16 + 8 + o2] = make_float2(dc[2], dc[3]);
}

// ---------------------------------------------------------------------------
// Step update: reduce NKC partials, phase update + wrap + sincos.
// Writes std-layout s/c (full precision) and bh-layout sc (tf32) for next mma.
// ---------------------------------------------------------------------------
__global__ void step_update(const float* __restrict__ pD, float* __restrict__ ph,
                            const float* __restrict__ s_in, const float* __restrict__ c_in,
                            float* __restrict__ s_out, float* __restrict__ c_out,
                            float* __restrict__ sc_out,
                            const float* __restrict__ omega,
                            const float* __restrict__ cs_ptr) {
    int g = blockIdx.x * 256 + threadIdx.x;   // (bh, n, o)
    int bh = g >> 13, rem = g & 8191, n = rem >> 3, o = rem & 7;
    float js = 0.f, jc = 0.f;
#pragma unroll
    for (int kc = 0; kc < NKC; kc++) {
        size_t base = ((size_t)kc * (Bb * Hh * Nn) + (bh << 10) + n) * 16;
        js += pD[base + o];
        jc += pD[base + 8 + o];
    }
    int b = bh >> 2, h = bh & 3;
    int gs = ((b << 10) + n) * HO + h * Oo + o;
    float si = s_in[gs], ci = c_in[gs];
    float coup = ci * js - si * jc;
    float np = ph[gs] + DT_F * (omega[h * Oo + o] + (*cs_ptr) * coup);
    float v = np + PI_F;
    np = v - floorf(v * INV_2PI_F) * TWO_PI_F - PI_F;
    ph[gs] = np;
    float sn, cn;
    sincosf(np, &sn, &cn);
    s_out[gs] = sn;
    c_out[gs] = cn;
    int scb = ((bh << 10) + n) * 16 + o;
    sc_out[scb] = tf32r(sn);
    sc_out[scb + 8] = tf32r(cn);
}

// ---------------------------------------------------------------------------
// Final small GEMM: out = C @ Wo^T + bo, K=32.
// ---------------------------------------------------------------------------
__global__ void gemm_out(const float* __restrict__ X, const float* __restrict__ W,
                         const float* __restrict__ bias, float* __restrict__ out) {
    __shared__ float As[64][33];
    __shared__ float Ws[64][33];
    int m0 = blockIdx.x * 64, n0 = blockIdx.y * 64;
    int tid = threadIdx.x;
    int tx = tid & 15, ty = tid >> 4;
    float acc[4][4] = {};
    for (int li = tid; li < 64 * 32; li += 256) {
        int r = li >> 5, c = li & 31;
        As[r][c] = X[(size_t)(m0 + r) * HO + c];
        Ws[r][c] = W[(size_t)(n0 + r) * HO + c];
    }
    __syncthreads();
#pragma unroll
    for (int kk = 0; kk < 32; kk++) {
        float a[4], bb[4];
#pragma unroll
        for (int i = 0; i < 4; i++) a[i] = As[ty * 4 + i][kk];
#pragma unroll
        for (int j = 0; j < 4; j++) bb[j] = Ws[tx * 4 + j][kk];
#pragma unroll
        for (int i = 0; i < 4; i++)
#pragma unroll
            for (int j = 0; j < 4; j++)
                acc[i][j] = fmaf(a[i], bb[j], acc[i][j]);
    }
#pragma unroll
    for (int i = 0; i < 4; i++) {
        int m = m0 + ty * 4 + i;
#pragma unroll
        for (int j = 0; j < 4; j++) {
            int n = n0 + tx * 4 + j;
            out[(size_t)m * Dd + n] = acc[i][j] + bias[n];
        }
    }
}

// ---------------------------------------------------------------------------
extern "C" void kernel_launch(void* const* d_in, const int* in_sizes, int n_in,
                              void* d_out, int out_size) {
    const float* x     = (const float*)d_in[0];
    const float* Wq    = (const float*)d_in[1];
    const float* Wk    = (const float*)d_in[2];
    const float* Wp    = (const float*)d_in[3];
    const float* bp    = (const float*)d_in[4];
    const float* Wo    = (const float*)d_in[5];
    const float* bo    = (const float*)d_in[6];
    const float* omega = (const float*)d_in[7];
    const float* cs    = (const float*)d_in[8];
    float* out = (float*)d_out;

    float *q, *k, *ph, *s0, *s1, *c0, *c1, *sc0, *sc1, *J, *pD;
    cudaGetSymbolAddress((void**)&q,   g_q);
    cudaGetSymbolAddress((void**)&k,   g_k);
    cudaGetSymbolAddress((void**)&ph,  g_ph);
    cudaGetSymbolAddress((void**)&s0,  g_s0);
    cudaGetSymbolAddress((void**)&s1,  g_s1);
    cudaGetSymbolAddress((void**)&c0,  g_c0);
    cudaGetSymbolAddress((void**)&c1,  g_c1);
    cudaGetSymbolAddress((void**)&sc0, g_sc0);
    cudaGetSymbolAddress((void**)&sc1, g_sc1);
    cudaGetSymbolAddress((void**)&J,   g_J);
    cudaGetSymbolAddress((void**)&pD,  g_pD);

    dim3 blk(256);
    // fused projections (q, k, ph + sincos, both layouts)
    proj_kernel<<<dim3(Bb * Nn / 64, 9), blk>>>(x, Wq, Wk, Wp, bp, q, k, ph, s0, c0, sc0);
    // attention J (tf32-rounded in softmax)
    size_t smem_sc = (size_t)2 * 64 * SP * sizeof(float);
    cudaFuncSetAttribute(scores_kernel, cudaFuncAttributeMaxDynamicSharedMemorySize, (int)smem_sc);
    scores_kernel<<<dim3(Nn / 128, Nn / 128, Bb * Hh), blk, smem_sc>>>(q, k, J);
    softmax_kernel<<<Bb * Hh * Nn, blk>>>(J);
    // 5 oscillator steps: pipelined tensor-core matvec partials + reduce/update
    float* sbuf[2] = {s0, s1};
    float* cbuf[2] = {c0, c1};
    float* scbuf[2] = {sc0, sc1};
    for (int t = 0; t < NSTEPS; t++) {
        step_mma<<<dim3(Nn / 128, NKC, Bb * Hh), blk>>>(J, scbuf[t & 1], pD);
        step_update<<<GTOT / 256, blk>>>(
            pD, ph, sbuf[t & 1], cbuf[t & 1],
            sbuf[(t + 1) & 1], cbuf[(t + 1) & 1], scbuf[(t + 1) & 1],
            omega, cs);
    }
    // output: out = cos(final phases) @ Wo^T + bo
    const float* cfin = cbuf[NSTEPS & 1];
    gemm_out<<<dim3(Bb * Nn / 64, Dd / 64), blk>>>(cfin, Wo, bo, out);
}

// round 12
// speedup vs baseline: 2.3301x; 1.1445x over previous
#include <cuda_runtime.h>
#include <cuda_bf16.h>
#include <math.h>

#define Bb 2
#define Nn 1024
#define Dd 256
#define Hh 4
#define Oo 8
#define HO 32
#define DKK 64
#define NSTEPS 5
#define DT_F 0.1f
#define PI_F 3.14159265358979323846f
#define TWO_PI_F 6.28318530717958647692f
#define INV_2PI_F 0.15915494309189533577f

#define GTOT (Bb * Nn * HO)   // 65536
#define NKC 8                 // k-chunks for step mma (K=1024 -> 128 each)
#define JROW 72               // bf16 J-tile row stride (36 words, conflict-free)
#define SCW 24                // sc smem words per j-pair (conflict-free pad)

typedef unsigned long long ull;
typedef unsigned int uint;

// Packed fp32x2 FMA (bit-identical to two scalar FFMAs).
#define FMA2(d, a, b) \
    asm("fma.rn.f32x2 %0, %1, %2, %0;" : "+l"(d) : "l"(a), "l"(b))
#define PACK2(d, x) \
    asm("mov.b64 %0, {%1, %1};" : "=l"(d) : "r"(__float_as_uint(x)))
#define UNPK2(lo, hi, v) \
    asm("mov.b64 {%0, %1}, %2;" : "=f"(lo), "=f"(hi) : "l"(v))

// pack two f32 -> bf16x2 (lo in low 16 bits)
__device__ __forceinline__ uint bf16x2(float lo, float hi) {
    uint r;
    asm("cvt.rn.bf16x2.f32 %0, %1, %2;" : "=r"(r) : "f"(hi), "f"(lo));
    return r;
}

// m16n8k16 bf16 mma, fp32 accumulate
#define MMA_BF16(d, a0, a1, a2, a3, b0, b1) \
    asm("mma.sync.aligned.m16n8k16.row.col.f32.bf16.bf16.f32 " \
        "{%0,%1,%2,%3}, {%4,%5,%6,%7}, {%8,%9}, {%0,%1,%2,%3};" \
        : "+f"(d[0]), "+f"(d[1]), "+f"(d[2]), "+f"(d[3]) \
        : "r"(a0), "r"(a1), "r"(a2), "r"(a3), "r"(b0), "r"(b1))

// cp.async helpers
#define CP16(dst_u32, src_ptr) \
    asm volatile("cp.async.cg.shared.global [%0], [%1], 16;" \
                 :: "r"(dst_u32), "l"(src_ptr))
#define CP_COMMIT() asm volatile("cp.async.commit_group;")
#define CP_WAIT(n)  asm volatile("cp.async.wait_group %0;" :: "n"(n))

// Scratch (no cudaMalloc allowed)
__device__ float g_q[Bb * Nn * Dd];
__device__ float g_k[Bb * Nn * Dd];
__device__ float g_ph[GTOT];
__device__ float g_s0[GTOT];
__device__ float g_s1[GTOT];
__device__ float g_c0[GTOT];
__device__ float g_c1[GTOT];
__device__ __nv_bfloat16 g_sch0[Bb * Hh * Nn * 16];  // [bh][jp][o16][2] sin|cos
__device__ __nv_bfloat16 g_sch1[Bb * Hh * Nn * 16];
__device__ float g_pD[NKC * Bb * Hh * Nn * 16];            // 4 MB partials
__device__ float g_J[(size_t)Bb * Hh * Nn * Nn];           // 32 MB fp32 scores
__device__ __nv_bfloat16 g_Jh[(size_t)Bb * Hh * Nn * Nn];  // 16 MB bf16 J

// ---------------------------------------------------------------------------
// Fused projection kernel: q = x@Wq^T, k = x@Wk^T, ph = x@Wp^T + bp (+sincos).
// ---------------------------------------------------------------------------
__global__ __launch_bounds__(256, 2) void proj_kernel(
    const float* __restrict__ x,
    const float* __restrict__ Wq, const float* __restrict__ Wk,
    const float* __restrict__ Wp, const float* __restrict__ bp,
    float* __restrict__ q, float* __restrict__ k,
    float* __restrict__ ph, float* __restrict__ s0, float* __restrict__ c0,
    __nv_bfloat16* __restrict__ sch0) {
    __shared__ __align__(16) float As[64][68];   // [kk][m]
    __shared__ __align__(16) float Bs[64][68];   // [kk][n]
    int m0 = blockIdx.x * 64;
    int y = blockIdx.y;
    const float* W;
    int n0, Nout;
    if (y < 4)      { W = Wq; n0 = y * 64;       Nout = Dd; }
    else if (y < 8) { W = Wk; n0 = (y - 4) * 64; Nout = Dd; }
    else            { W = Wp; n0 = 0;            Nout = HO; }
    int tid = threadIdx.x;
    int tx = tid & 15, ty = tid >> 4;
    ull acc2[4][2] = {};
    for (int kt = 0; kt < Dd; kt += 64) {
        for (int t = tid; t < 64 * 16; t += 256) {
            int r = t >> 4, c4 = (t & 15) * 4;
            float4 va = *(const float4*)&x[(size_t)(m0 + r) * Dd + kt + c4];
            As[c4 + 0][r] = va.x; As[c4 + 1][r] = va.y;
            As[c4 + 2][r] = va.z; As[c4 + 3][r] = va.w;
            float4 vb = make_float4(0.f, 0.f, 0.f, 0.f);
            if (n0 + r < Nout)
                vb = *(const float4*)&W[(size_t)(n0 + r) * Dd + kt + c4];
            Bs[c4 + 0][r] = vb.x; Bs[c4 + 1][r] = vb.y;
            Bs[c4 + 2][r] = vb.z; Bs[c4 + 3][r] = vb.w;
        }
        __syncthreads();
#pragma unroll
        for (int kk = 0; kk < 64; kk++) {
            float4 a = *(const float4*)&As[kk][ty * 4];
            ulonglong2 bv = *(const ulonglong2*)&Bs[kk][tx * 4];
            ull aa0, aa1, aa2, aa3;
            PACK2(aa0, a.x); PACK2(aa1, a.y); PACK2(aa2, a.z); PACK2(aa3, a.w);
            FMA2(acc2[0][0], aa0, bv.x); FMA2(acc2[0][1], aa0, bv.y);
            FMA2(acc2[1][0], aa1, bv.x); FMA2(acc2[1][1], aa1, bv.y);
            FMA2(acc2[2][0], aa2, bv.x); FMA2(acc2[2][1], aa2, bv.y);
            FMA2(acc2[3][0], aa3, bv.x); FMA2(acc2[3][1], aa3, bv.y);
        }
        __syncthreads();
    }
    float acc[4][4];
#pragma unroll
    for (int i = 0; i < 4; i++) {
        UNPK2(acc[i][0], acc[i][1], acc2[i][0]);
        UNPK2(acc[i][2], acc[i][3], acc2[i][1]);
    }
    if (y < 8) {
        float* out = (y < 4) ? q : k;
#pragma unroll
        for (int i = 0; i < 4; i++) {
            int m = m0 + ty * 4 + i;
            float4 v = make_float4(acc[i][0], acc[i][1], acc[i][2], acc[i][3]);
            *(float4*)&out[(size_t)m * Dd + n0 + tx * 4] = v;
        }
    } else if (tx * 4 < HO) {
#pragma unroll
        for (int i = 0; i < 4; i++) {
            int m = m0 + ty * 4 + i;
            int j = m & 1023, b = m >> 10;
            int jp = j >> 1, jb = j & 1;
#pragma unroll
            for (int jj = 0; jj < 4; jj++) {
                int n = tx * 4 + jj;
                float p = acc[i][jj] + bp[n];
                int g = m * HO + n;
                ph[g] = p;
                float sn, cn;
                sincosf(p, &sn, &cn);
                s0[g] = sn;
                c0[g] = cn;
                int bh = b * 4 + (n >> 3), o = n & 7;
                int base = ((bh << 9) + jp) * 32;
                sch0[base + o * 2 + jb] = __float2bfloat16_rn(sn);
                sch0[base + 16 + o * 2 + jb] = __float2bfloat16_rn(cn);
            }
        }
    }
}

// ---------------------------------------------------------------------------
// Scores: S[bh,i,j] = 0.125 * dot(q_i,k_j). 128x128 tile, 8x8 micro-tile.
// ---------------------------------------------------------------------------
#define SP 132
__global__ __launch_bounds__(256, 2) void scores_kernel(
    const float* __restrict__ q, const float* __restrict__ k,
    float* __restrict__ J) {
    extern __shared__ __align__(16) float sm[];
    float* Qs = sm;            // [64][SP]
    float* Ks = sm + 64 * SP;  // [64][SP]
    int bh = blockIdx.z;
    int b = bh >> 2, h = bh & 3;
    int i0 = blockIdx.x * 128, j0 = blockIdx.y * 128;
    int tid = threadIdx.x;
    for (int t = tid; t < 128 * 16; t += 256) {
        int r = t >> 4, c4 = (t & 15) * 4;
        float4 vq = *(const float4*)&q[(size_t)(b * Nn + i0 + r) * Dd + h * DKK + c4];
        Qs[(c4 + 0) * SP + r] = vq.x; Qs[(c4 + 1) * SP + r] = vq.y;
        Qs[(c4 + 2) * SP + r] = vq.z; Qs[(c4 + 3) * SP + r] = vq.w;
        float4 vk = *(const float4*)&k[(size_t)(b * Nn + j0 + r) * Dd + h * DKK + c4];
        Ks[(c4 + 0) * SP + r] = vk.x; Ks[(c4 + 1) * SP + r] = vk.y;
        Ks[(c4 + 2) * SP + r] = vk.z; Ks[(c4 + 3) * SP + r] = vk.w;
    }
    __syncthreads();
    int tx = tid & 15, ty = tid >> 4;
    ull acc2[8][4] = {};
#pragma unroll
    for (int kk = 0; kk < 64; kk++) {
        float4 a0 = *(const float4*)&Qs[kk * SP + ty * 8];
        float4 a1 = *(const float4*)&Qs[kk * SP + ty * 8 + 4];
        ulonglong2 b0 = *(const ulonglong2*)&Ks[kk * SP + tx * 8];
        ulonglong2 b1 = *(const ulonglong2*)&Ks[kk * SP + tx * 8 + 4];
        float av[8] = {a0.x, a0.y, a0.z, a0.w, a1.x, a1.y, a1.z, a1.w};
#pragma unroll
        for (int i = 0; i < 8; i++) {
            ull aa;
            PACK2(aa, av[i]);
            FMA2(acc2[i][0], aa, b0.x);
            FMA2(acc2[i][1], aa, b0.y);
            FMA2(acc2[i][2], aa, b1.x);
            FMA2(acc2[i][3], aa, b1.y);
        }
    }
    size_t rowbase = ((size_t)bh * Nn + i0 + ty * 8) * Nn + j0 + tx * 8;
#pragma unroll
    for (int i = 0; i < 8; i++) {
        float o0, o1, o2, o3, o4, o5, o6, o7;
        UNPK2(o0, o1, acc2[i][0]); UNPK2(o2, o3, acc2[i][1]);
        UNPK2(o4, o5, acc2[i][2]); UNPK2(o6, o7, acc2[i][3]);
        float4 v0 = make_float4(0.125f * o0, 0.125f * o1, 0.125f * o2, 0.125f * o3);
        float4 v1 = make_float4(0.125f * o4, 0.125f * o5, 0.125f * o6, 0.125f * o7);
        *(float4*)&J[rowbase + (size_t)i * Nn] = v0;
        *(float4*)&J[rowbase + (size_t)i * Nn + 4] = v1;
    }
}

// ---------------------------------------------------------------------------
// Row softmax over fp32 scores, output written as bf16 Jh.
// ---------------------------------------------------------------------------
__global__ void softmax_kernel(const float* __restrict__ J,
                               __nv_bfloat16* __restrict__ Jh) {
    __shared__ float red[8];
    size_t base = (size_t)blockIdx.x * Nn;
    int tid = threadIdx.x, lane = tid & 31, warp = tid >> 5;
    float4 v = reinterpret_cast<const float4*>(J + base)[tid];
    float m = fmaxf(fmaxf(v.x, v.y), fmaxf(v.z, v.w));
#pragma unroll
    for (int off = 16; off; off >>= 1)
        m = fmaxf(m, __shfl_xor_sync(0xffffffffu, m, off));
    if (lane == 0) red[warp] = m;
    __syncthreads();
    if (warp == 0) {
        float x = (lane < 8) ? red[lane] : -1e30f;
#pragma unroll
        for (int off = 16; off; off >>= 1)
            x = fmaxf(x, __shfl_xor_sync(0xffffffffu, x, off));
        if (lane == 0) red[0] = x;
    }
    __syncthreads();
    m = red[0];
    v.x = __expf(v.x - m); v.y = __expf(v.y - m);
    v.z = __expf(v.z - m); v.w = __expf(v.w - m);
    float s = v.x + v.y + v.z + v.w;
#pragma unroll
    for (int off = 16; off; off >>= 1)
        s += __shfl_xor_sync(0xffffffffu, s, off);
    __syncthreads();
    if (lane == 0) red[warp] = s;
    __syncthreads();
    if (warp == 0) {
        float x = (lane < 8) ? red[lane] : 0.f;
#pragma unroll
        for (int off = 16; off; off >>= 1)
            x += __shfl_xor_sync(0xffffffffu, x, off);
        if (lane == 0) red[0] = x;
    }
    __syncthreads();
    float inv = 1.f / red[0];
    uint2 pk;
    pk.x = bf16x2(v.x * inv, v.y * inv);
    pk.y = bf16x2(v.z * inv, v.w * inv);
    *(uint2*)&Jh[base + tid * 4] = pk;
}

// ---------------------------------------------------------------------------
// Step matvec: bf16 m16n8k16 MMA over bf16 J, cp.async double-buffered.
// pD[kc][bh][i][0..7]=J@s partial, [8..15]=J@c partial (fp32).
// Grid (8 i-strips, NKC k-chunks, 8 bh), 256 thr = 8 warps x 16 rows.
// K=128 per CTA in 2 sub-chunks of 64.
// ---------------------------------------------------------------------------
__global__ __launch_bounds__(256, 5) void step_mma(
    const __nv_bfloat16* __restrict__ Jh, const __nv_bfloat16* __restrict__ sch,
    float* __restrict__ pD) {
    __shared__ __align__(16) __nv_bfloat16 Jt[2][128 * JROW];  // 2 x 18 KB
    __shared__ __align__(16) float scs[64 * SCW];              // 6 KB
    int i0 = blockIdx.x * 128;
    int k0 = blockIdx.y * 128;
    int bh = blockIdx.z;
    int tid = threadIdx.x;
    // stage sc: 64 j-pairs x 16 words, re-strided to SCW
    {
        const uint* src = (const uint*)&sch[(((bh << 9) + (k0 >> 1)) << 5)];
#pragma unroll
        for (int it = 0; it < 4; it++) {
            int w = tid + it * 256;
            scs[(w >> 4) * SCW + (w & 15)] = __uint_as_float(src[w]);
        }
    }
    // cp.async J prologue: sub-chunk 0 (64 bf16 per row = 128 B)
    const __nv_bfloat16* Jbase = &Jh[((size_t)(bh << 10) + i0) * Nn + k0];
    int lr = tid >> 3, lc = (tid & 7) * 8;
#pragma unroll
    for (int it = 0; it < 4; it++) {
        int r = lr + it * 32;
        uint dst = (uint)__cvta_generic_to_shared(&Jt[0][r * JROW + lc]);
        CP16(dst, &Jbase[(size_t)r * Nn + lc]);
    }
    CP_COMMIT();

    int w = tid >> 5, lane = tid & 31;
    int gid = lane >> 2, tig = lane & 3;
    int r0 = w * 16;
    float ds[4] = {}, dc[4] = {};
#pragma unroll
    for (int sub = 0; sub < 2; sub++) {
        if (sub == 0) {   // prefetch sub 1
#pragma unroll
            for (int it = 0; it < 4; it++) {
                int r = lr + it * 32;
                uint dst = (uint)__cvta_generic_to_shared(&Jt[1][r * JROW + lc]);
                CP16(dst, &Jbase[(size_t)r * Nn + 64 + lc]);
            }
            CP_COMMIT();
            CP_WAIT(1);
        } else {
            CP_WAIT(0);
        }
        __syncthreads();
        const uint* bw = (const uint*)Jt[sub];
#pragma unroll
        for (int kk = 0; kk < 4; kk++) {
            int aw = (r0 + gid) * (JROW / 2) + kk * 8 + tig;
            uint a0 = bw[aw];
            uint a1 = bw[aw + 8 * (JROW / 2)];
            uint a2 = bw[aw + 4];
            uint a3 = bw[aw + 8 * (JROW / 2) + 4];
            int jp = sub * 32 + kk * 8 + tig;
            uint b0s = __float_as_uint(scs[jp * SCW + gid]);
            uint b1s = __float_as_uint(scs[(jp + 4) * SCW + gid]);
            uint b0c = __float_as_uint(scs[jp * SCW + 8 + gid]);
            uint b1c = __float_as_uint(scs[(jp + 4) * SCW + 8 + gid]);
            MMA_BF16(ds, a0, a1, a2, a3, b0s, b1s);
            MMA_BF16(dc, a0, a1, a2, a3, b0c, b1c);
        }
        __syncthreads();
    }
    size_t base = ((size_t)blockIdx.y * (Bb * Hh * Nn) + (bh << 10) + i0 + w * 16) * 16;
    int o2 = tig * 2;
    *(float2*)&pD[base + (size_t)gid * 16 + o2]           = make_float2(ds[0], ds[1]);
    *(float2*)&pD[base + (size_t)gid * 16 + 8 + o2]       = make_float2(dc[0], dc[1]);
    *(float2*)&pD[base + (size_t)(gid + 8) * 16 + o2]     = make_float2(ds[2], ds[3]);
    *(float2*)&pD[base + (size_t)(gid + 8) * 16 + 8 + o2] = make_float2(dc[2], dc[3]);
}

// ---------------------------------------------------------------------------
// Step update: reduce NKC partials, phase update + wrap + sincos.
// Writes std-layout s/c (fp32) and bh-layout bf16 sc for the next mma.
// ---------------------------------------------------------------------------
__global__ void step_update(const float* __restrict__ pD, float* __restrict__ ph,
                            const float* __restrict__ s_in, const float* __restrict__ c_in,
                            float* __restrict__ s_out, float* __restrict__ c_out,
                            __nv_bfloat16* __restrict__ sch_out,
                            const float* __restrict__ omega,
                            const float* __restrict__ cs_ptr) {
    int g = blockIdx.x * 256 + threadIdx.x;   // (bh, n, o)
    int bh = g >> 13, rem = g & 8191, n = rem >> 3, o = rem & 7;
    float js = 0.f, jc = 0.f;
#pragma unroll
    for (int kc = 0; kc < NKC; kc++) {
        size_t base = ((size_t)kc * (Bb * Hh * Nn) + (bh << 10) + n) * 16;
        js += pD[base + o];
        jc += pD[base + 8 + o];
    }
    int b = bh >> 2, h = bh & 3;
    int gs = ((b << 10) + n) * HO + h * Oo + o;
    float si = s_in[gs], ci = c_in[gs];
    float coup = ci * js - si * jc;
    float np = ph[gs] + DT_F * (omega[h * Oo + o] + (*cs_ptr) * coup);
    float v = np + PI_F;
    np = v - floorf(v * INV_2PI_F) * TWO_PI_F - PI_F;
    ph[gs] = np;
    float sn, cn;
    sincosf(np, &sn, &cn);
    s_out[gs] = sn;
    c_out[gs] = cn;
    int jp = n >> 1, jb = n & 1;
    int base2 = ((bh << 9) + jp) * 32;
    sch_out[base2 + o * 2 + jb] = __float2bfloat16_rn(sn);
    sch_out[base2 + 16 + o * 2 + jb] = __float2bfloat16_rn(cn);
}

// ---------------------------------------------------------------------------
// Final small GEMM: out = C @ Wo^T + bo, K=32.
// ---------------------------------------------------------------------------
__global__ void gemm_out(const float* __restrict__ X, const float* __restrict__ W,
                         const float* __restrict__ bias, float* __restrict__ out) {
    __shared__ float As[64][33];
    __shared__ float Ws[64][33];
    int m0 = blockIdx.x * 64, n0 = blockIdx.y * 64;
    int tid = threadIdx.x;
    int tx = tid & 15, ty = tid >> 4;
    float acc[4][4] = {};
    for (int li = tid; li < 64 * 32; li += 256) {
        int r = li >> 5, c = li & 31;
        As[r][c] = X[(size_t)(m0 + r) * HO + c];
        Ws[r][c] = W[(size_t)(n0 + r) * HO + c];
    }
    __syncthreads();
#pragma unroll
    for (int kk = 0; kk < 32; kk++) {
        float a[4], bb[4];
#pragma unroll
        for (int i = 0; i < 4; i++) a[i] = As[ty * 4 + i][kk];
#pragma unroll
        for (int j = 0; j < 4; j++) bb[j] = Ws[tx * 4 + j][kk];
#pragma unroll
        for (int i = 0; i < 4; i++)
#pragma unroll
            for (int j = 0; j < 4; j++)
                acc[i][j] = fmaf(a[i], bb[j], acc[i][j]);
    }
#pragma unroll
    for (int i = 0; i < 4; i++) {
        int m = m0 + ty * 4 + i;
#pragma unroll
        for (int j = 0; j < 4; j++) {
            int n = n0 + tx * 4 + j;
            out[(size_t)m * Dd + n] = acc[i][j] + bias[n];
        }
    }
}

// ---------------------------------------------------------------------------
extern "C" void kernel_launch(void* const* d_in, const int* in_sizes, int n_in,
                              void* d_out, int out_size) {
    const float* x     = (const float*)d_in[0];
    const float* Wq    = (const float*)d_in[1];
    const float* Wk    = (const float*)d_in[2];
    const float* Wp    = (const float*)d_in[3];
    const float* bp    = (const float*)d_in[4];
    const float* Wo    = (const float*)d_in[5];
    const float* bo    = (const float*)d_in[6];
    const float* omega = (const float*)d_in[7];
    const float* cs    = (const float*)d_in[8];
    float* out = (float*)d_out;

    float *q, *k, *ph, *s0, *s1, *c0, *c1, *J, *pD;
    __nv_bfloat16 *sch0, *sch1, *Jh;
    cudaGetSymbolAddress((void**)&q,    g_q);
    cudaGetSymbolAddress((void**)&k,    g_k);
    cudaGetSymbolAddress((void**)&ph,   g_ph);
    cudaGetSymbolAddress((void**)&s0,   g_s0);
    cudaGetSymbolAddress((void**)&s1,   g_s1);
    cudaGetSymbolAddress((void**)&c0,   g_c0);
    cudaGetSymbolAddress((void**)&c1,   g_c1);
    cudaGetSymbolAddress((void**)&sch0, g_sch0);
    cudaGetSymbolAddress((void**)&sch1, g_sch1);
    cudaGetSymbolAddress((void**)&J,    g_J);
    cudaGetSymbolAddress((void**)&Jh,   g_Jh);
    cudaGetSymbolAddress((void**)&pD,   g_pD);

    dim3 blk(256);
    // fused projections (q, k, ph + sincos, fp32 + bf16 layouts)
    proj_kernel<<<dim3(Bb * Nn / 64, 9), blk>>>(x, Wq, Wk, Wp, bp, q, k, ph, s0, c0, sch0);
    // attention: fp32 scores -> softmax -> bf16 J
    size_t smem_sc = (size_t)2 * 64 * SP * sizeof(float);
    cudaFuncSetAttribute(scores_kernel, cudaFuncAttributeMaxDynamicSharedMemorySize, (int)smem_sc);
    scores_kernel<<<dim3(Nn / 128, Nn / 128, Bb * Hh), blk, smem_sc>>>(q, k, J);
    softmax_kernel<<<Bb * Hh * Nn, blk>>>(J, Jh);
    // 5 oscillator steps: bf16 tensor-core matvec partials + reduce/update
    float* sbuf[2] = {s0, s1};
    float* cbuf[2] = {c0, c1};
    __nv_bfloat16* scbuf[2] = {sch0, sch1};
    for (int t = 0; t < NSTEPS; t++) {
        step_mma<<<dim3(Nn / 128, NKC, Bb * Hh), blk>>>(Jh, scbuf[t & 1], pD);
        step_update<<<GTOT / 256, blk>>>(
            pD, ph, sbuf[t & 1], cbuf[t & 1],
            sbuf[(t + 1) & 1], cbuf[(t + 1) & 1], scbuf[(t + 1) & 1],
            omega, cs);
    }
    // output: out = cos(final phases) @ Wo^T + bo
    const float* cfin = cbuf[NSTEPS & 1];
    gemm_out<<<dim3(Bb * Nn / 64, Dd / 64), blk>>>(cfin, Wo, bo, out);
}

// round 13
// speedup vs baseline: 2.8977x; 1.2436x over previous
#include <cuda_runtime.h>
#include <cuda_bf16.h>
#include <math.h>

#define Bb 2
#define Nn 1024
#define Dd 256
#define Hh 4
#define Oo 8
#define HO 32
#define DKK 64
#define NSTEPS 5
#define DT_F 0.1f
#define PI_F 3.14159265358979323846f
#define TWO_PI_F 6.28318530717958647692f
#define INV_2PI_F 0.15915494309189533577f

#define GTOT (Bb * Nn * HO)   // 65536
#define NKC 8                 // k-chunks for step mma (K=1024 -> 128 each)
#define JROW 72               // bf16 J-tile row stride (36 words, conflict-free)
#define SCW 24                // sc smem words per j-pair (conflict-free pad)
#define SSTR 1032             // fused-attn score smem row stride (floats)
#define KSTR 68               // fused-attn q/k smem row stride (floats)

typedef unsigned long long ull;
typedef unsigned int uint;

// Packed fp32x2 FMA (bit-identical to two scalar FFMAs).
#define FMA2(d, a, b) \
    asm("fma.rn.f32x2 %0, %1, %2, %0;" : "+l"(d) : "l"(a), "l"(b))
#define PACK2(d, x) \
    asm("mov.b64 %0, {%1, %1};" : "=l"(d) : "r"(__float_as_uint(x)))
#define UNPK2(lo, hi, v) \
    asm("mov.b64 {%0, %1}, %2;" : "=f"(lo), "=f"(hi) : "l"(v))

// pack two f32 -> bf16x2 (lo in low 16 bits)
__device__ __forceinline__ uint bf16x2(float lo, float hi) {
    uint r;
    asm("cvt.rn.bf16x2.f32 %0, %1, %2;" : "=r"(r) : "f"(hi), "f"(lo));
    return r;
}

// tf32 round-to-nearest
__device__ __forceinline__ float tf32r(float x) {
    uint u;
    asm("cvt.rna.tf32.f32 %0, %1;" : "=r"(u) : "f"(x));
    return __uint_as_float(u);
}

// m16n8k16 bf16 mma, fp32 accumulate
#define MMA_BF16(d, a0, a1, a2, a3, b0, b1) \
    asm("mma.sync.aligned.m16n8k16.row.col.f32.bf16.bf16.f32 " \
        "{%0,%1,%2,%3}, {%4,%5,%6,%7}, {%8,%9}, {%0,%1,%2,%3};" \
        : "+f"(d[0]), "+f"(d[1]), "+f"(d[2]), "+f"(d[3]) \
        : "r"(a0), "r"(a1), "r"(a2), "r"(a3), "r"(b0), "r"(b1))

// m16n8k8 tf32 mma, fp32 accumulate
#define MMA_TF32(d, a0, a1, a2, a3, b0, b1) \
    asm("mma.sync.aligned.m16n8k8.row.col.f32.tf32.tf32.f32 " \
        "{%0,%1,%2,%3}, {%4,%5,%6,%7}, {%8,%9}, {%0,%1,%2,%3};" \
        : "+f"(d[0]), "+f"(d[1]), "+f"(d[2]), "+f"(d[3]) \
        : "r"(a0), "r"(a1), "r"(a2), "r"(a3), "r"(b0), "r"(b1))

// cp.async helpers
#define CP16(dst_u32, src_ptr) \
    asm volatile("cp.async.cg.shared.global [%0], [%1], 16;" \
                 :: "r"(dst_u32), "l"(src_ptr))
#define CP_COMMIT() asm volatile("cp.async.commit_group;")
#define CP_WAIT(n)  asm volatile("cp.async.wait_group %0;" :: "n"(n))

// Scratch (no cudaMalloc allowed)
__device__ float g_q[Bb * Nn * Dd];
__device__ float g_k[Bb * Nn * Dd];
__device__ float g_ph[GTOT];
__device__ float g_s0[GTOT];
__device__ float g_s1[GTOT];
__device__ float g_c0[GTOT];
__device__ float g_c1[GTOT];
__device__ __nv_bfloat16 g_sch0[Bb * Hh * Nn * 16];  // [bh][jp][o16][2] sin|cos
__device__ __nv_bfloat16 g_sch1[Bb * Hh * Nn * 16];
__device__ float g_pD[NKC * Bb * Hh * Nn * 16];            // 4 MB partials
__device__ __nv_bfloat16 g_Jh[(size_t)Bb * Hh * Nn * Nn];  // 16 MB bf16 J

// ---------------------------------------------------------------------------
// Fused projection kernel: q = 0.125*x@Wq^T (tf32), k = x@Wk^T (tf32),
// ph = x@Wp^T + bp (+sincos, fp32 + bf16 layouts).
// ---------------------------------------------------------------------------
__global__ __launch_bounds__(256, 2) void proj_kernel(
    const float* __restrict__ x,
    const float* __restrict__ Wq, const float* __restrict__ Wk,
    const float* __restrict__ Wp, const float* __restrict__ bp,
    float* __restrict__ q, float* __restrict__ k,
    float* __restrict__ ph, float* __restrict__ s0, float* __restrict__ c0,
    __nv_bfloat16* __restrict__ sch0) {
    __shared__ __align__(16) float As[64][68];   // [kk][m]
    __shared__ __align__(16) float Bs[64][68];   // [kk][n]
    int m0 = blockIdx.x * 64;
    int y = blockIdx.y;
    const float* W;
    int n0, Nout;
    if (y < 4)      { W = Wq; n0 = y * 64;       Nout = Dd; }
    else if (y < 8) { W = Wk; n0 = (y - 4) * 64; Nout = Dd; }
    else            { W = Wp; n0 = 0;            Nout = HO; }
    int tid = threadIdx.x;
    int tx = tid & 15, ty = tid >> 4;
    ull acc2[4][2] = {};
    for (int kt = 0; kt < Dd; kt += 64) {
        for (int t = tid; t < 64 * 16; t += 256) {
            int r = t >> 4, c4 = (t & 15) * 4;
            float4 va = *(const float4*)&x[(size_t)(m0 + r) * Dd + kt + c4];
            As[c4 + 0][r] = va.x; As[c4 + 1][r] = va.y;
            As[c4 + 2][r] = va.z; As[c4 + 3][r] = va.w;
            float4 vb = make_float4(0.f, 0.f, 0.f, 0.f);
            if (n0 + r < Nout)
                vb = *(const float4*)&W[(size_t)(n0 + r) * Dd + kt + c4];
            Bs[c4 + 0][r] = vb.x; Bs[c4 + 1][r] = vb.y;
            Bs[c4 + 2][r] = vb.z; Bs[c4 + 3][r] = vb.w;
        }
        __syncthreads();
#pragma unroll
        for (int kk = 0; kk < 64; kk++) {
            float4 a = *(const float4*)&As[kk][ty * 4];
            ulonglong2 bv = *(const ulonglong2*)&Bs[kk][tx * 4];
            ull aa0, aa1, aa2, aa3;
            PACK2(aa0, a.x); PACK2(aa1, a.y); PACK2(aa2, a.z); PACK2(aa3, a.w);
            FMA2(acc2[0][0], aa0, bv.x); FMA2(acc2[0][1], aa0, bv.y);
            FMA2(acc2[1][0], aa1, bv.x); FMA2(acc2[1][1], aa1, bv.y);
            FMA2(acc2[2][0], aa2, bv.x); FMA2(acc2[2][1], aa2, bv.y);
            FMA2(acc2[3][0], aa3, bv.x); FMA2(acc2[3][1], aa3, bv.y);
        }
        __syncthreads();
    }
    float acc[4][4];
#pragma unroll
    for (int i = 0; i < 4; i++) {
        UNPK2(acc[i][0], acc[i][1], acc2[i][0]);
        UNPK2(acc[i][2], acc[i][3], acc2[i][1]);
    }
    if (y < 4) {
        // q: pre-scale by 1/8 (exact) and round to tf32 for the scores MMA
#pragma unroll
        for (int i = 0; i < 4; i++) {
            int m = m0 + ty * 4 + i;
            float4 v = make_float4(tf32r(0.125f * acc[i][0]), tf32r(0.125f * acc[i][1]),
                                   tf32r(0.125f * acc[i][2]), tf32r(0.125f * acc[i][3]));
            *(float4*)&q[(size_t)m * Dd + n0 + tx * 4] = v;
        }
    } else if (y < 8) {
#pragma unroll
        for (int i = 0; i < 4; i++) {
            int m = m0 + ty * 4 + i;
            float4 v = make_float4(tf32r(acc[i][0]), tf32r(acc[i][1]),
                                   tf32r(acc[i][2]), tf32r(acc[i][3]));
            *(float4*)&k[(size_t)m * Dd + n0 + tx * 4] = v;
        }
    } else if (tx * 4 < HO) {
#pragma unroll
        for (int i = 0; i < 4; i++) {
            int m = m0 + ty * 4 + i;
            int j = m & 1023, b = m >> 10;
            int jp = j >> 1, jb = j & 1;
#pragma unroll
            for (int jj = 0; jj < 4; jj++) {
                int n = tx * 4 + jj;
                float p = acc[i][jj] + bp[n];
                int g = m * HO + n;
                ph[g] = p;
                float sn, cn;
                sincosf(p, &sn, &cn);
                s0[g] = sn;
                c0[g] = cn;
                int bh = b * 4 + (n >> 3), o = n & 7;
                int base = ((bh << 9) + jp) * 32;
                sch0[base + o * 2 + jb] = __float2bfloat16_rn(sn);
                sch0[base + 16 + o * 2 + jb] = __float2bfloat16_rn(cn);
            }
        }
    }
}

// ---------------------------------------------------------------------------
// Fused attention: scores (tf32 MMA) + row softmax + bf16 J write.
// Grid (32 i-strips of 32 rows, 8 bh), 256 threads, 1 CTA/SM (~206 KB smem).
// K streamed in 8 chunks of 128 j via cp.async double buffer.
// Warp w: m-half = w>>2 (16 rows), j-block = (w&3)*32 within each chunk.
// Scores accumulate into smem [32][SSTR]; softmax in-smem; Jh out.
// ---------------------------------------------------------------------------
__global__ __launch_bounds__(256, 1) void attn_kernel(
    const float* __restrict__ q, const float* __restrict__ k,
    __nv_bfloat16* __restrict__ Jh) {
    extern __shared__ __align__(16) float dsm[];
    float* Sc = dsm;                      // 32*SSTR = 33024 floats (132 KB)
    float* Qs = Sc + 32 * SSTR;           // 32*KSTR = 2176 floats
    float* Ks = Qs + 32 * KSTR;           // 2*128*KSTR = 17408 floats
    int i0 = blockIdx.x * 32;
    int bh = blockIdx.y;
    int b = bh >> 2, h = bh & 3;
    int tid = threadIdx.x;
    // stage q strip (already 0.125-scaled + tf32-rounded)
#pragma unroll
    for (int it = 0; it < 2; it++) {
        int idx = tid + it * 256;
        int r = idx >> 4, c4 = (idx & 15) * 4;
        float4 v = *(const float4*)&q[(size_t)((b << 10) + i0 + r) * Dd + h * DKK + c4];
        *(float4*)&Qs[r * KSTR + c4] = v;
    }
    // prologue: k chunk 0
    const float* kbase = &k[(size_t)(b << 10) * Dd + h * DKK];
    int ldr = tid >> 4, ldc = (tid & 15) * 4;   // 16 rows per pass? (idx>>4 up to 127)
#pragma unroll
    for (int it = 0; it < 8; it++) {
        int idx = tid + it * 256;
        int jr = idx >> 4, c4 = (idx & 15) * 4;
        uint dst = (uint)__cvta_generic_to_shared(&Ks[jr * KSTR + c4]);
        CP16(dst, &kbase[(size_t)jr * Dd + c4]);
    }
    CP_COMMIT();

    int w = tid >> 5, lane = tid & 31;
    int gid = lane >> 2, tig = lane & 3;
    int m0 = (w >> 2) * 16, jq = (w & 3) * 32;
    for (int c = 0; c < 8; c++) {
        if (c < 7) {
            float* bufn = &Ks[((c + 1) & 1) * 128 * KSTR];
#pragma unroll
            for (int it = 0; it < 8; it++) {
                int idx = tid + it * 256;
                int jr = idx >> 4, c4 = (idx & 15) * 4;
                uint dst = (uint)__cvta_generic_to_shared(&bufn[jr * KSTR + c4]);
                CP16(dst, &kbase[(size_t)(((c + 1) << 7) + jr) * Dd + c4]);
            }
            CP_COMMIT();
            CP_WAIT(1);
        } else {
            CP_WAIT(0);
        }
        __syncthreads();
        const float* buf = &Ks[(c & 1) * 128 * KSTR];
        float d0[4] = {}, d1[4] = {}, d2[4] = {}, d3[4] = {};
#pragma unroll
        for (int kk = 0; kk < 8; kk++) {
            int kb8 = kk * 8;
            uint a0 = __float_as_uint(Qs[(m0 + gid) * KSTR + kb8 + tig]);
            uint a1 = __float_as_uint(Qs[(m0 + gid + 8) * KSTR + kb8 + tig]);
            uint a2 = __float_as_uint(Qs[(m0 + gid) * KSTR + kb8 + tig + 4]);
            uint a3 = __float_as_uint(Qs[(m0 + gid + 8) * KSTR + kb8 + tig + 4]);
            uint b0, b1;
            b0 = __float_as_uint(buf[(jq + 0 + gid) * KSTR + kb8 + tig]);
            b1 = __float_as_uint(buf[(jq + 0 + gid) * KSTR + kb8 + tig + 4]);
            MMA_TF32(d0, a0, a1, a2, a3, b0, b1);
            b0 = __float_as_uint(buf[(jq + 8 + gid) * KSTR + kb8 + tig]);
            b1 = __float_as_uint(buf[(jq + 8 + gid) * KSTR + kb8 + tig + 4]);
            MMA_TF32(d1, a0, a1, a2, a3, b0, b1);
            b0 = __float_as_uint(buf[(jq + 16 + gid) * KSTR + kb8 + tig]);
            b1 = __float_as_uint(buf[(jq + 16 + gid) * KSTR + kb8 + tig + 4]);
            MMA_TF32(d2, a0, a1, a2, a3, b0, b1);
            b0 = __float_as_uint(buf[(jq + 24 + gid) * KSTR + kb8 + tig]);
            b1 = __float_as_uint(buf[(jq + 24 + gid) * KSTR + kb8 + tig + 4]);
            MMA_TF32(d3, a0, a1, a2, a3, b0, b1);
        }
        // write score tile to smem
        int cc = c * 128 + jq + tig * 2;
        *(float2*)&Sc[(m0 + gid) * SSTR + cc]          = make_float2(d0[0], d0[1]);
        *(float2*)&Sc[(m0 + gid + 8) * SSTR + cc]      = make_float2(d0[2], d0[3]);
        *(float2*)&Sc[(m0 + gid) * SSTR + cc + 8]      = make_float2(d1[0], d1[1]);
        *(float2*)&Sc[(m0 + gid + 8) * SSTR + cc + 8]  = make_float2(d1[2], d1[3]);
        *(float2*)&Sc[(m0 + gid) * SSTR + cc + 16]     = make_float2(d2[0], d2[1]);
        *(float2*)&Sc[(m0 + gid + 8) * SSTR + cc + 16] = make_float2(d2[2], d2[3]);
        *(float2*)&Sc[(m0 + gid) * SSTR + cc + 24]     = make_float2(d3[0], d3[1]);
        *(float2*)&Sc[(m0 + gid + 8) * SSTR + cc + 24] = make_float2(d3[2], d3[3]);
        __syncthreads();
    }
    // in-smem softmax: 8 threads per row, 128 elements each
    int row = tid >> 3, l8 = tid & 7;
    float* Sr = &Sc[row * SSTR];
    float mx = -1e30f;
#pragma unroll
    for (int it = 0; it < 32; it++) {
        float4 v = *(const float4*)&Sr[l8 * 4 + it * 32];
        mx = fmaxf(mx, fmaxf(fmaxf(v.x, v.y), fmaxf(v.z, v.w)));
    }
#pragma unroll
    for (int off = 1; off < 8; off <<= 1)
        mx = fmaxf(mx, __shfl_xor_sync(0xffffffffu, mx, off));
    float sum = 0.f;
#pragma unroll
    for (int it = 0; it < 32; it++) {
        float4 v = *(const float4*)&Sr[l8 * 4 + it * 32];
        v.x = __expf(v.x - mx); v.y = __expf(v.y - mx);
        v.z = __expf(v.z - mx); v.w = __expf(v.w - mx);
        sum += (v.x + v.y) + (v.z + v.w);
        *(float4*)&Sr[l8 * 4 + it * 32] = v;
    }
#pragma unroll
    for (int off = 1; off < 8; off <<= 1)
        sum += __shfl_xor_sync(0xffffffffu, sum, off);
    float inv = 1.f / sum;
    __nv_bfloat16* Jr = &Jh[((size_t)(bh << 10) + i0 + row) * Nn];
#pragma unroll
    for (int it = 0; it < 32; it++) {
        float4 v = *(const float4*)&Sr[l8 * 4 + it * 32];
        uint2 pk;
        pk.x = bf16x2(v.x * inv, v.y * inv);
        pk.y = bf16x2(v.z * inv, v.w * inv);
        *(uint2*)&Jr[l8 * 4 + it * 32] = pk;
    }
}

// ---------------------------------------------------------------------------
// Step matvec: bf16 m16n8k16 MMA over bf16 J, cp.async double-buffered.
// ---------------------------------------------------------------------------
__global__ __launch_bounds__(256, 5) void step_mma(
    const __nv_bfloat16* __restrict__ Jh, const __nv_bfloat16* __restrict__ sch,
    float* __restrict__ pD) {
    __shared__ __align__(16) __nv_bfloat16 Jt[2][128 * JROW];  // 2 x 18 KB
    __shared__ __align__(16) float scs[64 * SCW];              // 6 KB
    int i0 = blockIdx.x * 128;
    int k0 = blockIdx.y * 128;
    int bh = blockIdx.z;
    int tid = threadIdx.x;
    {
        const uint* src = (const uint*)&sch[(((bh << 9) + (k0 >> 1)) << 5)];
#pragma unroll
        for (int it = 0; it < 4; it++) {
            int w = tid + it * 256;
            scs[(w >> 4) * SCW + (w & 15)] = __uint_as_float(src[w]);
        }
    }
    const __nv_bfloat16* Jbase = &Jh[((size_t)(bh << 10) + i0) * Nn + k0];
    int lr = tid >> 3, lc = (tid & 7) * 8;
#pragma unroll
    for (int it = 0; it < 4; it++) {
        int r = lr + it * 32;
        uint dst = (uint)__cvta_generic_to_shared(&Jt[0][r * JROW + lc]);
        CP16(dst, &Jbase[(size_t)r * Nn + lc]);
    }
    CP_COMMIT();

    int w = tid >> 5, lane = tid & 31;
    int gid = lane >> 2, tig = lane & 3;
    int r0 = w * 16;
    float ds[4] = {}, dc[4] = {};
#pragma unroll
    for (int sub = 0; sub < 2; sub++) {
        if (sub == 0) {
#pragma unroll
            for (int it = 0; it < 4; it++) {
                int r = lr + it * 32;
                uint dst = (uint)__cvta_generic_to_shared(&Jt[1][r * JROW + lc]);
                CP16(dst, &Jbase[(size_t)r * Nn + 64 + lc]);
            }
            CP_COMMIT();
            CP_WAIT(1);
        } else {
            CP_WAIT(0);
        }
        __syncthreads();
        const uint* bw = (const uint*)Jt[sub];
#pragma unroll
        for (int kk = 0; kk < 4; kk++) {
            int aw = (r0 + gid) * (JROW / 2) + kk * 8 + tig;
            uint a0 = bw[aw];
            uint a1 = bw[aw + 8 * (JROW / 2)];
            uint a2 = bw[aw + 4];
            uint a3 = bw[aw + 8 * (JROW / 2) + 4];
            int jp = sub * 32 + kk * 8 + tig;
            uint b0s = __float_as_uint(scs[jp * SCW + gid]);
            uint b1s = __float_as_uint(scs[(jp + 4) * SCW + gid]);
            uint b0c = __float_as_uint(scs[jp * SCW + 8 + gid]);
            uint b1c = __float_as_uint(scs[(jp + 4) * SCW + 8 + gid]);
            MMA_BF16(ds, a0, a1, a2, a3, b0s, b1s);
            MMA_BF16(dc, a0, a1, a2, a3, b0c, b1c);
        }
        __syncthreads();
    }
    size_t base = ((size_t)blockIdx.y * (Bb * Hh * Nn) + (bh << 10) + i0 + w * 16) * 16;
    int o2 = tig * 2;
    *(float2*)&pD[base + (size_t)gid * 16 + o2]           = make_float2(ds[0], ds[1]);
    *(float2*)&pD[base + (size_t)gid * 16 + 8 + o2]       = make_float2(dc[0], dc[1]);
    *(float2*)&pD[base + (size_t)(gid + 8) * 16 + o2]     = make_float2(ds[2], ds[3]);
    *(float2*)&pD[base + (size_t)(gid + 8) * 16 + 8 + o2] = make_float2(dc[2], dc[3]);
}

// ---------------------------------------------------------------------------
// Step update: reduce NKC partials, phase update + wrap + sincos.
// ---------------------------------------------------------------------------
__global__ void step_update(const float* __restrict__ pD, float* __restrict__ ph,
                            const float* __restrict__ s_in, const float* __restrict__ c_in,
                            float* __restrict__ s_out, float* __restrict__ c_out,
                            __nv_bfloat16* __restrict__ sch_out,
                            const float* __restrict__ omega,
                            const float* __restrict__ cs_ptr) {
    int g = blockIdx.x * 256 + threadIdx.x;   // (bh, n, o)
    int bh = g >> 13, rem = g & 8191, n = rem >> 3, o = rem & 7;
    float js = 0.f, jc = 0.f;
#pragma unroll
    for (int kc = 0; kc < NKC; kc++) {
        size_t base = ((size_t)kc * (Bb * Hh * Nn) + (bh << 10) + n) * 16;
        js += pD[base + o];
        jc += pD[base + 8 + o];
    }
    int b = bh >> 2, h = bh & 3;
    int gs = ((b << 10) + n) * HO + h * Oo + o;
    float si = s_in[gs], ci = c_in[gs];
    float coup = ci * js - si * jc;
    float np = ph[gs] + DT_F * (omega[h * Oo + o] + (*cs_ptr) * coup);
    float v = np + PI_F;
    np = v - floorf(v * INV_2PI_F) * TWO_PI_F - PI_F;
    ph[gs] = np;
    float sn, cn;
    sincosf(np, &sn, &cn);
    s_out[gs] = sn;
    c_out[gs] = cn;
    int jp = n >> 1, jb = n & 1;
    int base2 = ((bh << 9) + jp) * 32;
    sch_out[base2 + o * 2 + jb] = __float2bfloat16_rn(sn);
    sch_out[base2 + 16 + o * 2 + jb] = __float2bfloat16_rn(cn);
}

// ---------------------------------------------------------------------------
// Final small GEMM: out = C @ Wo^T + bo, K=32.
// ---------------------------------------------------------------------------
__global__ void gemm_out(const float* __restrict__ X, const float* __restrict__ W,
                         const float* __restrict__ bias, float* __restrict__ out) {
    __shared__ float As[64][33];
    __shared__ float Ws[64][33];
    int m0 = blockIdx.x * 64, n0 = blockIdx.y * 64;
    int tid = threadIdx.x;
    int tx = tid & 15, ty = tid >> 4;
    float acc[4][4] = {};
    for (int li = tid; li < 64 * 32; li += 256) {
        int r = li >> 5, c = li & 31;
        As[r][c] = X[(size_t)(m0 + r) * HO + c];
        Ws[r][c] = W[(size_t)(n0 + r) * HO + c];
    }
    __syncthreads();
#pragma unroll
    for (int kk = 0; kk < 32; kk++) {
        float a[4], bb[4];
#pragma unroll
        for (int i = 0; i < 4; i++) a[i] = As[ty * 4 + i][kk];
#pragma unroll
        for (int j = 0; j < 4; j++) bb[j] = Ws[tx * 4 + j][kk];
#pragma unroll
        for (int i = 0; i < 4; i++)
#pragma unroll
            for (int j = 0; j < 4; j++)
                acc[i][j] = fmaf(a[i], bb[j], acc[i][j]);
    }
#pragma unroll
    for (int i = 0; i < 4; i++) {
        int m = m0 + ty * 4 + i;
#pragma unroll
        for (int j = 0; j < 4; j++) {
            int n = n0 + tx * 4 + j;
            out[(size_t)m * Dd + n] = acc[i][j] + bias[n];
        }
    }
}

// ---------------------------------------------------------------------------
extern "C" void kernel_launch(void* const* d_in, const int* in_sizes, int n_in,
                              void* d_out, int out_size) {
    const float* x     = (const float*)d_in[0];
    const float* Wq    = (const float*)d_in[1];
    const float* Wk    = (const float*)d_in[2];
    const float* Wp    = (const float*)d_in[3];
    const float* bp    = (const float*)d_in[4];
    const float* Wo    = (const float*)d_in[5];
    const float* bo    = (const float*)d_in[6];
    const float* omega = (const float*)d_in[7];
    const float* cs    = (const float*)d_in[8];
    float* out = (float*)d_out;

    float *q, *k, *ph, *s0, *s1, *c0, *c1, *pD;
    __nv_bfloat16 *sch0, *sch1, *Jh;
    cudaGetSymbolAddress((void**)&q,    g_q);
    cudaGetSymbolAddress((void**)&k,    g_k);
    cudaGetSymbolAddress((void**)&ph,   g_ph);
    cudaGetSymbolAddress((void**)&s0,   g_s0);
    cudaGetSymbolAddress((void**)&s1,   g_s1);
    cudaGetSymbolAddress((void**)&c0,   g_c0);
    cudaGetSymbolAddress((void**)&c1,   g_c1);
    cudaGetSymbolAddress((void**)&sch0, g_sch0);
    cudaGetSymbolAddress((void**)&sch1, g_sch1);
    cudaGetSymbolAddress((void**)&Jh,   g_Jh);
    cudaGetSymbolAddress((void**)&pD,   g_pD);

    dim3 blk(256);
    // fused projections (q, k tf32; ph + sincos, fp32 + bf16 layouts)
    proj_kernel<<<dim3(Bb * Nn / 64, 9), blk>>>(x, Wq, Wk, Wp, bp, q, k, ph, s0, c0, sch0);
    // fused scores + softmax -> bf16 J
    size_t smem_at = (size_t)(32 * SSTR + 32 * KSTR + 2 * 128 * KSTR) * sizeof(float);
    cudaFuncSetAttribute(attn_kernel, cudaFuncAttributeMaxDynamicSharedMemorySize, (int)smem_at);
    attn_kernel<<<dim3(Nn / 32, Bb * Hh), blk, smem_at>>>(q, k, Jh);
    // 5 oscillator steps: bf16 tensor-core matvec partials + reduce/update
    float* sbuf[2] = {s0, s1};
    float* cbuf[2] = {c0, c1};
    __nv_bfloat16* scbuf[2] = {sch0, sch1};
    for (int t = 0; t < NSTEPS; t++) {
        step_mma<<<dim3(Nn / 128, NKC, Bb * Hh), blk>>>(Jh, scbuf[t & 1], pD);
        step_update<<<GTOT / 256, blk>>>(
            pD, ph, sbuf[t & 1], cbuf[t & 1],
            sbuf[(t + 1) & 1], cbuf[(t + 1) & 1], scbuf[(t + 1) & 1],
            omega, cs);
    }
    // output: out = cos(final phases) @ Wo^T + bo
    const float* cfin = cbuf[NSTEPS & 1];
    gemm_out<<<dim3(Bb * Nn / 64, Dd / 64), blk>>>(cfin, Wo, bo, out);
}

// round 14
// speedup vs baseline: 3.0307x; 1.0459x over previous
#include <cuda_runtime.h>
#include <cuda_bf16.h>
#include <math.h>

#define Bb 2
#define Nn 1024
#define Dd 256
#define Hh 4
#define Oo 8
#define HO 32
#define DKK 64
#define NSTEPS 5
#define DT_F 0.1f
#define PI_F 3.14159265358979323846f
#define TWO_PI_F 6.28318530717958647692f
#define INV_2PI_F 0.15915494309189533577f

#define GTOT (Bb * Nn * HO)   // 65536
#define SSTR 1032             // fused-attn score smem row stride (floats)
#define KSTR 68               // fused-attn q/k smem row stride (floats)
#define JW 516                // step J-tile row stride in 32-bit words (==4 mod 32)

typedef unsigned long long ull;
typedef unsigned int uint;

// Packed fp32x2 FMA (bit-identical to two scalar FFMAs).
#define FMA2(d, a, b) \
    asm("fma.rn.f32x2 %0, %1, %2, %0;" : "+l"(d) : "l"(a), "l"(b))
#define PACK2(d, x) \
    asm("mov.b64 %0, {%1, %1};" : "=l"(d) : "r"(__float_as_uint(x)))
#define UNPK2(lo, hi, v) \
    asm("mov.b64 {%0, %1}, %2;" : "=f"(lo), "=f"(hi) : "l"(v))

// pack two f32 -> bf16x2 (lo in low 16 bits)
__device__ __forceinline__ uint bf16x2(float lo, float hi) {
    uint r;
    asm("cvt.rn.bf16x2.f32 %0, %1, %2;" : "=r"(r) : "f"(hi), "f"(lo));
    return r;
}

// tf32 round-to-nearest
__device__ __forceinline__ float tf32r(float x) {
    uint u;
    asm("cvt.rna.tf32.f32 %0, %1;" : "=r"(u) : "f"(x));
    return __uint_as_float(u);
}

// m16n8k16 bf16 mma, fp32 accumulate
#define MMA_BF16(d, a0, a1, a2, a3, b0, b1) \
    asm("mma.sync.aligned.m16n8k16.row.col.f32.bf16.bf16.f32 " \
        "{%0,%1,%2,%3}, {%4,%5,%6,%7}, {%8,%9}, {%0,%1,%2,%3};" \
        : "+f"(d[0]), "+f"(d[1]), "+f"(d[2]), "+f"(d[3]) \
        : "r"(a0), "r"(a1), "r"(a2), "r"(a3), "r"(b0), "r"(b1))

// m16n8k8 tf32 mma, fp32 accumulate
#define MMA_TF32(d, a0, a1, a2, a3, b0, b1) \
    asm("mma.sync.aligned.m16n8k8.row.col.f32.tf32.tf32.f32 " \
        "{%0,%1,%2,%3}, {%4,%5,%6,%7}, {%8,%9}, {%0,%1,%2,%3};" \
        : "+f"(d[0]), "+f"(d[1]), "+f"(d[2]), "+f"(d[3]) \
        : "r"(a0), "r"(a1), "r"(a2), "r"(a3), "r"(b0), "r"(b1))

// cp.async helpers
#define CP16(dst_u32, src_ptr) \
    asm volatile("cp.async.cg.shared.global [%0], [%1], 16;" \
                 :: "r"(dst_u32), "l"(src_ptr))
#define CP_COMMIT() asm volatile("cp.async.commit_group;")
#define CP_WAIT(n)  asm volatile("cp.async.wait_group %0;" :: "n"(n))

// Scratch (no cudaMalloc allowed)
__device__ float g_q[Bb * Nn * Dd];
__device__ float g_k[Bb * Nn * Dd];
__device__ float g_ph[GTOT];
__device__ float g_s0[GTOT];
__device__ float g_s1[GTOT];
__device__ float g_c0[GTOT];
__device__ float g_c1[GTOT];
__device__ __nv_bfloat16 g_sch0[Bb * Hh * Nn * 16];  // [bh][jp][s0..7|c0..7]x2
__device__ __nv_bfloat16 g_sch1[Bb * Hh * Nn * 16];
__device__ __nv_bfloat16 g_Jh[(size_t)Bb * Hh * Nn * Nn];  // 16 MB bf16 J

// ---------------------------------------------------------------------------
// Fused projection kernel: q = 0.125*x@Wq^T (tf32), k = x@Wk^T (tf32),
// ph = x@Wp^T + bp (+sincos, fp32 + bf16 layouts).
// ---------------------------------------------------------------------------
__global__ __launch_bounds__(256, 2) void proj_kernel(
    const float* __restrict__ x,
    const float* __restrict__ Wq, const float* __restrict__ Wk,
    const float* __restrict__ Wp, const float* __restrict__ bp,
    float* __restrict__ q, float* __restrict__ k,
    float* __restrict__ ph, float* __restrict__ s0, float* __restrict__ c0,
    __nv_bfloat16* __restrict__ sch0) {
    __shared__ __align__(16) float As[64][68];   // [kk][m]
    __shared__ __align__(16) float Bs[64][68];   // [kk][n]
    int m0 = blockIdx.x * 64;
    int y = blockIdx.y;
    const float* W;
    int n0, Nout;
    if (y < 4)      { W = Wq; n0 = y * 64;       Nout = Dd; }
    else if (y < 8) { W = Wk; n0 = (y - 4) * 64; Nout = Dd; }
    else            { W = Wp; n0 = 0;            Nout = HO; }
    int tid = threadIdx.x;
    int tx = tid & 15, ty = tid >> 4;
    ull acc2[4][2] = {};
    for (int kt = 0; kt < Dd; kt += 64) {
        for (int t = tid; t < 64 * 16; t += 256) {
            int r = t >> 4, c4 = (t & 15) * 4;
            float4 va = *(const float4*)&x[(size_t)(m0 + r) * Dd + kt + c4];
            As[c4 + 0][r] = va.x; As[c4 + 1][r] = va.y;
            As[c4 + 2][r] = va.z; As[c4 + 3][r] = va.w;
            float4 vb = make_float4(0.f, 0.f, 0.f, 0.f);
            if (n0 + r < Nout)
                vb = *(const float4*)&W[(size_t)(n0 + r) * Dd + kt + c4];
            Bs[c4 + 0][r] = vb.x; Bs[c4 + 1][r] = vb.y;
            Bs[c4 + 2][r] = vb.z; Bs[c4 + 3][r] = vb.w;
        }
        __syncthreads();
#pragma unroll
        for (int kk = 0; kk < 64; kk++) {
            float4 a = *(const float4*)&As[kk][ty * 4];
            ulonglong2 bv = *(const ulonglong2*)&Bs[kk][tx * 4];
            ull aa0, aa1, aa2, aa3;
            PACK2(aa0, a.x); PACK2(aa1, a.y); PACK2(aa2, a.z); PACK2(aa3, a.w);
            FMA2(acc2[0][0], aa0, bv.x); FMA2(acc2[0][1], aa0, bv.y);
            FMA2(acc2[1][0], aa1, bv.x); FMA2(acc2[1][1], aa1, bv.y);
            FMA2(acc2[2][0], aa2, bv.x); FMA2(acc2[2][1], aa2, bv.y);
            FMA2(acc2[3][0], aa3, bv.x); FMA2(acc2[3][1], aa3, bv.y);
        }
        __syncthreads();
    }
    float acc[4][4];
#pragma unroll
    for (int i = 0; i < 4; i++) {
        UNPK2(acc[i][0], acc[i][1], acc2[i][0]);
        UNPK2(acc[i][2], acc[i][3], acc2[i][1]);
    }
    if (y < 4) {
#pragma unroll
        for (int i = 0; i < 4; i++) {
            int m = m0 + ty * 4 + i;
            float4 v = make_float4(tf32r(0.125f * acc[i][0]), tf32r(0.125f * acc[i][1]),
                                   tf32r(0.125f * acc[i][2]), tf32r(0.125f * acc[i][3]));
            *(float4*)&q[(size_t)m * Dd + n0 + tx * 4] = v;
        }
    } else if (y < 8) {
#pragma unroll
        for (int i = 0; i < 4; i++) {
            int m = m0 + ty * 4 + i;
            float4 v = make_float4(tf32r(acc[i][0]), tf32r(acc[i][1]),
                                   tf32r(acc[i][2]), tf32r(acc[i][3]));
            *(float4*)&k[(size_t)m * Dd + n0 + tx * 4] = v;
        }
    } else if (tx * 4 < HO) {
#pragma unroll
        for (int i = 0; i < 4; i++) {
            int m = m0 + ty * 4 + i;
            int j = m & 1023, b = m >> 10;
            int jp = j >> 1, jb = j & 1;
#pragma unroll
            for (int jj = 0; jj < 4; jj++) {
                int n = tx * 4 + jj;
                float p = acc[i][jj] + bp[n];
                int g = m * HO + n;
                ph[g] = p;
                float sn, cn;
                sincosf(p, &sn, &cn);
                s0[g] = sn;
                c0[g] = cn;
                int bh = b * 4 + (n >> 3), o = n & 7;
                int base = ((bh << 9) + jp) * 32;
                sch0[base + o * 2 + jb] = __float2bfloat16_rn(sn);
                sch0[base + 16 + o * 2 + jb] = __float2bfloat16_rn(cn);
            }
        }
    }
}

// ---------------------------------------------------------------------------
// Fused attention: scores (tf32 MMA) + row softmax + bf16 J write.
// ---------------------------------------------------------------------------
__global__ __launch_bounds__(256, 1) void attn_kernel(
    const float* __restrict__ q, const float* __restrict__ k,
    __nv_bfloat16* __restrict__ Jh) {
    extern __shared__ __align__(16) float dsm[];
    float* Sc = dsm;                      // 32*SSTR floats
    float* Qs = Sc + 32 * SSTR;           // 32*KSTR
    float* Ks = Qs + 32 * KSTR;           // 2*128*KSTR
    int i0 = blockIdx.x * 32;
    int bh = blockIdx.y;
    int b = bh >> 2, h = bh & 3;
    int tid = threadIdx.x;
#pragma unroll
    for (int it = 0; it < 2; it++) {
        int idx = tid + it * 256;
        int r = idx >> 4, c4 = (idx & 15) * 4;
        float4 v = *(const float4*)&q[(size_t)((b << 10) + i0 + r) * Dd + h * DKK + c4];
        *(float4*)&Qs[r * KSTR + c4] = v;
    }
    const float* kbase = &k[(size_t)(b << 10) * Dd + h * DKK];
#pragma unroll
    for (int it = 0; it < 8; it++) {
        int idx = tid + it * 256;
        int jr = idx >> 4, c4 = (idx & 15) * 4;
        uint dst = (uint)__cvta_generic_to_shared(&Ks[jr * KSTR + c4]);
        CP16(dst, &kbase[(size_t)jr * Dd + c4]);
    }
    CP_COMMIT();

    int w = tid >> 5, lane = tid & 31;
    int gid = lane >> 2, tig = lane & 3;
    int m0 = (w >> 2) * 16, jq = (w & 3) * 32;
    for (int c = 0; c < 8; c++) {
        if (c < 7) {
            float* bufn = &Ks[((c + 1) & 1) * 128 * KSTR];
#pragma unroll
            for (int it = 0; it < 8; it++) {
                int idx = tid + it * 256;
                int jr = idx >> 4, c4 = (idx & 15) * 4;
                uint dst = (uint)__cvta_generic_to_shared(&bufn[jr * KSTR + c4]);
                CP16(dst, &kbase[(size_t)(((c + 1) << 7) + jr) * Dd + c4]);
            }
            CP_COMMIT();
            CP_WAIT(1);
        } else {
            CP_WAIT(0);
        }
        __syncthreads();
        const float* buf = &Ks[(c & 1) * 128 * KSTR];
        float d0[4] = {}, d1[4] = {}, d2[4] = {}, d3[4] = {};
#pragma unroll
        for (int kk = 0; kk < 8; kk++) {
            int kb8 = kk * 8;
            uint a0 = __float_as_uint(Qs[(m0 + gid) * KSTR + kb8 + tig]);
            uint a1 = __float_as_uint(Qs[(m0 + gid + 8) * KSTR + kb8 + tig]);
            uint a2 = __float_as_uint(Qs[(m0 + gid) * KSTR + kb8 + tig + 4]);
            uint a3 = __float_as_uint(Qs[(m0 + gid + 8) * KSTR + kb8 + tig + 4]);
            uint b0, b1;
            b0 = __float_as_uint(buf[(jq + 0 + gid) * KSTR + kb8 + tig]);
            b1 = __float_as_uint(buf[(jq + 0 + gid) * KSTR + kb8 + tig + 4]);
            MMA_TF32(d0, a0, a1, a2, a3, b0, b1);
            b0 = __float_as_uint(buf[(jq + 8 + gid) * KSTR + kb8 + tig]);
            b1 = __float_as_uint(buf[(jq + 8 + gid) * KSTR + kb8 + tig + 4]);
            MMA_TF32(d1, a0, a1, a2, a3, b0, b1);
            b0 = __float_as_uint(buf[(jq + 16 + gid) * KSTR + kb8 + tig]);
            b1 = __float_as_uint(buf[(jq + 16 + gid) * KSTR + kb8 + tig + 4]);
            MMA_TF32(d2, a0, a1, a2, a3, b0, b1);
            b0 = __float_as_uint(buf[(jq + 24 + gid) * KSTR + kb8 + tig]);
            b1 = __float_as_uint(buf[(jq + 24 + gid) * KSTR + kb8 + tig + 4]);
            MMA_TF32(d3, a0, a1, a2, a3, b0, b1);
        }
        int cc = c * 128 + jq + tig * 2;
        *(float2*)&Sc[(m0 + gid) * SSTR + cc]          = make_float2(d0[0], d0[1]);
        *(float2*)&Sc[(m0 + gid + 8) * SSTR + cc]      = make_float2(d0[2], d0[3]);
        *(float2*)&Sc[(m0 + gid) * SSTR + cc + 8]      = make_float2(d1[0], d1[1]);
        *(float2*)&Sc[(m0 + gid + 8) * SSTR + cc + 8]  = make_float2(d1[2], d1[3]);
        *(float2*)&Sc[(m0 + gid) * SSTR + cc + 16]     = make_float2(d2[0], d2[1]);
        *(float2*)&Sc[(m0 + gid + 8) * SSTR + cc + 16] = make_float2(d2[2], d2[3]);
        *(float2*)&Sc[(m0 + gid) * SSTR + cc + 24]     = make_float2(d3[0], d3[1]);
        *(float2*)&Sc[(m0 + gid + 8) * SSTR + cc + 24] = make_float2(d3[2], d3[3]);
        __syncthreads();
    }
    int row = tid >> 3, l8 = tid & 7;
    float* Sr = &Sc[row * SSTR];
    float mx = -1e30f;
#pragma unroll
    for (int it = 0; it < 32; it++) {
        float4 v = *(const float4*)&Sr[l8 * 4 + it * 32];
        mx = fmaxf(mx, fmaxf(fmaxf(v.x, v.y), fmaxf(v.z, v.w)));
    }
#pragma unroll
    for (int off = 1; off < 8; off <<= 1)
        mx = fmaxf(mx, __shfl_xor_sync(0xffffffffu, mx, off));
    float sum = 0.f;
#pragma unroll
    for (int it = 0; it < 32; it++) {
        float4 v = *(const float4*)&Sr[l8 * 4 + it * 32];
        v.x = __expf(v.x - mx); v.y = __expf(v.y - mx);
        v.z = __expf(v.z - mx); v.w = __expf(v.w - mx);
        sum += (v.x + v.y) + (v.z + v.w);
        *(float4*)&Sr[l8 * 4 + it * 32] = v;
    }
#pragma unroll
    for (int off = 1; off < 8; off <<= 1)
        sum += __shfl_xor_sync(0xffffffffu, sum, off);
    float inv = 1.f / sum;
    __nv_bfloat16* Jr = &Jh[((size_t)(bh << 10) + i0 + row) * Nn];
#pragma unroll
    for (int it = 0; it < 32; it++) {
        float4 v = *(const float4*)&Sr[l8 * 4 + it * 32];
        uint2 pk;
        pk.x = bf16x2(v.x * inv, v.y * inv);
        pk.y = bf16x2(v.z * inv, v.w * inv);
        *(uint2*)&Jr[l8 * 4 + it * 32] = pk;
    }
}

// ---------------------------------------------------------------------------
// Fully fused Kuramoto step: full-K matvec (bf16 MMA) + in-smem reduce +
// phase update + sincos, one kernel, no global partials.
// Grid (64 i-strips of 16 rows, 8 bh), 256 thr = 8 warps; warp w owns
// k-chunk [128w, 128w+128). smem: J 16x1032 bf16 (JW=516 words/row,
// ==4 mod 32 -> conflict-free A loads) + full sch copy + 8KB partials.
// ---------------------------------------------------------------------------
#define STEP_SMEM ((8256 + 8192 + 2048) * 4)   // 73984 B
__global__ __launch_bounds__(256, 3) void step_fused(
    const __nv_bfloat16* __restrict__ Jh, const __nv_bfloat16* __restrict__ sch,
    float* __restrict__ ph,
    const float* __restrict__ s_in, const float* __restrict__ c_in,
    float* __restrict__ s_out, float* __restrict__ c_out,
    __nv_bfloat16* __restrict__ sch_out,
    const float* __restrict__ omega, const float* __restrict__ cs_ptr) {
    extern __shared__ __align__(16) uint sm4[];
    uint* Jt  = sm4;              // 16 rows x JW words (8256)
    uint* scs = sm4 + 8256;       // 8192 words: sch[bh] copy [jp][16w]
    float* Pr = (float*)(sm4 + 8256 + 8192);   // [8 warps][16 rows][16]
    int i0 = blockIdx.x * 16;
    int bh = blockIdx.y;
    int b = bh >> 2, h = bh & 3;
    int tid = threadIdx.x;
    // burst-load J strip (32 KB) + sch (32 KB) via cp.async, full MLP
    const __nv_bfloat16* Jsrc = Jh + ((size_t)(bh << 10) + i0) * Nn;
#pragma unroll
    for (int it = 0; it < 8; it++) {
        int u = tid + it * 256;
        int r = u >> 7, cu = u & 127;
        uint dst = (uint)__cvta_generic_to_shared(&Jt[r * JW + cu * 4]);
        CP16(dst, Jsrc + (size_t)r * Nn + cu * 8);
    }
    const __nv_bfloat16* Ssrc = sch + ((size_t)bh << 14);
#pragma unroll
    for (int it = 0; it < 8; it++) {
        int v = tid + it * 256;
        uint dst = (uint)__cvta_generic_to_shared(&scs[v * 4]);
        CP16(dst, Ssrc + v * 8);
    }
    CP_COMMIT();
    CP_WAIT(0);
    __syncthreads();

    int w = tid >> 5, lane = tid & 31;
    int gid = lane >> 2, tig = lane & 3;
    float ds[4] = {}, dc[4] = {};
    int rA0 = gid * JW + w * 64;
    int rA1 = (gid + 8) * JW + w * 64;
#pragma unroll
    for (int kk = 0; kk < 8; kk++) {
        uint a0 = Jt[rA0 + kk * 8 + tig];
        uint a1 = Jt[rA1 + kk * 8 + tig];
        uint a2 = Jt[rA0 + kk * 8 + tig + 4];
        uint a3 = Jt[rA1 + kk * 8 + tig + 4];
        int jb = w * 64 + kk * 8;
        uint b0s = scs[(jb + tig) * 16 + gid];
        uint b1s = scs[(jb + tig + 4) * 16 + gid];
        uint b0c = scs[(jb + tig) * 16 + 8 + gid];
        uint b1c = scs[(jb + tig + 4) * 16 + 8 + gid];
        MMA_BF16(ds, a0, a1, a2, a3, b0s, b1s);
        MMA_BF16(dc, a0, a1, a2, a3, b0c, b1c);
    }
    int pw = w * 256;
    *(float2*)&Pr[pw + gid * 16 + tig * 2]           = make_float2(ds[0], ds[1]);
    *(float2*)&Pr[pw + gid * 16 + 8 + tig * 2]       = make_float2(dc[0], dc[1]);
    *(float2*)&Pr[pw + (gid + 8) * 16 + tig * 2]     = make_float2(ds[2], ds[3]);
    *(float2*)&Pr[pw + (gid + 8) * 16 + 8 + tig * 2] = make_float2(dc[2], dc[3]);
    __syncthreads();

    if (tid < 128) {
        int row = tid >> 3, o = tid & 7;
        float js = 0.f, jc = 0.f;
#pragma unroll
        for (int w2 = 0; w2 < 8; w2++) {
            js += Pr[w2 * 256 + row * 16 + o];
            jc += Pr[w2 * 256 + row * 16 + 8 + o];
        }
        int n = i0 + row;
        int gs = ((b << 10) + n) * HO + h * Oo + o;
        float si = s_in[gs], ci = c_in[gs];
        float coup = ci * js - si * jc;
        float np = ph[gs] + DT_F * (omega[h * Oo + o] + (*cs_ptr) * coup);
        float v = np + PI_F;
        np = v - floorf(v * INV_2PI_F) * TWO_PI_F - PI_F;
        ph[gs] = np;
        float sn, cn;
        sincosf(np, &sn, &cn);
        s_out[gs] = sn;
        c_out[gs] = cn;
        int base2 = ((bh << 9) + (n >> 1)) * 32 + (n & 1);
        sch_out[base2 + o * 2] = __float2bfloat16_rn(sn);
        sch_out[base2 + 16 + o * 2] = __float2bfloat16_rn(cn);
    }
}

// ---------------------------------------------------------------------------
// Final small GEMM: out = C @ Wo^T + bo, K=32.
// ---------------------------------------------------------------------------
__global__ void gemm_out(const float* __restrict__ X, const float* __restrict__ W,
                         const float* __restrict__ bias, float* __restrict__ out) {
    __shared__ float As[64][33];
    __shared__ float Ws[64][33];
    int m0 = blockIdx.x * 64, n0 = blockIdx.y * 64;
    int tid = threadIdx.x;
    int tx = tid & 15, ty = tid >> 4;
    float acc[4][4] = {};
    for (int li = tid; li < 64 * 32; li += 256) {
        int r = li >> 5, c = li & 31;
        As[r][c] = X[(size_t)(m0 + r) * HO + c];
        Ws[r][c] = W[(size_t)(n0 + r) * HO + c];
    }
    __syncthreads();
#pragma unroll
    for (int kk = 0; kk < 32; kk++) {
        float a[4], bb[4];
#pragma unroll
        for (int i = 0; i < 4; i++) a[i] = As[ty * 4 + i][kk];
#pragma unroll
        for (int j = 0; j < 4; j++) bb[j] = Ws[tx * 4 + j][kk];
#pragma unroll
        for (int i = 0; i < 4; i++)
#pragma unroll
            for (int j = 0; j < 4; j++)
                acc[i][j] = fmaf(a[i], bb[j], acc[i][j]);
    }
#pragma unroll
    for (int i = 0; i < 4; i++) {
        int m = m0 + ty * 4 + i;
#pragma unroll
        for (int j = 0; j < 4; j++) {
            int n = n0 + tx * 4 + j;
            out[(size_t)m * Dd + n] = acc[i][j] + bias[n];
        }
    }
}

// ---------------------------------------------------------------------------
extern "C" void kernel_launch(void* const* d_in, const int* in_sizes, int n_in,
                              void* d_out, int out_size) {
    const float* x     = (const float*)d_in[0];
    const float* Wq    = (const float*)d_in[1];
    const float* Wk    = (const float*)d_in[2];
    const float* Wp    = (const float*)d_in[3];
    const float* bp    = (const float*)d_in[4];
    const float* Wo    = (const float*)d_in[5];
    const float* bo    = (const float*)d_in[6];
    const float* omega = (const float*)d_in[7];
    const float* cs    = (const float*)d_in[8];
    float* out = (float*)d_out;

    float *q, *k, *ph, *s0, *s1, *c0, *c1;
    __nv_bfloat16 *sch0, *sch1, *Jh;
    cudaGetSymbolAddress((void**)&q,    g_q);
    cudaGetSymbolAddress((void**)&k,    g_k);
    cudaGetSymbolAddress((void**)&ph,   g_ph);
    cudaGetSymbolAddress((void**)&s0,   g_s0);
    cudaGetSymbolAddress((void**)&s1,   g_s1);
    cudaGetSymbolAddress((void**)&c0,   g_c0);
    cudaGetSymbolAddress((void**)&c1,   g_c1);
    cudaGetSymbolAddress((void**)&sch0, g_sch0);
    cudaGetSymbolAddress((void**)&sch1, g_sch1);
    cudaGetSymbolAddress((void**)&Jh,   g_Jh);

    dim3 blk(256);
    // fused projections (q, k tf32; ph + sincos, fp32 + bf16 layouts)
    proj_kernel<<<dim3(Bb * Nn / 64, 9), blk>>>(x, Wq, Wk, Wp, bp, q, k, ph, s0, c0, sch0);
    // fused scores + softmax -> bf16 J
    size_t smem_at = (size_t)(32 * SSTR + 32 * KSTR + 2 * 128 * KSTR) * sizeof(float);
    cudaFuncSetAttribute(attn_kernel, cudaFuncAttributeMaxDynamicSharedMemorySize, (int)smem_at);
    attn_kernel<<<dim3(Nn / 32, Bb * Hh), blk, smem_at>>>(q, k, Jh);
    // 5 fully-fused oscillator steps (one kernel each, no global partials)
    cudaFuncSetAttribute(step_fused, cudaFuncAttributeMaxDynamicSharedMemorySize, STEP_SMEM);
    float* sbuf[2] = {s0, s1};
    float* cbuf[2] = {c0, c1};
    __nv_bfloat16* scbuf[2] = {sch0, sch1};
    for (int t = 0; t < NSTEPS; t++) {
        step_fused<<<dim3(Nn / 16, Bb * Hh), blk, STEP_SMEM>>>(
            Jh, scbuf[t & 1], ph, sbuf[t & 1], cbuf[t & 1],
            sbuf[(t + 1) & 1], cbuf[(t + 1) & 1], scbuf[(t + 1) & 1],
            omega, cs);
    }
    // output: out = cos(final phases) @ Wo^T + bo
    const float* cfin = cbuf[NSTEPS & 1];
    gemm_out<<<dim3(Bb * Nn / 64, Dd / 64), blk>>>(cfin, Wo, bo, out);
}

// round 16
// speedup vs baseline: 3.0945x; 1.0210x over previous
#include <cuda_runtime.h>
#include <cuda_bf16.h>
#include <math.h>

#define Bb 2
#define Nn 1024
#define Dd 256
#define Hh 4
#define Oo 8
#define HO 32
#define DKK 64
#define NSTEPS 5
#define DT_F 0.1f
#define PI_F 3.14159265358979323846f
#define TWO_PI_F 6.28318530717958647692f
#define INV_2PI_F 0.15915494309189533577f

#define GTOT (Bb * Nn * HO)   // 65536
#define SSTR 1032             // fused-attn score smem row stride (floats)
#define KSTR 68               // fused-attn q/k smem row stride (floats)
#define JW2 132               // step J-chunk row stride in words (==4 mod 32)
#define SCW 24                // sc smem words per j-pair (conflict-free pad)

typedef unsigned long long ull;
typedef unsigned int uint;

// Packed fp32x2 FMA (bit-identical to two scalar FFMAs).
#define FMA2(d, a, b) \
    asm("fma.rn.f32x2 %0, %1, %2, %0;" : "+l"(d) : "l"(a), "l"(b))
#define PACK2(d, x) \
    asm("mov.b64 %0, {%1, %1};" : "=l"(d) : "r"(__float_as_uint(x)))
#define UNPK2(lo, hi, v) \
    asm("mov.b64 {%0, %1}, %2;" : "=f"(lo), "=f"(hi) : "l"(v))

// pack two f32 -> bf16x2 (lo in low 16 bits)
__device__ __forceinline__ uint bf16x2(float lo, float hi) {
    uint r;
    asm("cvt.rn.bf16x2.f32 %0, %1, %2;" : "=r"(r) : "f"(hi), "f"(lo));
    return r;
}

// tf32 round-to-nearest
__device__ __forceinline__ float tf32r(float x) {
    uint u;
    asm("cvt.rna.tf32.f32 %0, %1;" : "=r"(u) : "f"(x));
    return __uint_as_float(u);
}

// m16n8k16 bf16 mma, fp32 accumulate
#define MMA_BF16(d, a0, a1, a2, a3, b0, b1) \
    asm("mma.sync.aligned.m16n8k16.row.col.f32.bf16.bf16.f32 " \
        "{%0,%1,%2,%3}, {%4,%5,%6,%7}, {%8,%9}, {%0,%1,%2,%3};" \
        : "+f"(d[0]), "+f"(d[1]), "+f"(d[2]), "+f"(d[3]) \
        : "r"(a0), "r"(a1), "r"(a2), "r"(a3), "r"(b0), "r"(b1))

// m16n8k8 tf32 mma, fp32 accumulate
#define MMA_TF32(d, a0, a1, a2, a3, b0, b1) \
    asm("mma.sync.aligned.m16n8k8.row.col.f32.tf32.tf32.f32 " \
        "{%0,%1,%2,%3}, {%4,%5,%6,%7}, {%8,%9}, {%0,%1,%2,%3};" \
        : "+f"(d[0]), "+f"(d[1]), "+f"(d[2]), "+f"(d[3]) \
        : "r"(a0), "r"(a1), "r"(a2), "r"(a3), "r"(b0), "r"(b1))

// cp.async helpers
#define CP16(dst_u32, src_ptr) \
    asm volatile("cp.async.cg.shared.global [%0], [%1], 16;" \
                 :: "r"(dst_u32), "l"(src_ptr))
#define CP_COMMIT() asm volatile("cp.async.commit_group;")
#define CP_WAIT(n)  asm volatile("cp.async.wait_group %0;" :: "n"(n))

// Scratch (no cudaMalloc allowed)
__device__ float g_q[Bb * Nn * Dd];
__device__ float g_k[Bb * Nn * Dd];
__device__ float g_ph[GTOT];
__device__ float g_s0[GTOT];
__device__ float g_s1[GTOT];
__device__ float g_c0[GTOT];
__device__ float g_c1[GTOT];
__device__ __nv_bfloat16 g_sch0[Bb * Hh * Nn * 16];  // [bh][jp][s0..7|c0..7]x2
__device__ __nv_bfloat16 g_sch1[Bb * Hh * Nn * 16];
__device__ __nv_bfloat16 g_Jh[(size_t)Bb * Hh * Nn * Nn];  // 16 MB bf16 J

// ---------------------------------------------------------------------------
// Fused projection kernel: q = 0.125*x@Wq^T (tf32), k = x@Wk^T (tf32),
// ph = x@Wp^T + bp (+sincos, fp32 + bf16 layouts).
// ---------------------------------------------------------------------------
__global__ __launch_bounds__(256, 2) void proj_kernel(
    const float* __restrict__ x,
    const float* __restrict__ Wq, const float* __restrict__ Wk,
    const float* __restrict__ Wp, const float* __restrict__ bp,
    float* __restrict__ q, float* __restrict__ k,
    float* __restrict__ ph, float* __restrict__ s0, float* __restrict__ c0,
    __nv_bfloat16* __restrict__ sch0) {
    __shared__ __align__(16) float As[64][68];   // [kk][m]
    __shared__ __align__(16) float Bs[64][68];   // [kk][n]
    int m0 = blockIdx.x * 64;
    int y = blockIdx.y;
    const float* W;
    int n0, Nout;
    if (y < 4)      { W = Wq; n0 = y * 64;       Nout = Dd; }
    else if (y < 8) { W = Wk; n0 = (y - 4) * 64; Nout = Dd; }
    else            { W = Wp; n0 = 0;            Nout = HO; }
    int tid = threadIdx.x;
    int tx = tid & 15, ty = tid >> 4;
    ull acc2[4][2] = {};
    for (int kt = 0; kt < Dd; kt += 64) {
        for (int t = tid; t < 64 * 16; t += 256) {
            int r = t >> 4, c4 = (t & 15) * 4;
            float4 va = *(const float4*)&x[(size_t)(m0 + r) * Dd + kt + c4];
            As[c4 + 0][r] = va.x; As[c4 + 1][r] = va.y;
            As[c4 + 2][r] = va.z; As[c4 + 3][r] = va.w;
            float4 vb = make_float4(0.f, 0.f, 0.f, 0.f);
            if (n0 + r < Nout)
                vb = *(const float4*)&W[(size_t)(n0 + r) * Dd + kt + c4];
            Bs[c4 + 0][r] = vb.x; Bs[c4 + 1][r] = vb.y;
            Bs[c4 + 2][r] = vb.z; Bs[c4 + 3][r] = vb.w;
        }
        __syncthreads();
#pragma unroll
        for (int kk = 0; kk < 64; kk++) {
            float4 a = *(const float4*)&As[kk][ty * 4];
            ulonglong2 bv = *(const ulonglong2*)&Bs[kk][tx * 4];
            ull aa0, aa1, aa2, aa3;
            PACK2(aa0, a.x); PACK2(aa1, a.y); PACK2(aa2, a.z); PACK2(aa3, a.w);
            FMA2(acc2[0][0], aa0, bv.x); FMA2(acc2[0][1], aa0, bv.y);
            FMA2(acc2[1][0], aa1, bv.x); FMA2(acc2[1][1], aa1, bv.y);
            FMA2(acc2[2][0], aa2, bv.x); FMA2(acc2[2][1], aa2, bv.y);
            FMA2(acc2[3][0], aa3, bv.x); FMA2(acc2[3][1], aa3, bv.y);
        }
        __syncthreads();
    }
    float acc[4][4];
#pragma unroll
    for (int i = 0; i < 4; i++) {
        UNPK2(acc[i][0], acc[i][1], acc2[i][0]);
        UNPK2(acc[i][2], acc[i][3], acc2[i][1]);
    }
    if (y < 4) {
#pragma unroll
        for (int i = 0; i < 4; i++) {
            int m = m0 + ty * 4 + i;
            float4 v = make_float4(tf32r(0.125f * acc[i][0]), tf32r(0.125f * acc[i][1]),
                                   tf32r(0.125f * acc[i][2]), tf32r(0.125f * acc[i][3]));
            *(float4*)&q[(size_t)m * Dd + n0 + tx * 4] = v;
        }
    } else if (y < 8) {
#pragma unroll
        for (int i = 0; i < 4; i++) {
            int m = m0 + ty * 4 + i;
            float4 v = make_float4(tf32r(acc[i][0]), tf32r(acc[i][1]),
                                   tf32r(acc[i][2]), tf32r(acc[i][3]));
            *(float4*)&k[(size_t)m * Dd + n0 + tx * 4] = v;
        }
    } else if (tx * 4 < HO) {
#pragma unroll
        for (int i = 0; i < 4; i++) {
            int m = m0 + ty * 4 + i;
            int j = m & 1023, b = m >> 10;
            int jp = j >> 1, jb = j & 1;
#pragma unroll
            for (int jj = 0; jj < 4; jj++) {
                int n = tx * 4 + jj;
                float p = acc[i][jj] + bp[n];
                int g = m * HO + n;
                ph[g] = p;
                float sn, cn;
                sincosf(p, &sn, &cn);
                s0[g] = sn;
                c0[g] = cn;
                int bh = b * 4 + (n >> 3), o = n & 7;
                int base = ((bh << 9) + jp) * 32;
                sch0[base + o * 2 + jb] = __float2bfloat16_rn(sn);
                sch0[base + 16 + o * 2 + jb] = __float2bfloat16_rn(cn);
            }
        }
    }
}

// ---------------------------------------------------------------------------
// Fused attention: scores (tf32 MMA) + row softmax + bf16 J write.
// ---------------------------------------------------------------------------
__global__ __launch_bounds__(256, 1) void attn_kernel(
    const float* __restrict__ q, const float* __restrict__ k,
    __nv_bfloat16* __restrict__ Jh) {
    extern __shared__ __align__(16) float dsm[];
    float* Sc = dsm;                      // 32*SSTR floats
    float* Qs = Sc + 32 * SSTR;           // 32*KSTR
    float* Ks = Qs + 32 * KSTR;           // 2*128*KSTR
    int i0 = blockIdx.x * 32;
    int bh = blockIdx.y;
    int b = bh >> 2, h = bh & 3;
    int tid = threadIdx.x;
#pragma unroll
    for (int it = 0; it < 2; it++) {
        int idx = tid + it * 256;
        int r = idx >> 4, c4 = (idx & 15) * 4;
        float4 v = *(const float4*)&q[(size_t)((b << 10) + i0 + r) * Dd + h * DKK + c4];
        *(float4*)&Qs[r * KSTR + c4] = v;
    }
    const float* kbase = &k[(size_t)(b << 10) * Dd + h * DKK];
#pragma unroll
    for (int it = 0; it < 8; it++) {
        int idx = tid + it * 256;
        int jr = idx >> 4, c4 = (idx & 15) * 4;
        uint dst = (uint)__cvta_generic_to_shared(&Ks[jr * KSTR + c4]);
        CP16(dst, &kbase[(size_t)jr * Dd + c4]);
    }
    CP_COMMIT();

    int w = tid >> 5, lane = tid & 31;
    int gid = lane >> 2, tig = lane & 3;
    int m0 = (w >> 2) * 16, jq = (w & 3) * 32;
    for (int c = 0; c < 8; c++) {
        if (c < 7) {
            float* bufn = &Ks[((c + 1) & 1) * 128 * KSTR];
#pragma unroll
            for (int it = 0; it < 8; it++) {
                int idx = tid + it * 256;
                int jr = idx >> 4, c4 = (idx & 15) * 4;
                uint dst = (uint)__cvta_generic_to_shared(&bufn[jr * KSTR + c4]);
                CP16(dst, &kbase[(size_t)(((c + 1) << 7) + jr) * Dd + c4]);
            }
            CP_COMMIT();
            CP_WAIT(1);
        } else {
            CP_WAIT(0);
        }
        __syncthreads();
        const float* buf = &Ks[(c & 1) * 128 * KSTR];
        float d0[4] = {}, d1[4] = {}, d2[4] = {}, d3[4] = {};
#pragma unroll
        for (int kk = 0; kk < 8; kk++) {
            int kb8 = kk * 8;
            uint a0 = __float_as_uint(Qs[(m0 + gid) * KSTR + kb8 + tig]);
            uint a1 = __float_as_uint(Qs[(m0 + gid + 8) * KSTR + kb8 + tig]);
            uint a2 = __float_as_uint(Qs[(m0 + gid) * KSTR + kb8 + tig + 4]);
            uint a3 = __float_as_uint(Qs[(m0 + gid + 8) * KSTR + kb8 + tig + 4]);
            uint b0, b1;
            b0 = __float_as_uint(buf[(jq + 0 + gid) * KSTR + kb8 + tig]);
            b1 = __float_as_uint(buf[(jq + 0 + gid) * KSTR + kb8 + tig + 4]);
            MMA_TF32(d0, a0, a1, a2, a3, b0, b1);
            b0 = __float_as_uint(buf[(jq + 8 + gid) * KSTR + kb8 + tig]);
            b1 = __float_as_uint(buf[(jq + 8 + gid) * KSTR + kb8 + tig + 4]);
            MMA_TF32(d1, a0, a1, a2, a3, b0, b1);
            b0 = __float_as_uint(buf[(jq + 16 + gid) * KSTR + kb8 + tig]);
            b1 = __float_as_uint(buf[(jq + 16 + gid) * KSTR + kb8 + tig + 4]);
            MMA_TF32(d2, a0, a1, a2, a3, b0, b1);
            b0 = __float_as_uint(buf[(jq + 24 + gid) * KSTR + kb8 + tig]);
            b1 = __float_as_uint(buf[(jq + 24 + gid) * KSTR + kb8 + tig + 4]);
            MMA_TF32(d3, a0, a1, a2, a3, b0, b1);
        }
        int cc = c * 128 + jq + tig * 2;
        *(float2*)&Sc[(m0 + gid) * SSTR + cc]          = make_float2(d0[0], d0[1]);
        *(float2*)&Sc[(m0 + gid + 8) * SSTR + cc]      = make_float2(d0[2], d0[3]);
        *(float2*)&Sc[(m0 + gid) * SSTR + cc + 8]      = make_float2(d1[0], d1[1]);
        *(float2*)&Sc[(m0 + gid + 8) * SSTR + cc + 8]  = make_float2(d1[2], d1[3]);
        *(float2*)&Sc[(m0 + gid) * SSTR + cc + 16]     = make_float2(d2[0], d2[1]);
        *(float2*)&Sc[(m0 + gid + 8) * SSTR + cc + 16] = make_float2(d2[2], d2[3]);
        *(float2*)&Sc[(m0 + gid) * SSTR + cc + 24]     = make_float2(d3[0], d3[1]);
        *(float2*)&Sc[(m0 + gid + 8) * SSTR + cc + 24] = make_float2(d3[2], d3[3]);
        __syncthreads();
    }
    int row = tid >> 3, l8 = tid & 7;
    float* Sr = &Sc[row * SSTR];
    float mx = -1e30f;
#pragma unroll
    for (int it = 0; it < 32; it++) {
        float4 v = *(const float4*)&Sr[l8 * 4 + it * 32];
        mx = fmaxf(mx, fmaxf(fmaxf(v.x, v.y), fmaxf(v.z, v.w)));
    }
#pragma unroll
    for (int off = 1; off < 8; off <<= 1)
        mx = fmaxf(mx, __shfl_xor_sync(0xffffffffu, mx, off));
    float sum = 0.f;
#pragma unroll
    for (int it = 0; it < 32; it++) {
        float4 v = *(const float4*)&Sr[l8 * 4 + it * 32];
        v.x = __expf(v.x - mx); v.y = __expf(v.y - mx);
        v.z = __expf(v.z - mx); v.w = __expf(v.w - mx);
        sum += (v.x + v.y) + (v.z + v.w);
        *(float4*)&Sr[l8 * 4 + it * 32] = v;
    }
#pragma unroll
    for (int off = 1; off < 8; off <<= 1)
        sum += __shfl_xor_sync(0xffffffffu, sum, off);
    float inv = 1.f / sum;
    __nv_bfloat16* Jr = &Jh[((size_t)(bh << 10) + i0 + row) * Nn];
#pragma unroll
    for (int it = 0; it < 32; it++) {
        float4 v = *(const float4*)&Sr[l8 * 4 + it * 32];
        uint2 pk;
        pk.x = bf16x2(v.x * inv, v.y * inv);
        pk.y = bf16x2(v.z * inv, v.w * inv);
        *(uint2*)&Jr[l8 * 4 + it * 32] = pk;
    }
}

// ---------------------------------------------------------------------------
// Fully fused Kuramoto step, pipelined: 32 rows/CTA, K=1024 in 4 chunks of
// 256 j, cp.async double-buffered (load chunk c+1 during MMAs of chunk c).
// In-smem 8-warp reduce + phase update + sincos epilogue (256 threads).
// smem: 2 x (J chunk 32x132w) + 2 x (sc chunk 128x24w) + partials 4096 f.
// ---------------------------------------------------------------------------
#define ROWS 32
#define STEP_SMEM ((2 * (ROWS * JW2) + 2 * (128 * SCW) + 4096) * 4)   // 74752 B
__global__ __launch_bounds__(256, 3) void step_fused(
    const __nv_bfloat16* __restrict__ Jh, const __nv_bfloat16* __restrict__ sch,
    float* __restrict__ ph,
    const float* __restrict__ s_in, const float* __restrict__ c_in,
    float* __restrict__ s_out, float* __restrict__ c_out,
    __nv_bfloat16* __restrict__ sch_out,
    const float* __restrict__ omega, const float* __restrict__ cs_ptr) {
    extern __shared__ __align__(16) uint sm4[];
    uint* Jbuf[2] = {sm4, sm4 + ROWS * JW2};
    uint* sbuf[2] = {sm4 + 2 * ROWS * JW2, sm4 + 2 * ROWS * JW2 + 128 * SCW};
    float* Pr = (float*)(sm4 + 2 * ROWS * JW2 + 2 * 128 * SCW);  // [8][32][16]
    int i0 = blockIdx.x * ROWS;
    int bh = blockIdx.y;
    int b = bh >> 2, h = bh & 3;
    int tid = threadIdx.x;
    const __nv_bfloat16* Jsrc = Jh + ((size_t)(bh << 10) + i0) * Nn;
    const __nv_bfloat16* Ssrc = sch + ((size_t)bh << 14);

    // chunk loader: J 32x256 bf16 (16 KB) + sc 128 jp x 16 words (8 KB)
#define LOAD_CHUNK(c, JB, SB) do {                                          \
        int _cj = (c) << 8;                                                 \
        _Pragma("unroll")                                                   \
        for (int _it = 0; _it < 4; _it++) {                                 \
            int _u = tid + _it * 256;                                       \
            int _r = _u >> 5, _cw = (_u & 31) * 4;                          \
            uint _d = (uint)__cvta_generic_to_shared(&(JB)[_r * JW2 + _cw]);\
            CP16(_d, Jsrc + (size_t)_r * Nn + _cj + _cw * 2);               \
        }                                                                   \
        _Pragma("unroll")                                                   \
        for (int _it = 0; _it < 2; _it++) {                                 \
            int _u = tid + _it * 256;                                       \
            int _p = _u >> 2, _wq = (_u & 3) * 4;                           \
            uint _d = (uint)__cvta_generic_to_shared(&(SB)[_p * SCW + _wq]);\
            CP16(_d, Ssrc + ((size_t)(((c) << 7) + _p)) * 32 + _wq * 2);    \
        }                                                                   \
    } while (0)

    LOAD_CHUNK(0, Jbuf[0], sbuf[0]);
    CP_COMMIT();

    int w = tid >> 5, lane = tid & 31;
    int gid = lane >> 2, tig = lane & 3;
    float ds[2][4] = {}, dc[2][4] = {};
#pragma unroll
    for (int c = 0; c < 4; c++) {
        if (c < 3) {
            LOAD_CHUNK(c + 1, Jbuf[(c + 1) & 1], sbuf[(c + 1) & 1]);
            CP_COMMIT();
            CP_WAIT(1);
        } else {
            CP_WAIT(0);
        }
        __syncthreads();
        const uint* JB = Jbuf[c & 1];
        const uint* SB = sbuf[c & 1];
#pragma unroll
        for (int kk = 0; kk < 2; kk++) {
            int wb = w * 16 + kk * 8;        // local word/jp base for this warp
            uint b0s = SB[(wb + tig) * SCW + gid];
            uint b1s = SB[(wb + tig + 4) * SCW + gid];
            uint b0c = SB[(wb + tig) * SCW + 8 + gid];
            uint b1c = SB[(wb + tig + 4) * SCW + 8 + gid];
#pragma unroll
            for (int rg = 0; rg < 2; rg++) {
                int r0 = (rg * 16 + gid) * JW2 + wb + tig;
                int r1 = (rg * 16 + gid + 8) * JW2 + wb + tig;
                uint a0 = JB[r0];
                uint a1 = JB[r1];
                uint a2 = JB[r0 + 4];
                uint a3 = JB[r1 + 4];
                MMA_BF16(ds[rg], a0, a1, a2, a3, b0s, b1s);
                MMA_BF16(dc[rg], a0, a1, a2, a3, b0c, b1c);
            }
        }
        __syncthreads();
    }
#pragma unroll
    for (int rg = 0; rg < 2; rg++) {
        int pw = w * 512;
        *(float2*)&Pr[pw + (rg * 16 + gid) * 16 + tig * 2]           = make_float2(ds[rg][0], ds[rg][1]);
        *(float2*)&Pr[pw + (rg * 16 + gid) * 16 + 8 + tig * 2]       = make_float2(dc[rg][0], dc[rg][1]);
        *(float2*)&Pr[pw + (rg * 16 + gid + 8) * 16 + tig * 2]       = make_float2(ds[rg][2], ds[rg][3]);
        *(float2*)&Pr[pw + (rg * 16 + gid + 8) * 16 + 8 + tig * 2]   = make_float2(dc[rg][2], dc[rg][3]);
    }
    __syncthreads();

    {
        int row = tid >> 3, o = tid & 7;
        float js = 0.f, jc = 0.f;
#pragma unroll
        for (int w2 = 0; w2 < 8; w2++) {
            js += Pr[w2 * 512 + row * 16 + o];
            jc += Pr[w2 * 512 + row * 16 + 8 + o];
        }
        int n = i0 + row;
        int gs = ((b << 10) + n) * HO + h * Oo + o;
        float si = s_in[gs], ci = c_in[gs];
        float coup = ci * js - si * jc;
        float np = ph[gs] + DT_F * (omega[h * Oo + o] + (*cs_ptr) * coup);
        float v = np + PI_F;
        np = v - floorf(v * INV_2PI_F) * TWO_PI_F - PI_F;
        ph[gs] = np;
        float sn, cn;
        sincosf(np, &sn, &cn);
        s_out[gs] = sn;
        c_out[gs] = cn;
        int base2 = ((bh << 9) + (n >> 1)) * 32 + (n & 1);
        sch_out[base2 + o * 2] = __float2bfloat16_rn(sn);
        sch_out[base2 + 16 + o * 2] = __float2bfloat16_rn(cn);
    }
#undef LOAD_CHUNK
}

// ---------------------------------------------------------------------------
// Final small GEMM: out = C @ Wo^T + bo, K=32.
// ---------------------------------------------------------------------------
__global__ void gemm_out(const float* __restrict__ X, const float* __restrict__ W,
                         const float* __restrict__ bias, float* __restrict__ out) {
    __shared__ float As[64][33];
    __shared__ float Ws[64][33];
    int m0 = blockIdx.x * 64, n0 = blockIdx.y * 64;
    int tid = threadIdx.x;
    int tx = tid & 15, ty = tid >> 4;
    float acc[4][4] = {};
    for (int li = tid; li < 64 * 32; li += 256) {
        int r = li >> 5, c = li & 31;
        As[r][c] = X[(size_t)(m0 + r) * HO + c];
        Ws[r][c] = W[(size_t)(n0 + r) * HO + c];
    }
    __syncthreads();
#pragma unroll
    for (int kk = 0; kk < 32; kk++) {
        float a[4], bb[4];
#pragma unroll
        for (int i = 0; i < 4; i++) a[i] = As[ty * 4 + i][kk];
#pragma unroll
        for (int j = 0; j < 4; j++) bb[j] = Ws[tx * 4 + j][kk];
#pragma unroll
        for (int i = 0; i < 4; i++)
#pragma unroll
            for (int j = 0; j < 4; j++)
                acc[i][j] = fmaf(a[i], bb[j], acc[i][j]);
    }
#pragma unroll
    for (int i = 0; i < 4; i++) {
        int m = m0 + ty * 4 + i;
#pragma unroll
        for (int j = 0; j < 4; j++) {
            int n = n0 + tx * 4 + j;
            out[(size_t)m * Dd + n] = acc[i][j] + bias[n];
        }
    }
}

// ---------------------------------------------------------------------------
extern "C" void kernel_launch(void* const* d_in, const int* in_sizes, int n_in,
                              void* d_out, int out_size) {
    const float* x     = (const float*)d_in[0];
    const float* Wq    = (const float*)d_in[1];
    const float* Wk    = (const float*)d_in[2];
    const float* Wp    = (const float*)d_in[3];
    const float* bp    = (const float*)d_in[4];
    const float* Wo    = (const float*)d_in[5];
    const float* bo    = (const float*)d_in[6];
    const float* omega = (const float*)d_in[7];
    const float* cs    = (const float*)d_in[8];
    float* out = (float*)d_out;

    float *q, *k, *ph, *s0, *s1, *c0, *c1;
    __nv_bfloat16 *sch0, *sch1, *Jh;
    cudaGetSymbolAddress((void**)&q,    g_q);
    cudaGetSymbolAddress((void**)&k,    g_k);
    cudaGetSymbolAddress((void**)&ph,   g_ph);
    cudaGetSymbolAddress((void**)&s0,   g_s0);
    cudaGetSymbolAddress((void**)&s1,   g_s1);
    cudaGetSymbolAddress((void**)&c0,   g_c0);
    cudaGetSymbolAddress((void**)&c1,   g_c1);
    cudaGetSymbolAddress((void**)&sch0, g_sch0);
    cudaGetSymbolAddress((void**)&sch1, g_sch1);
    cudaGetSymbolAddress((void**)&Jh,   g_Jh);

    dim3 blk(256);
    // fused projections (q, k tf32; ph + sincos, fp32 + bf16 layouts)
    proj_kernel<<<dim3(Bb * Nn / 64, 9), blk>>>(x, Wq, Wk, Wp, bp, q, k, ph, s0, c0, sch0);
    // fused scores + softmax -> bf16 J
    size_t smem_at = (size_t)(32 * SSTR + 32 * KSTR + 2 * 128 * KSTR) * sizeof(float);
    cudaFuncSetAttribute(attn_kernel, cudaFuncAttributeMaxDynamicSharedMemorySize, (int)smem_at);
    attn_kernel<<<dim3(Nn / 32, Bb * Hh), blk, smem_at>>>(q, k, Jh);
    // 5 pipelined fused oscillator steps
    cudaFuncSetAttribute(step_fused, cudaFuncAttributeMaxDynamicSharedMemorySize, STEP_SMEM);
    float* sbufp[2] = {s0, s1};
    float* cbufp[2] = {c0, c1};
    __nv_bfloat16* scbuf[2] = {sch0, sch1};
    for (int t = 0; t < NSTEPS; t++) {
        step_fused<<<dim3(Nn / ROWS, Bb * Hh), blk, STEP_SMEM>>>(
            Jh, scbuf[t & 1], ph, sbufp[t & 1], cbufp[t & 1],
            sbufp[(t + 1) & 1], cbufp[(t + 1) & 1], scbuf[(t + 1) & 1],
            omega, cs);
    }
    // output: out = cos(final phases) @ Wo^T + bo
    const float* cfin = cbufp[NSTEPS & 1];
    gemm_out<<<dim3(Bb * Nn / 64, Dd / 64), blk>>>(cfin, Wo, bo, out);
}

// round 17
// speedup vs baseline: 3.2454x; 1.0488x over previous
#include <cuda_runtime.h>
#include <cuda_bf16.h>
#include <math.h>

#define Bb 2
#define Nn 1024
#define Dd 256
#define Hh 4
#define Oo 8
#define HO 32
#define DKK 64
#define NSTEPS 5
#define DT_F 0.1f
#define PI_F 3.14159265358979323846f
#define TWO_PI_F 6.28318530717958647692f
#define INV_2PI_F 0.15915494309189533577f

#define GTOT (Bb * Nn * HO)   // 65536
#define SSTR 1032             // fused-attn score smem row stride (floats)
#define KSTR 68               // fused-attn q/k smem row stride (floats)
#define SCW 24                // sc smem words per j-pair (conflict-free pad)
#define JWF 516               // persistent J row stride in words (==4 mod 32)
#define NBLK 256              // persistent grid size (32 strips x 8 bh)

typedef unsigned long long ull;
typedef unsigned int uint;

// Packed fp32x2 FMA (bit-identical to two scalar FFMAs).
#define FMA2(d, a, b) \
    asm("fma.rn.f32x2 %0, %1, %2, %0;" : "+l"(d) : "l"(a), "l"(b))
#define PACK2(d, x) \
    asm("mov.b64 %0, {%1, %1};" : "=l"(d) : "r"(__float_as_uint(x)))
#define UNPK2(lo, hi, v) \
    asm("mov.b64 {%0, %1}, %2;" : "=f"(lo), "=f"(hi) : "l"(v))

// pack two f32 -> bf16x2 (lo in low 16 bits)
__device__ __forceinline__ uint bf16x2(float lo, float hi) {
    uint r;
    asm("cvt.rn.bf16x2.f32 %0, %1, %2;" : "=r"(r) : "f"(hi), "f"(lo));
    return r;
}

// tf32 round-to-nearest
__device__ __forceinline__ float tf32r(float x) {
    uint u;
    asm("cvt.rna.tf32.f32 %0, %1;" : "=r"(u) : "f"(x));
    return __uint_as_float(u);
}

// m16n8k16 bf16 mma, fp32 accumulate
#define MMA_BF16(d, a0, a1, a2, a3, b0, b1) \
    asm("mma.sync.aligned.m16n8k16.row.col.f32.bf16.bf16.f32 " \
        "{%0,%1,%2,%3}, {%4,%5,%6,%7}, {%8,%9}, {%0,%1,%2,%3};" \
        : "+f"(d[0]), "+f"(d[1]), "+f"(d[2]), "+f"(d[3]) \
        : "r"(a0), "r"(a1), "r"(a2), "r"(a3), "r"(b0), "r"(b1))

// m16n8k8 tf32 mma, fp32 accumulate
#define MMA_TF32(d, a0, a1, a2, a3, b0, b1) \
    asm("mma.sync.aligned.m16n8k8.row.col.f32.tf32.tf32.f32 " \
        "{%0,%1,%2,%3}, {%4,%5,%6,%7}, {%8,%9}, {%0,%1,%2,%3};" \
        : "+f"(d[0]), "+f"(d[1]), "+f"(d[2]), "+f"(d[3]) \
        : "r"(a0), "r"(a1), "r"(a2), "r"(a3), "r"(b0), "r"(b1))

// cp.async helpers
#define CP16(dst_u32, src_ptr) \
    asm volatile("cp.async.cg.shared.global [%0], [%1], 16;" \
                 :: "r"(dst_u32), "l"(src_ptr))
#define CP_COMMIT() asm volatile("cp.async.commit_group;")
#define CP_WAIT(n)  asm volatile("cp.async.wait_group %0;" :: "n"(n))

// Scratch (no cudaMalloc allowed)
__device__ float g_q[Bb * Nn * Dd];
__device__ float g_k[Bb * Nn * Dd];
__device__ float g_ph[GTOT];
__device__ float g_s0[GTOT];
__device__ float g_c0[GTOT];
__device__ float g_c1[GTOT];
__device__ __nv_bfloat16 g_sch0[Bb * Hh * Nn * 16];  // [bh][jp][s0..7|c0..7]x2
__device__ __nv_bfloat16 g_sch1[Bb * Hh * Nn * 16];
__device__ __nv_bfloat16 g_Jh[(size_t)Bb * Hh * Nn * Nn];  // 16 MB bf16 J
// software grid barrier state (persists across launches; gen monotonic)
__device__ uint g_barcnt = 0;
__device__ volatile uint g_bargen = 0;

// ---------------------------------------------------------------------------
// Fused projection kernel: q = 0.125*x@Wq^T (tf32), k = x@Wk^T (tf32),
// ph = x@Wp^T + bp (+sincos, fp32 + bf16 layouts).
// ---------------------------------------------------------------------------
__global__ __launch_bounds__(256, 2) void proj_kernel(
    const float* __restrict__ x,
    const float* __restrict__ Wq, const float* __restrict__ Wk,
    const float* __restrict__ Wp, const float* __restrict__ bp,
    float* __restrict__ q, float* __restrict__ k,
    float* __restrict__ ph, float* __restrict__ s0, float* __restrict__ c0,
    __nv_bfloat16* __restrict__ sch0) {
    __shared__ __align__(16) float As[64][68];   // [kk][m]
    __shared__ __align__(16) float Bs[64][68];   // [kk][n]
    int m0 = blockIdx.x * 64;
    int y = blockIdx.y;
    const float* W;
    int n0, Nout;
    if (y < 4)      { W = Wq; n0 = y * 64;       Nout = Dd; }
    else if (y < 8) { W = Wk; n0 = (y - 4) * 64; Nout = Dd; }
    else            { W = Wp; n0 = 0;            Nout = HO; }
    int tid = threadIdx.x;
    int tx = tid & 15, ty = tid >> 4;
    ull acc2[4][2] = {};
    for (int kt = 0; kt < Dd; kt += 64) {
        for (int t = tid; t < 64 * 16; t += 256) {
            int r = t >> 4, c4 = (t & 15) * 4;
            float4 va = *(const float4*)&x[(size_t)(m0 + r) * Dd + kt + c4];
            As[c4 + 0][r] = va.x; As[c4 + 1][r] = va.y;
            As[c4 + 2][r] = va.z; As[c4 + 3][r] = va.w;
            float4 vb = make_float4(0.f, 0.f, 0.f, 0.f);
            if (n0 + r < Nout)
                vb = *(const float4*)&W[(size_t)(n0 + r) * Dd + kt + c4];
            Bs[c4 + 0][r] = vb.x; Bs[c4 + 1][r] = vb.y;
            Bs[c4 + 2][r] = vb.z; Bs[c4 + 3][r] = vb.w;
        }
        __syncthreads();
#pragma unroll
        for (int kk = 0; kk < 64; kk++) {
            float4 a = *(const float4*)&As[kk][ty * 4];
            ulonglong2 bv = *(const ulonglong2*)&Bs[kk][tx * 4];
            ull aa0, aa1, aa2, aa3;
            PACK2(aa0, a.x); PACK2(aa1, a.y); PACK2(aa2, a.z); PACK2(aa3, a.w);
            FMA2(acc2[0][0], aa0, bv.x); FMA2(acc2[0][1], aa0, bv.y);
            FMA2(acc2[1][0], aa1, bv.x); FMA2(acc2[1][1], aa1, bv.y);
            FMA2(acc2[2][0], aa2, bv.x); FMA2(acc2[2][1], aa2, bv.y);
            FMA2(acc2[3][0], aa3, bv.x); FMA2(acc2[3][1], aa3, bv.y);
        }
        __syncthreads();
    }
    float acc[4][4];
#pragma unroll
    for (int i = 0; i < 4; i++) {
        UNPK2(acc[i][0], acc[i][1], acc2[i][0]);
        UNPK2(acc[i][2], acc[i][3], acc2[i][1]);
    }
    if (y < 4) {
#pragma unroll
        for (int i = 0; i < 4; i++) {
            int m = m0 + ty * 4 + i;
            float4 v = make_float4(tf32r(0.125f * acc[i][0]), tf32r(0.125f * acc[i][1]),
                                   tf32r(0.125f * acc[i][2]), tf32r(0.125f * acc[i][3]));
            *(float4*)&q[(size_t)m * Dd + n0 + tx * 4] = v;
        }
    } else if (y < 8) {
#pragma unroll
        for (int i = 0; i < 4; i++) {
            int m = m0 + ty * 4 + i;
            float4 v = make_float4(tf32r(acc[i][0]), tf32r(acc[i][1]),
                                   tf32r(acc[i][2]), tf32r(acc[i][3]));
            *(float4*)&k[(size_t)m * Dd + n0 + tx * 4] = v;
        }
    } else if (tx * 4 < HO) {
#pragma unroll
        for (int i = 0; i < 4; i++) {
            int m = m0 + ty * 4 + i;
            int j = m & 1023, b = m >> 10;
            int jp = j >> 1, jb = j & 1;
#pragma unroll
            for (int jj = 0; jj < 4; jj++) {
                int n = tx * 4 + jj;
                float p = acc[i][jj] + bp[n];
                int g = m * HO + n;
                ph[g] = p;
                float sn, cn;
                sincosf(p, &sn, &cn);
                s0[g] = sn;
                c0[g] = cn;
                int bh = b * 4 + (n >> 3), o = n & 7;
                int base = ((bh << 9) + jp) * 32;
                sch0[base + o * 2 + jb] = __float2bfloat16_rn(sn);
                sch0[base + 16 + o * 2 + jb] = __float2bfloat16_rn(cn);
            }
        }
    }
}

// ---------------------------------------------------------------------------
// Fused attention: scores (tf32 MMA) + row softmax + bf16 J write.
// ---------------------------------------------------------------------------
__global__ __launch_bounds__(256, 1) void attn_kernel(
    const float* __restrict__ q, const float* __restrict__ k,
    __nv_bfloat16* __restrict__ Jh) {
    extern __shared__ __align__(16) float dsm[];
    float* Sc = dsm;                      // 32*SSTR floats
    float* Qs = Sc + 32 * SSTR;           // 32*KSTR
    float* Ks = Qs + 32 * KSTR;           // 2*128*KSTR
    int i0 = blockIdx.x * 32;
    int bh = blockIdx.y;
    int b = bh >> 2, h = bh & 3;
    int tid = threadIdx.x;
#pragma unroll
    for (int it = 0; it < 2; it++) {
        int idx = tid + it * 256;
        int r = idx >> 4, c4 = (idx & 15) * 4;
        float4 v = *(const float4*)&q[(size_t)((b << 10) + i0 + r) * Dd + h * DKK + c4];
        *(float4*)&Qs[r * KSTR + c4] = v;
    }
    const float* kbase = &k[(size_t)(b << 10) * Dd + h * DKK];
#pragma unroll
    for (int it = 0; it < 8; it++) {
        int idx = tid + it * 256;
        int jr = idx >> 4, c4 = (idx & 15) * 4;
        uint dst = (uint)__cvta_generic_to_shared(&Ks[jr * KSTR + c4]);
        CP16(dst, &kbase[(size_t)jr * Dd + c4]);
    }
    CP_COMMIT();

    int w = tid >> 5, lane = tid & 31;
    int gid = lane >> 2, tig = lane & 3;
    int m0 = (w >> 2) * 16, jq = (w & 3) * 32;
    for (int c = 0; c < 8; c++) {
        if (c < 7) {
            float* bufn = &Ks[((c + 1) & 1) * 128 * KSTR];
#pragma unroll
            for (int it = 0; it < 8; it++) {
                int idx = tid + it * 256;
                int jr = idx >> 4, c4 = (idx & 15) * 4;
                uint dst = (uint)__cvta_generic_to_shared(&bufn[jr * KSTR + c4]);
                CP16(dst, &kbase[(size_t)(((c + 1) << 7) + jr) * Dd + c4]);
            }
            CP_COMMIT();
            CP_WAIT(1);
        } else {
            CP_WAIT(0);
        }
        __syncthreads();
        const float* buf = &Ks[(c & 1) * 128 * KSTR];
        float d0[4] = {}, d1[4] = {}, d2[4] = {}, d3[4] = {};
#pragma unroll
        for (int kk = 0; kk < 8; kk++) {
            int kb8 = kk * 8;
            uint a0 = __float_as_uint(Qs[(m0 + gid) * KSTR + kb8 + tig]);
            uint a1 = __float_as_uint(Qs[(m0 + gid + 8) * KSTR + kb8 + tig]);
            uint a2 = __float_as_uint(Qs[(m0 + gid) * KSTR + kb8 + tig + 4]);
            uint a3 = __float_as_uint(Qs[(m0 + gid + 8) * KSTR + kb8 + tig + 4]);
            uint b0, b1;
            b0 = __float_as_uint(buf[(jq + 0 + gid) * KSTR + kb8 + tig]);
            b1 = __float_as_uint(buf[(jq + 0 + gid) * KSTR + kb8 + tig + 4]);
            MMA_TF32(d0, a0, a1, a2, a3, b0, b1);
            b0 = __float_as_uint(buf[(jq + 8 + gid) * KSTR + kb8 + tig]);
            b1 = __float_as_uint(buf[(jq + 8 + gid) * KSTR + kb8 + tig + 4]);
            MMA_TF32(d1, a0, a1, a2, a3, b0, b1);
            b0 = __float_as_uint(buf[(jq + 16 + gid) * KSTR + kb8 + tig]);
            b1 = __float_as_uint(buf[(jq + 16 + gid) * KSTR + kb8 + tig + 4]);
            MMA_TF32(d2, a0, a1, a2, a3, b0, b1);
            b0 = __float_as_uint(buf[(jq + 24 + gid) * KSTR + kb8 + tig]);
            b1 = __float_as_uint(buf[(jq + 24 + gid) * KSTR + kb8 + tig + 4]);
            MMA_TF32(d3, a0, a1, a2, a3, b0, b1);
        }
        int cc = c * 128 + jq + tig * 2;
        *(float2*)&Sc[(m0 + gid) * SSTR + cc]          = make_float2(d0[0], d0[1]);
        *(float2*)&Sc[(m0 + gid + 8) * SSTR + cc]      = make_float2(d0[2], d0[3]);
        *(float2*)&Sc[(m0 + gid) * SSTR + cc + 8]      = make_float2(d1[0], d1[1]);
        *(float2*)&Sc[(m0 + gid + 8) * SSTR + cc + 8]  = make_float2(d1[2], d1[3]);
        *(float2*)&Sc[(m0 + gid) * SSTR + cc + 16]     = make_float2(d2[0], d2[1]);
        *(float2*)&Sc[(m0 + gid + 8) * SSTR + cc + 16] = make_float2(d2[2], d2[3]);
        *(float2*)&Sc[(m0 + gid) * SSTR + cc + 24]     = make_float2(d3[0], d3[1]);
        *(float2*)&Sc[(m0 + gid + 8) * SSTR + cc + 24] = make_float2(d3[2], d3[3]);
        __syncthreads();
    }
    int row = tid >> 3, l8 = tid & 7;
    float* Sr = &Sc[row * SSTR];
    float mx = -1e30f;
#pragma unroll
    for (int it = 0; it < 32; it++) {
        float4 v = *(const float4*)&Sr[l8 * 4 + it * 32];
        mx = fmaxf(mx, fmaxf(fmaxf(v.x, v.y), fmaxf(v.z, v.w)));
    }
#pragma unroll
    for (int off = 1; off < 8; off <<= 1)
        mx = fmaxf(mx, __shfl_xor_sync(0xffffffffu, mx, off));
    float sum = 0.f;
#pragma unroll
    for (int it = 0; it < 32; it++) {
        float4 v = *(const float4*)&Sr[l8 * 4 + it * 32];
        v.x = __expf(v.x - mx); v.y = __expf(v.y - mx);
        v.z = __expf(v.z - mx); v.w = __expf(v.w - mx);
        sum += (v.x + v.y) + (v.z + v.w);
        *(float4*)&Sr[l8 * 4 + it * 32] = v;
    }
#pragma unroll
    for (int off = 1; off < 8; off <<= 1)
        sum += __shfl_xor_sync(0xffffffffu, sum, off);
    float inv = 1.f / sum;
    __nv_bfloat16* Jr = &Jh[((size_t)(bh << 10) + i0 + row) * Nn];
#pragma unroll
    for (int it = 0; it < 32; it++) {
        float4 v = *(const float4*)&Sr[l8 * 4 + it * 32];
        uint2 pk;
        pk.x = bf16x2(v.x * inv, v.y * inv);
        pk.y = bf16x2(v.z * inv, v.w * inv);
        *(uint2*)&Jr[l8 * 4 + it * 32] = pk;
    }
}

// ---------------------------------------------------------------------------
// Persistent Kuramoto stepper: ALL 5 steps in one launch.
// Grid (32, 8) = 256 CTAs, each owns a 32-row strip of one bh. J strip
// (64 KB) staged to smem ONCE; phase/sin/cos held in registers (1 osc per
// thread). Per step: stream sch[bh] in 4 cp.async double-buffered chunks,
// bf16 MMA matvec, in-smem reduce, phase update, write own sch slice, then
// software grid barrier (sense-reversing, all 256 CTAs co-resident:
// 107 KB smem + launch_bounds(256,2) -> >=2 CTAs/SM -> 296 slots >= 256).
// ---------------------------------------------------------------------------
#define PSMEM ((32 * JWF + 2 * 128 * SCW + 4096) * 4)   // 107008 B
__global__ __launch_bounds__(256, 2) void step_persist(
    const __nv_bfloat16* __restrict__ Jh,
    __nv_bfloat16* __restrict__ schA, __nv_bfloat16* __restrict__ schB,
    const float* __restrict__ ph_g,
    const float* __restrict__ s0g, const float* __restrict__ c0g,
    float* __restrict__ cfin,
    const float* __restrict__ omega, const float* __restrict__ cs_ptr) {
    extern __shared__ __align__(16) uint sm4[];
    uint* Jt = sm4;                          // 32 x JWF words
    uint* sb0 = sm4 + 32 * JWF;              // 128 x SCW
    uint* sb1 = sb0 + 128 * SCW;
    float* Pr = (float*)(sb1 + 128 * SCW);   // [8][32][16]
    int i0 = blockIdx.x * 32;
    int bh = blockIdx.y;
    int b = bh >> 2, h = bh & 3;
    int tid = threadIdx.x;
    // stage J strip once: 32 rows x 1024 bf16
    const __nv_bfloat16* Jsrc = Jh + ((size_t)(bh << 10) + i0) * Nn;
#pragma unroll
    for (int it = 0; it < 16; it++) {
        int u = tid + it * 256;
        int r = u >> 7, qd = u & 127;
        uint dst = (uint)__cvta_generic_to_shared(&Jt[r * JWF + qd * 4]);
        CP16(dst, Jsrc + (size_t)r * Nn + qd * 8);
    }
    CP_COMMIT();
    // thread-owned oscillator state
    int row = tid >> 3, o = tid & 7;
    int n = i0 + row;
    int gs = ((b << 10) + n) * HO + h * Oo + o;
    float phv = ph_g[gs], si = s0g[gs], ci = c0g[gs];
    float om = omega[h * Oo + o], csv = *cs_ptr;
    CP_WAIT(0);
    __syncthreads();

    int w = tid >> 5, lane = tid & 31;
    int gid = lane >> 2, tig = lane & 3;
    uint* sbuf[2] = {sb0, sb1};

#define LOADSC(c, SB) do {                                                  \
        _Pragma("unroll")                                                   \
        for (int _it = 0; _it < 2; _it++) {                                 \
            int _u = tid + _it * 256;                                       \
            int _p = _u >> 2, _wq = (_u & 3) * 4;                           \
            uint _d = (uint)__cvta_generic_to_shared(&(SB)[_p * SCW + _wq]);\
            CP16(_d, Ssrc + ((size_t)(((c) << 7) + _p)) * 32 + _wq * 2);    \
        }                                                                   \
    } while (0)

    for (int step = 0; step < NSTEPS; step++) {
        const __nv_bfloat16* Ssrc = ((step & 1) ? schB : schA) + ((size_t)bh << 14);
        LOADSC(0, sbuf[0]);
        CP_COMMIT();
        float ds[2][4] = {}, dc[2][4] = {};
#pragma unroll
        for (int c = 0; c < 4; c++) {
            if (c < 3) {
                LOADSC(c + 1, sbuf[(c + 1) & 1]);
                CP_COMMIT();
                CP_WAIT(1);
            } else {
                CP_WAIT(0);
            }
            __syncthreads();
            const uint* SB = sbuf[c & 1];
#pragma unroll
            for (int kk = 0; kk < 2; kk++) {
                int wb = w * 16 + kk * 8;
                uint b0s = SB[(wb + tig) * SCW + gid];
                uint b1s = SB[(wb + tig + 4) * SCW + gid];
                uint b0c = SB[(wb + tig) * SCW + 8 + gid];
                uint b1c = SB[(wb + tig + 4) * SCW + 8 + gid];
                int aw = c * 128 + wb + tig;
#pragma unroll
                for (int rg = 0; rg < 2; rg++) {
                    int r0 = (rg * 16 + gid) * JWF + aw;
                    int r1 = (rg * 16 + gid + 8) * JWF + aw;
                    uint a0 = Jt[r0], a1 = Jt[r1];
                    uint a2 = Jt[r0 + 4], a3 = Jt[r1 + 4];
                    MMA_BF16(ds[rg], a0, a1, a2, a3, b0s, b1s);
                    MMA_BF16(dc[rg], a0, a1, a2, a3, b0c, b1c);
                }
            }
            __syncthreads();
        }
#pragma unroll
        for (int rg = 0; rg < 2; rg++) {
            int pw = w * 512;
            *(float2*)&Pr[pw + (rg * 16 + gid) * 16 + tig * 2]         = make_float2(ds[rg][0], ds[rg][1]);
            *(float2*)&Pr[pw + (rg * 16 + gid) * 16 + 8 + tig * 2]     = make_float2(dc[rg][0], dc[rg][1]);
            *(float2*)&Pr[pw + (rg * 16 + gid + 8) * 16 + tig * 2]     = make_float2(ds[rg][2], ds[rg][3]);
            *(float2*)&Pr[pw + (rg * 16 + gid + 8) * 16 + 8 + tig * 2] = make_float2(dc[rg][2], dc[rg][3]);
        }
        __syncthreads();
        float js = 0.f, jc = 0.f;
#pragma unroll
        for (int w2 = 0; w2 < 8; w2++) {
            js += Pr[w2 * 512 + row * 16 + o];
            jc += Pr[w2 * 512 + row * 16 + 8 + o];
        }
        float coup = ci * js - si * jc;
        float np = phv + DT_F * (om + csv * coup);
        float v = np + PI_F;
        np = v - floorf(v * INV_2PI_F) * TWO_PI_F - PI_F;
        phv = np;
        sincosf(np, &si, &ci);
        if (step < NSTEPS - 1) {
            __nv_bfloat16* so = (step & 1) ? schA : schB;
            int base2 = ((bh << 9) + (n >> 1)) * 32 + (n & 1);
            so[base2 + o * 2] = __float2bfloat16_rn(si);
            so[base2 + 16 + o * 2] = __float2bfloat16_rn(ci);
            // grid barrier (sense-reversing)
            __threadfence();
            __syncthreads();
            if (tid == 0) {
                uint gen = g_bargen;
                if (atomicAdd(&g_barcnt, 1) == NBLK - 1) {
                    g_barcnt = 0;
                    __threadfence();
                    g_bargen = gen + 1;
                } else {
                    while (g_bargen == gen) { }
                }
            }
            __syncthreads();
        } else {
            cfin[gs] = ci;
        }
    }
#undef LOADSC
}

// ---------------------------------------------------------------------------
// Final small GEMM: out = C @ Wo^T + bo, K=32.
// ---------------------------------------------------------------------------
__global__ void gemm_out(const float* __restrict__ X, const float* __restrict__ W,
                         const float* __restrict__ bias, float* __restrict__ out) {
    __shared__ float As[64][33];
    __shared__ float Ws[64][33];
    int m0 = blockIdx.x * 64, n0 = blockIdx.y * 64;
    int tid = threadIdx.x;
    int tx = tid & 15, ty = tid >> 4;
    float acc[4][4] = {};
    for (int li = tid; li < 64 * 32; li += 256) {
        int r = li >> 5, c = li & 31;
        As[r][c] = X[(size_t)(m0 + r) * HO + c];
        Ws[r][c] = W[(size_t)(n0 + r) * HO + c];
    }
    __syncthreads();
#pragma unroll
    for (int kk = 0; kk < 32; kk++) {
        float a[4], bb[4];
#pragma unroll
        for (int i = 0; i < 4; i++) a[i] = As[ty * 4 + i][kk];
#pragma unroll
        for (int j = 0; j < 4; j++) bb[j] = Ws[tx * 4 + j][kk];
#pragma unroll
        for (int i = 0; i < 4; i++)
#pragma unroll
            for (int j = 0; j < 4; j++)
                acc[i][j] = fmaf(a[i], bb[j], acc[i][j]);
    }
#pragma unroll
    for (int i = 0; i < 4; i++) {
        int m = m0 + ty * 4 + i;
#pragma unroll
        for (int j = 0; j < 4; j++) {
            int n = n0 + tx * 4 + j;
            out[(size_t)m * Dd + n] = acc[i][j] + bias[n];
        }
    }
}

// ---------------------------------------------------------------------------
extern "C" void kernel_launch(void* const* d_in, const int* in_sizes, int n_in,
                              void* d_out, int out_size) {
    const float* x     = (const float*)d_in[0];
    const float* Wq    = (const float*)d_in[1];
    const float* Wk    = (const float*)d_in[2];
    const float* Wp    = (const float*)d_in[3];
    const float* bp    = (const float*)d_in[4];
    const float* Wo    = (const float*)d_in[5];
    const float* bo    = (const float*)d_in[6];
    const float* omega = (const float*)d_in[7];
    const float* cs    = (const float*)d_in[8];
    float* out = (float*)d_out;

    float *q, *k, *ph, *s0, *c0, *c1;
    __nv_bfloat16 *sch0, *sch1, *Jh;
    cudaGetSymbolAddress((void**)&q,    g_q);
    cudaGetSymbolAddress((void**)&k,    g_k);
    cudaGetSymbolAddress((void**)&ph,   g_ph);
    cudaGetSymbolAddress((void**)&s0,   g_s0);
    cudaGetSymbolAddress((void**)&c0,   g_c0);
    cudaGetSymbolAddress((void**)&c1,   g_c1);
    cudaGetSymbolAddress((void**)&sch0, g_sch0);
    cudaGetSymbolAddress((void**)&sch1, g_sch1);
    cudaGetSymbolAddress((void**)&Jh,   g_Jh);

    dim3 blk(256);
    // fused projections (q, k tf32; ph + sincos, fp32 + bf16 layouts)
    proj_kernel<<<dim3(Bb * Nn / 64, 9), blk>>>(x, Wq, Wk, Wp, bp, q, k, ph, s0, c0, sch0);
    // fused scores + softmax -> bf16 J
    size_t smem_at = (size_t)(32 * SSTR + 32 * KSTR + 2 * 128 * KSTR) * sizeof(float);
    cudaFuncSetAttribute(attn_kernel, cudaFuncAttributeMaxDynamicSharedMemorySize, (int)smem_at);
    attn_kernel<<<dim3(Nn / 32, Bb * Hh), blk, smem_at>>>(q, k, Jh);
    // all 5 oscillator steps in ONE persistent launch
    cudaFuncSetAttribute(step_persist, cudaFuncAttributeMaxDynamicSharedMemorySize, PSMEM);
    step_persist<<<dim3(32, Bb * Hh), blk, PSMEM>>>(
        Jh, sch0, sch1, ph, s0, c0, c1, omega, cs);
    // output: out = cos(final phases) @ Wo^T + bo
    gemm_out<<<dim3(Bb * Nn / 64, Dd / 64), blk>>>(c1, Wo, bo, out);
}